// round 2
// baseline (speedup 1.0000x reference)
#include <cuda_runtime.h>

#define BB 256
#define CC 128
#define NT 256
#define RB 8

// ---------------- scratch (device globals; no allocation APIs) ---------------
__device__ float g_a1[BB*CC*24*24];
__device__ float g_a2[BB*CC*24*24];
__device__ float g_p1[BB*CC*12*12];
__device__ float g_a3[BB*CC*12*12];
__device__ float g_z [BB*CC*6*6];
__device__ float g_val[BB*CC*6*6];
__device__ float g_f1[BB*CC*9*9];
__device__ float g_f2[BB*CC*20*20];
__device__ float g_f3[BB*CC*24*24];
__device__ float g_f4[BB*CC*28*28];
__device__ double g_rec_sum;
__device__ double g_dict_sum;

__global__ void init_kernel() { g_rec_sum = 0.0; g_dict_sum = 0.0; }

__inline__ __device__ float warp_sum(float v) {
    #pragma unroll
    for (int o = 16; o; o >>= 1) v += __shfl_xor_sync(0xffffffffu, v, o);
    return v;
}

// ---------------- generic direct conv (K = 4 or 5) ---------------------------
// Block: (batch, 32 output channels, 8 output rows). 256 threads.
// Thread tile: 4 couts x 2 pixel-quads x 4 pixels = 32 accumulators.
// trans=1: W is torch ConvTranspose layout (in,out,k,k); effective conv weight
// is flipped + in/out transposed; use with pad=K-1 for stride-1 deconv.
template<int K>
__global__ void __launch_bounds__(256)
conv_direct(const float* __restrict__ in, const float* __restrict__ W,
            const float* __restrict__ bias, float* __restrict__ out,
            int Cin, int Cout, int inH, int inW, int outH, int outW,
            int pad, int relu, int trans, int CIB)
{
    extern __shared__ float sm[];
    const int KK = K * K;
    const int tid = threadIdx.x;
    const int b   = blockIdx.x;
    const int coB = blockIdx.y * 32;
    const int r0  = blockIdx.z * RB;

    const int QW  = (outW + 3) >> 2;
    const int PWA = QW * 4 + K - 1;
    const int TH  = RB + K - 1;

    float* xs = sm;                       // CIB * TH * PWA
    float* ws = sm + CIB * TH * PWA;      // CIB * KK * 32  [ci][tap][co32]

    const int coq = tid & 7;
    const int pq  = tid >> 3;

    int rbe = outH - r0; if (rbe > RB) rbe = RB;
    const int nquads = rbe * QW;

    int qrow[2], qx[2]; bool qv[2];
    #pragma unroll
    for (int qi = 0; qi < 2; qi++) {
        int q = pq + qi * 32;
        qv[qi] = (q < nquads);
        int qq = qv[qi] ? q : 0;
        qrow[qi] = qq / QW;
        qx[qi]   = (qq - qrow[qi] * QW) << 2;
    }

    float acc[2][4][4];
    #pragma unroll
    for (int a = 0; a < 2; a++)
        #pragma unroll
        for (int j = 0; j < 4; j++)
            #pragma unroll
            for (int k = 0; k < 4; k++) acc[a][j][k] = 0.f;

    const int xsN = CIB * TH * PWA;
    const int wsN = CIB * KK * 32;

    for (int cb = 0; cb < Cin; cb += CIB) {
        for (int i = tid; i < xsN; i += NT) {
            int ci = i / (TH * PWA); int r = i - ci * (TH * PWA);
            int ty = r / PWA;        int tx = r - ty * PWA;
            int iy = r0 + ty - pad;  int ix = tx - pad;
            float v = 0.f;
            if ((unsigned)iy < (unsigned)inH && (unsigned)ix < (unsigned)inW)
                v = in[((size_t)(b * Cin + cb + ci) * inH + iy) * inW + ix];
            xs[i] = v;
        }
        for (int i = tid; i < wsN; i += NT) {
            int col = i & 31; int t = i >> 5;
            int ci = t / KK;  int tap = t - ci * KK;
            int ky = tap / K; int kx = tap - ky * K;
            int cig = cb + ci; int cog = coB + col;
            float wv;
            if (trans)
                wv = W[(((size_t)cig * Cout + cog) * K + (K - 1 - ky)) * K + (K - 1 - kx)];
            else
                wv = W[(((size_t)cog * Cin + cig) * K + ky) * K + kx];
            ws[(ci * KK + tap) * 32 + col] = wv;
        }
        __syncthreads();

        int cie = Cin - cb; if (cie > CIB) cie = CIB;
        for (int ci = 0; ci < cie; ci++) {
            const float* xci = xs + ci * (TH * PWA);
            const float* wci = ws + ci * (KK * 32) + (coq << 2);
            #pragma unroll
            for (int ky = 0; ky < K; ky++) {
                float xa[K + 3], xb[K + 3];
                const float* pa = xci + (qrow[0] + ky) * PWA + qx[0];
                const float* pb = xci + (qrow[1] + ky) * PWA + qx[1];
                #pragma unroll
                for (int t = 0; t < K + 3; t++) { xa[t] = pa[t]; xb[t] = pb[t]; }
                #pragma unroll
                for (int kx = 0; kx < K; kx++) {
                    const float* wp = wci + (ky * K + kx) * 32;
                    float w0 = wp[0], w1 = wp[1], w2 = wp[2], w3 = wp[3];
                    #pragma unroll
                    for (int k = 0; k < 4; k++) {
                        float va = xa[kx + k], vb = xb[kx + k];
                        acc[0][0][k] += w0 * va; acc[0][1][k] += w1 * va;
                        acc[0][2][k] += w2 * va; acc[0][3][k] += w3 * va;
                        acc[1][0][k] += w0 * vb; acc[1][1][k] += w1 * vb;
                        acc[1][2][k] += w2 * vb; acc[1][3][k] += w3 * vb;
                    }
                }
            }
        }
        __syncthreads();
    }

    #pragma unroll
    for (int qi = 0; qi < 2; qi++) {
        if (!qv[qi]) continue;
        int oy = r0 + qrow[qi];
        #pragma unroll
        for (int j = 0; j < 4; j++) {
            int co = coB + coq * 4 + j;
            float bz = bias[co];
            float* op = out + ((size_t)(b * Cout + co) * outH + oy) * outW + qx[qi];
            #pragma unroll
            for (int k = 0; k < 4; k++) {
                int ox = qx[qi] + k;
                if (ox < outW) {
                    float v = acc[qi][j][k] + bz;
                    if (relu) v = fmaxf(v, 0.f);
                    op[k] = v;
                }
            }
        }
    }
}

// ---------------- stride-2 transposed conv, k=4: (B,128,9,9)->(B,128,20,20) --
__global__ void __launch_bounds__(256)
deconv_s2_k4(const float* __restrict__ in, const float* __restrict__ W,
             const float* __restrict__ bias, float* __restrict__ out)
{
    __shared__ float xs[8 * 81];
    __shared__ float ws[8 * 16 * 32];
    const int tid = threadIdx.x;
    const int b   = blockIdx.x;
    const int coB = blockIdx.y * 32;
    const int r0  = blockIdx.z * 10;
    const int coq = tid & 7;
    const int pq  = tid >> 3;

    int qrow[2], qx[2]; bool qv[2];
    #pragma unroll
    for (int qi = 0; qi < 2; qi++) {
        int q = pq + qi * 32;
        qv[qi] = (q < 50);                 // 10 rows * 5 quads
        int qq = qv[qi] ? q : 0;
        qrow[qi] = qq / 5;
        qx[qi]   = (qq - qrow[qi] * 5) << 2;
    }

    float acc[2][4][4];
    #pragma unroll
    for (int a = 0; a < 2; a++)
        #pragma unroll
        for (int j = 0; j < 4; j++)
            #pragma unroll
            for (int k = 0; k < 4; k++) acc[a][j][k] = 0.f;

    for (int cb = 0; cb < 128; cb += 8) {
        for (int i = tid; i < 8 * 81; i += NT) {
            int ci = i / 81; int p = i - ci * 81;
            xs[i] = in[(size_t)(b * 128 + cb + ci) * 81 + p];
        }
        for (int i = tid; i < 8 * 16 * 32; i += NT) {
            int col = i & 31; int t = i >> 5;
            int ci = t >> 4;  int tap = t & 15;
            int dy = tap >> 2; int dx = tap & 3;
            ws[i] = W[(((size_t)(cb + ci) * 128 + coB + col) * 4 + (3 - dy)) * 4 + (3 - dx)];
        }
        __syncthreads();

        for (int ci = 0; ci < 8; ci++) {
            const float* xci = xs + ci * 81;
            #pragma unroll
            for (int dy = 0; dy < 4; dy++) {
                int u0 = r0 + qrow[0] + dy - 3;
                int u1 = r0 + qrow[1] + dy - 3;
                bool va = ((u0 & 1) == 0) && u0 >= 0 && u0 <= 16;
                bool vb = ((u1 & 1) == 0) && u1 >= 0 && u1 <= 16;
                const float* ra = xci + ((va ? u0 : 0) >> 1) * 9;
                const float* rb = xci + ((vb ? u1 : 0) >> 1) * 9;
                #pragma unroll
                for (int dx = 0; dx < 4; dx++) {
                    const float* wp = ws + (ci * 16 + dy * 4 + dx) * 32 + (coq << 2);
                    float w0 = wp[0], w1 = wp[1], w2 = wp[2], w3 = wp[3];
                    #pragma unroll
                    for (int k = 0; k < 4; k++) {
                        int v0 = qx[0] + k + dx - 3;
                        if (va && ((v0 & 1) == 0) && v0 >= 0 && v0 <= 16) {
                            float xv = ra[v0 >> 1];
                            acc[0][0][k] += w0 * xv; acc[0][1][k] += w1 * xv;
                            acc[0][2][k] += w2 * xv; acc[0][3][k] += w3 * xv;
                        }
                        int v1 = qx[1] + k + dx - 3;
                        if (vb && ((v1 & 1) == 0) && v1 >= 0 && v1 <= 16) {
                            float xv = rb[v1 >> 1];
                            acc[1][0][k] += w0 * xv; acc[1][1][k] += w1 * xv;
                            acc[1][2][k] += w2 * xv; acc[1][3][k] += w3 * xv;
                        }
                    }
                }
            }
        }
        __syncthreads();
    }

    #pragma unroll
    for (int qi = 0; qi < 2; qi++) {
        if (!qv[qi]) continue;
        int oy = r0 + qrow[qi];
        #pragma unroll
        for (int j = 0; j < 4; j++) {
            int co = coB + coq * 4 + j;
            float bz = bias[co];
            float* op = out + ((size_t)(b * 128 + co) * 20 + oy) * 20 + qx[qi];
            #pragma unroll
            for (int k = 0; k < 4; k++)
                op[k] = fmaxf(acc[qi][j][k] + bz, 0.f);
        }
    }
}

// ---------------- maxpool 2x2 -------------------------------------------------
__global__ void maxpool2(const float* __restrict__ in, float* __restrict__ out,
                         int planes, int H, int W)
{
    int oh = H >> 1, ow = W >> 1;
    size_t total = (size_t)planes * oh * ow;
    for (size_t i = (size_t)blockIdx.x * blockDim.x + threadIdx.x; i < total;
         i += (size_t)gridDim.x * blockDim.x) {
        int p = (int)(i % (size_t)(oh * ow));
        size_t c = i / (size_t)(oh * ow);
        int y = p / ow, x = p - y * ow;
        const float* ip = in + (c * H + 2 * y) * W + 2 * x;
        out[i] = fmaxf(fmaxf(ip[0], ip[1]), fmaxf(ip[W], ip[W + 1]));
    }
}

// ---------------- VQ: argmax(d2), gather val, dict MSE ------------------------
__global__ void __launch_bounds__(256)
vq_kernel(const float* __restrict__ z, const float* __restrict__ dict,
          float* __restrict__ val, float* __restrict__ idx_out)
{
    extern __shared__ float dsm[];           // 128 * 129
    __shared__ float zt[36 * 128];           // zt[pos*128 + c]
    __shared__ float wn[128];
    __shared__ int   sidx[36];

    const int b = blockIdx.x, tid = threadIdx.x;

    for (int i = tid; i < 128 * 128; i += NT) {
        int k = i >> 7; int c = i & 127;
        dsm[k * 129 + c] = dict[i];
    }
    for (int i = tid; i < 36 * 128; i += NT) {
        int pos = i >> 7; int c = i & 127;
        zt[i] = z[(size_t)(b * 128 + c) * 36 + pos];
    }
    __syncthreads();
    if (tid < 128) {
        float s = 0.f;
        const float* dp = dsm + tid * 129;
        for (int c = 0; c < 128; c++) s += dp[c] * dp[c];
        wn[tid] = s;
    }
    __syncthreads();

    const int lane = tid & 31, wid = tid >> 5;
    for (int pos = wid; pos < 36; pos += 8) {
        float d0 = 0.f, d1 = 0.f, d2s = 0.f, d3 = 0.f, zn = 0.f;
        const float* zp = zt + pos * 128;
        const float* p0 = dsm + (lane      ) * 129;
        const float* p1 = dsm + (lane + 32 ) * 129;
        const float* p2 = dsm + (lane + 64 ) * 129;
        const float* p3 = dsm + (lane + 96 ) * 129;
        for (int c = 0; c < 128; c++) {
            float zv = zp[c];
            zn += zv * zv;
            d0 += p0[c] * zv; d1 += p1[c] * zv;
            d2s += p2[c] * zv; d3 += p3[c] * zv;
        }
        float bv = zn + wn[lane] - 2.f * d0; int bk = lane;
        float v1 = zn + wn[lane + 32] - 2.f * d1; if (v1 > bv) { bv = v1; bk = lane + 32; }
        float v2 = zn + wn[lane + 64] - 2.f * d2s; if (v2 > bv) { bv = v2; bk = lane + 64; }
        float v3 = zn + wn[lane + 96] - 2.f * d3; if (v3 > bv) { bv = v3; bk = lane + 96; }
        #pragma unroll
        for (int o = 16; o; o >>= 1) {
            float ov = __shfl_xor_sync(0xffffffffu, bv, o);
            int   ok = __shfl_xor_sync(0xffffffffu, bk, o);
            if (ov > bv || (ov == bv && ok < bk)) { bv = ov; bk = ok; }
        }
        if (lane == 0) {
            sidx[pos] = bk;
            if (idx_out) idx_out[b * 36 + pos] = (float)bk;
        }
    }
    __syncthreads();

    float lsum = 0.f;
    for (int i = tid; i < 4608; i += NT) {
        int c = i / 36; int pos = i - c * 36;
        float v  = dsm[sidx[pos] * 129 + c];
        float zv = zt[pos * 128 + c];
        val[(size_t)(b * 128 + c) * 36 + pos] = v;
        float d = v - zv;
        lsum += d * d;
    }
    lsum = warp_sum(lsum);
    if ((tid & 31) == 0) atomicAdd(&g_dict_sum, (double)lsum);
}

// ---------------- mu (1x1 conv) fused with reconstruction loss ---------------
__global__ void __launch_bounds__(256)
mu_loss(const float* __restrict__ f4, const float* __restrict__ x,
        const float* __restrict__ mw, const float* __restrict__ mb)
{
    __shared__ float mws[128];
    const int b = blockIdx.x, tid = threadIdx.x;
    if (tid < 128) mws[tid] = mw[tid];
    __syncthreads();
    float lsum = 0.f;
    for (int px = tid; px < 784; px += NT) {
        const float* fp = f4 + (size_t)b * 128 * 784 + px;
        float s = mb[0];
        #pragma unroll 4
        for (int c = 0; c < 128; c++) s += fp[(size_t)c * 784] * mws[c];
        float d = s - x[(size_t)b * 784 + px];
        lsum += d * d;
    }
    lsum = warp_sum(lsum);
    if ((tid & 31) == 0) atomicAdd(&g_rec_sum, (double)lsum);
}

__global__ void finalize_kernel(float* loss_out)
{
    if (loss_out) {
        double dict_mse = g_dict_sum / 1179648.0;      // 256*128*36
        loss_out[0] = (float)(g_rec_sum / 200704.0);   // 256*1*28*28
        loss_out[1] = (float)(dict_mse * 5.0);
        loss_out[2] = (float)(dict_mse * 1.25);
        loss_out[3] = 0.f;
    }
}

// ---------------- host side ---------------------------------------------------
static void launch_conv(int K, const float* in, const float* W, const float* bias,
                        float* out, int Cin, int inH, int inW, int outH, int outW,
                        int pad, int relu, int trans)
{
    int CIB = (Cin >= 8) ? 8 : 1;
    int QW = (outW + 3) / 4;
    int PWA = QW * 4 + K - 1;
    int TH = RB + K - 1;
    size_t smem = (size_t)(CIB * TH * PWA + CIB * K * K * 32) * sizeof(float);
    dim3 grid(BB, 128 / 32, (outH + RB - 1) / RB);
    if (K == 5)
        conv_direct<5><<<grid, NT, smem>>>(in, W, bias, out, Cin, 128,
                                           inH, inW, outH, outW, pad, relu, trans, CIB);
    else
        conv_direct<4><<<grid, NT, smem>>>(in, W, bias, out, Cin, 128,
                                           inH, inW, outH, outW, pad, relu, trans, CIB);
}

extern "C" void kernel_launch(void* const* d_in, const int* in_sizes, int n_in,
                              void* d_out, int out_size)
{
    const float* x    = (const float*)d_in[0];
    const float* w1   = (const float*)d_in[1];
    const float* b1   = (const float*)d_in[2];
    const float* w2   = (const float*)d_in[3];
    const float* b2   = (const float*)d_in[4];
    const float* w3   = (const float*)d_in[5];
    const float* b3   = (const float*)d_in[6];
    const float* t1w  = (const float*)d_in[7];
    const float* t1b  = (const float*)d_in[8];
    const float* t2w  = (const float*)d_in[9];
    const float* t2b  = (const float*)d_in[10];
    const float* t3w  = (const float*)d_in[11];
    const float* t3b  = (const float*)d_in[12];
    const float* t4w  = (const float*)d_in[13];
    const float* t4b  = (const float*)d_in[14];
    const float* mw   = (const float*)d_in[15];
    const float* mb   = (const float*)d_in[16];
    const float* dictw= (const float*)d_in[17];

    float* outp = (float*)d_out;
    float* loss_ptr = outp;                     // losses first
    float* idx_ptr  = outp + 4;                 // then index (as float)
    if (out_size < 9220) {                      // fallback: index only
        loss_ptr = nullptr;
        idx_ptr  = outp;
    }

    float *a1, *a2, *p1, *a3, *zb, *valb, *f1, *f2, *f3, *f4;
    cudaGetSymbolAddress((void**)&a1, g_a1);
    cudaGetSymbolAddress((void**)&a2, g_a2);
    cudaGetSymbolAddress((void**)&p1, g_p1);
    cudaGetSymbolAddress((void**)&a3, g_a3);
    cudaGetSymbolAddress((void**)&zb, g_z);
    cudaGetSymbolAddress((void**)&valb, g_val);
    cudaGetSymbolAddress((void**)&f1, g_f1);
    cudaGetSymbolAddress((void**)&f2, g_f2);
    cudaGetSymbolAddress((void**)&f3, g_f3);
    cudaGetSymbolAddress((void**)&f4, g_f4);

    init_kernel<<<1, 1>>>();

    // encoder
    launch_conv(5, x,  w1, b1, a1, 1,   28, 28, 24, 24, 0, 1, 0);
    launch_conv(5, a1, w2, b2, a2, 128, 24, 24, 24, 24, 2, 1, 0);
    maxpool2<<<1024, 256>>>(a2, p1, BB * CC, 24, 24);
    launch_conv(5, p1, w3, b3, a3, 128, 12, 12, 12, 12, 2, 0, 0);
    maxpool2<<<256, 256>>>(a3, zb, BB * CC, 12, 12);

    // VQ
    static bool attr_set = false;
    if (!attr_set) {
        cudaFuncSetAttribute(vq_kernel, cudaFuncAttributeMaxDynamicSharedMemorySize,
                             128 * 129 * (int)sizeof(float));
        attr_set = true;
    }
    vq_kernel<<<BB, NT, 128 * 129 * sizeof(float)>>>(zb, dictw, valb, idx_ptr);

    // decoder
    launch_conv(4, valb, t1w, t1b, f1, 128, 6, 6, 9, 9, 3, 1, 1);
    deconv_s2_k4<<<dim3(BB, 4, 2), NT>>>(f1, t2w, t2b, f2);
    launch_conv(5, f2, t3w, t3b, f3, 128, 20, 20, 24, 24, 4, 1, 1);
    launch_conv(5, f3, t4w, t4b, f4, 128, 24, 24, 28, 28, 4, 1, 1);

    // mu + losses
    mu_loss<<<BB, NT>>>(f4, x, mw, mb);
    finalize_kernel<<<1, 1>>>(loss_ptr);
}

// round 4
// speedup vs baseline: 1.6043x; 1.6043x over previous
#include <cuda_runtime.h>
#include <cuda_bf16.h>
#include <cstdint>

#define BB 256
#define CC 128
#define NT 256
#define RB 8

// ---------------- scratch (device globals; no allocation APIs) ---------------
__device__ float g_a1[BB*CC*24*24];
__device__ float g_a2[BB*CC*24*24];
__device__ float g_p1[BB*CC*12*12];
__device__ float g_a3[BB*CC*12*12];
__device__ float g_z [BB*CC*6*6];
__device__ float g_val[BB*CC*6*6];
__device__ float g_f1[BB*CC*9*9];
__device__ __nv_bfloat16 g_f2h[(size_t)BB*400*128];   // t2 out, NHWC bf16
__device__ __nv_bfloat16 g_f3h[(size_t)BB*576*128];   // t3 out, NHWC bf16
__device__ __nv_bfloat16 g_f4h[(size_t)BB*784*128];   // t4 out, NHWC bf16
// packed weights: per tap, [co][ci] row-major, pitch 136 bf16 (272B)
__device__ __nv_bfloat16 g_wp3[25*128*136];
__device__ __nv_bfloat16 g_wp4[25*128*136];
__device__ double g_rec_sum;
__device__ double g_dict_sum;

__global__ void init_kernel() { g_rec_sum = 0.0; g_dict_sum = 0.0; }

__inline__ __device__ float warp_sum(float v) {
    #pragma unroll
    for (int o = 16; o; o >>= 1) v += __shfl_xor_sync(0xffffffffu, v, o);
    return v;
}

// ---------------- mma helpers -------------------------------------------------
__device__ __forceinline__ uint32_t smem_u32(const void* p) {
    uint32_t a;
    asm("{ .reg .u64 t; cvta.to.shared.u64 t, %1; cvt.u32.u64 %0, t; }"
        : "=r"(a) : "l"(p));
    return a;
}

#define LDSM_X4(r0, r1, r2, r3, addr)                                          \
    asm volatile("ldmatrix.sync.aligned.m8n8.x4.shared.b16 {%0,%1,%2,%3}, [%4];" \
                 : "=r"(r0), "=r"(r1), "=r"(r2), "=r"(r3) : "r"(addr))

#define MMA_BF16(c, a0, a1, a2, a3, b0, b1)                                    \
    asm volatile("mma.sync.aligned.m16n8k16.row.col.f32.bf16.bf16.f32 "        \
                 "{%0,%1,%2,%3}, {%4,%5,%6,%7}, {%8,%9}, {%0,%1,%2,%3};"       \
                 : "+f"((c)[0]), "+f"((c)[1]), "+f"((c)[2]), "+f"((c)[3])      \
                 : "r"(a0), "r"(a1), "r"(a2), "r"(a3), "r"(b0), "r"(b1))

// ---------------- weight prepack: torch (in,out,5,5) fp32 -> bf16 [tap][co][ci]
__global__ void prepack_w(const float* __restrict__ W, __nv_bfloat16* __restrict__ dst)
{
    int tap = blockIdx.x;
    int ky = tap / 5, kx = tap - ky * 5;
    __nv_bfloat16* base = dst + (size_t)tap * 128 * 136;
    for (int i = threadIdx.x; i < 16384; i += blockDim.x) {
        int co = i >> 7, ci = i & 127;
        float v = W[(((size_t)ci * 128 + co) * 5 + (4 - ky)) * 5 + (4 - kx)];
        base[co * 136 + ci] = __float2bfloat16(v);
    }
}

// ---------------- tensor-core conv via mma.sync: NHWC bf16, K=5, pad=4 --------
// Grid: (tiles, B), 256 threads / 8 warps. Per CTA: 128 pixels x 128 couts.
// Per warp: 16 pixels x 128 couts, fp32 register accumulators.
__global__ void __launch_bounds__(256)
tc_conv(const __nv_bfloat16* __restrict__ in, const __nv_bfloat16* __restrict__ wpack,
        const float* __restrict__ bias, __nv_bfloat16* __restrict__ out,
        int Hin, int Win, int Hout, int Wout)
{
    extern __shared__ char dsm[];
    __shared__ float sbias[128];

    const int tid  = threadIdx.x;
    const int wid  = tid >> 5;
    const int lane = tid & 31;
    const int b    = blockIdx.y;
    const int Npix = Hout * Wout;
    const int pbase = blockIdx.x * 128;

    // SMEM: A tile 128 rows x 272B, B tile 128 rows x 272B
    char* smAp = dsm;
    char* smBp = dsm + 128 * 272;
    const uint32_t smA = smem_u32(smAp);
    const uint32_t smB = smem_u32(smBp);

    if (tid < 128) sbias[tid] = bias[tid];

    // A staging: thread -> (pixel row, half). 2 threads per row, 64 ci each.
    const int arow = tid >> 1;
    const int ahalf = tid & 1;
    const int ap = pbase + arow;
    const bool apv = (ap < Npix);
    const int apy = apv ? ap / Wout : 0;
    const int apx = apv ? ap - apy * Wout : 0;
    char* adst = smAp + arow * 272 + ahalf * 128;

    float acc[16][4];
    #pragma unroll
    for (int n = 0; n < 16; n++)
        #pragma unroll
        for (int j = 0; j < 4; j++) acc[n][j] = 0.f;

    // ldmatrix address components (constant across taps/k-steps)
    const uint32_t a_base = smA + (wid * 16 + (lane & 15)) * 272 + ((lane >> 4) << 4);
    const uint32_t b_row  = ((lane >> 4) << 3) + (lane & 7);
    const uint32_t b_off  = ((lane >> 3) & 1) << 4;

    for (int tap = 0; tap < 25; ++tap) {
        const int ky = tap / 5, kx = tap - ky * 5;
        __syncthreads();   // protect previous iteration's reads

        // stage B: linear copy of 34816 bytes (prepacked layout == smem layout)
        {
            const uint4* wsrc = (const uint4*)(wpack + (size_t)tap * 128 * 136);
            uint4* wdst = (uint4*)smBp;
            #pragma unroll
            for (int j = 0; j < 8; ++j)
                wdst[j * 256 + tid] = wsrc[j * 256 + tid];
            if (tid < 128) wdst[2048 + tid] = wsrc[2048 + tid];
        }
        // stage A: shifted-window NHWC row (or zeros)
        {
            const int iy = apy + ky - 4, ix = apx + kx - 4;
            const bool inb = apv && (unsigned)iy < (unsigned)Hin && (unsigned)ix < (unsigned)Win;
            const uint4* asrc = (const uint4*)(in + ((size_t)(b * Hin + iy) * Win + ix) * 128
                                               + ahalf * 64);
            #pragma unroll
            for (int j = 0; j < 8; ++j)
                ((uint4*)adst)[j] = inb ? asrc[j] : make_uint4(0u, 0u, 0u, 0u);
        }
        __syncthreads();

        #pragma unroll
        for (int ks = 0; ks < 8; ++ks) {
            uint32_t a0, a1, a2, a3;
            LDSM_X4(a0, a1, a2, a3, a_base + ks * 32);
            #pragma unroll
            for (int p = 0; p < 8; ++p) {
                uint32_t r0, r1, r2, r3;
                uint32_t baddr = smB + (p * 16 + b_row) * 272 + ks * 32 + b_off;
                LDSM_X4(r0, r1, r2, r3, baddr);
                MMA_BF16(acc[2 * p],     a0, a1, a2, a3, r0, r1);
                MMA_BF16(acc[2 * p + 1], a0, a1, a2, a3, r2, r3);
            }
        }
    }

    // epilogue: +bias, relu, bf16, NHWC store
    const int row0 = pbase + wid * 16 + (lane >> 2);
    const int row1 = row0 + 8;
    const bool v0 = (row0 < Npix), v1 = (row1 < Npix);
    __nv_bfloat16* o0 = out + ((size_t)b * Npix + row0) * 128;
    __nv_bfloat16* o1 = out + ((size_t)b * Npix + row1) * 128;
    #pragma unroll
    for (int nt = 0; nt < 16; ++nt) {
        const int co = nt * 8 + 2 * (lane & 3);
        const float bz0 = sbias[co], bz1 = sbias[co + 1];
        if (v0) {
            __nv_bfloat162 h = __floats2bfloat162_rn(fmaxf(acc[nt][0] + bz0, 0.f),
                                                     fmaxf(acc[nt][1] + bz1, 0.f));
            *(uint32_t*)(o0 + co) = *reinterpret_cast<uint32_t*>(&h);
        }
        if (v1) {
            __nv_bfloat162 h = __floats2bfloat162_rn(fmaxf(acc[nt][2] + bz0, 0.f),
                                                     fmaxf(acc[nt][3] + bz1, 0.f));
            *(uint32_t*)(o1 + co) = *reinterpret_cast<uint32_t*>(&h);
        }
    }
}

// ---------------- generic direct conv (fp32 SIMT, exact encoder) --------------
template<int K>
__global__ void __launch_bounds__(256)
conv_direct(const float* __restrict__ in, const float* __restrict__ W,
            const float* __restrict__ bias, float* __restrict__ out,
            int Cin, int Cout, int inH, int inW, int outH, int outW,
            int pad, int relu, int trans, int CIB)
{
    extern __shared__ float sm[];
    const int KK = K * K;
    const int tid = threadIdx.x;
    const int b   = blockIdx.x;
    const int coB = blockIdx.y * 32;
    const int r0  = blockIdx.z * RB;

    const int QW  = (outW + 3) >> 2;
    const int PWA = QW * 4 + K - 1;
    const int TH  = RB + K - 1;

    float* xs = sm;
    float* ws = sm + CIB * TH * PWA;

    const int coq = tid & 7;
    const int pq  = tid >> 3;

    int rbe = outH - r0; if (rbe > RB) rbe = RB;
    const int nquads = rbe * QW;

    int qrow[2], qx[2]; bool qv[2];
    #pragma unroll
    for (int qi = 0; qi < 2; qi++) {
        int q = pq + qi * 32;
        qv[qi] = (q < nquads);
        int qq = qv[qi] ? q : 0;
        qrow[qi] = qq / QW;
        qx[qi]   = (qq - qrow[qi] * QW) << 2;
    }

    float acc[2][4][4];
    #pragma unroll
    for (int a = 0; a < 2; a++)
        #pragma unroll
        for (int j = 0; j < 4; j++)
            #pragma unroll
            for (int k = 0; k < 4; k++) acc[a][j][k] = 0.f;

    const int xsN = CIB * TH * PWA;
    const int wsN = CIB * KK * 32;

    for (int cb = 0; cb < Cin; cb += CIB) {
        for (int i = tid; i < xsN; i += NT) {
            int ci = i / (TH * PWA); int r = i - ci * (TH * PWA);
            int ty = r / PWA;        int tx = r - ty * PWA;
            int iy = r0 + ty - pad;  int ix = tx - pad;
            float v = 0.f;
            if ((unsigned)iy < (unsigned)inH && (unsigned)ix < (unsigned)inW)
                v = in[((size_t)(b * Cin + cb + ci) * inH + iy) * inW + ix];
            xs[i] = v;
        }
        for (int i = tid; i < wsN; i += NT) {
            int col = i & 31; int t = i >> 5;
            int ci = t / KK;  int tap = t - ci * KK;
            int ky = tap / K; int kx = tap - ky * K;
            int cig = cb + ci; int cog = coB + col;
            float wv;
            if (trans)
                wv = W[(((size_t)cig * Cout + cog) * K + (K - 1 - ky)) * K + (K - 1 - kx)];
            else
                wv = W[(((size_t)cog * Cin + cig) * K + ky) * K + kx];
            ws[(ci * KK + tap) * 32 + col] = wv;
        }
        __syncthreads();

        int cie = Cin - cb; if (cie > CIB) cie = CIB;
        for (int ci = 0; ci < cie; ci++) {
            const float* xci = xs + ci * (TH * PWA);
            const float* wci = ws + ci * (KK * 32) + (coq << 2);
            #pragma unroll
            for (int ky = 0; ky < K; ky++) {
                float xa[K + 3], xb[K + 3];
                const float* pa = xci + (qrow[0] + ky) * PWA + qx[0];
                const float* pb = xci + (qrow[1] + ky) * PWA + qx[1];
                #pragma unroll
                for (int t = 0; t < K + 3; t++) { xa[t] = pa[t]; xb[t] = pb[t]; }
                #pragma unroll
                for (int kx = 0; kx < K; kx++) {
                    const float* wp = wci + (ky * K + kx) * 32;
                    float w0 = wp[0], w1 = wp[1], w2 = wp[2], w3 = wp[3];
                    #pragma unroll
                    for (int k = 0; k < 4; k++) {
                        float va = xa[kx + k], vb = xb[kx + k];
                        acc[0][0][k] += w0 * va; acc[0][1][k] += w1 * va;
                        acc[0][2][k] += w2 * va; acc[0][3][k] += w3 * va;
                        acc[1][0][k] += w0 * vb; acc[1][1][k] += w1 * vb;
                        acc[1][2][k] += w2 * vb; acc[1][3][k] += w3 * vb;
                    }
                }
            }
        }
        __syncthreads();
    }

    #pragma unroll
    for (int qi = 0; qi < 2; qi++) {
        if (!qv[qi]) continue;
        int oy = r0 + qrow[qi];
        #pragma unroll
        for (int j = 0; j < 4; j++) {
            int co = coB + coq * 4 + j;
            float bz = bias[co];
            float* op = out + ((size_t)(b * Cout + co) * outH + oy) * outW + qx[qi];
            #pragma unroll
            for (int k = 0; k < 4; k++) {
                int ox = qx[qi] + k;
                if (ox < outW) {
                    float v = acc[qi][j][k] + bz;
                    if (relu) v = fmaxf(v, 0.f);
                    op[k] = v;
                }
            }
        }
    }
}

// -------- stride-2 transposed conv k=4: NCHW fp32 in -> NHWC bf16 out --------
__global__ void __launch_bounds__(256)
deconv_s2_k4(const float* __restrict__ in, const float* __restrict__ W,
             const float* __restrict__ bias, __nv_bfloat16* __restrict__ out)
{
    __shared__ float xs[8 * 81];
    __shared__ float ws[8 * 16 * 32];
    const int tid = threadIdx.x;
    const int b   = blockIdx.x;
    const int coB = blockIdx.y * 32;
    const int r0  = blockIdx.z * 10;
    const int coq = tid & 7;
    const int pq  = tid >> 3;

    int qrow[2], qx[2]; bool qv[2];
    #pragma unroll
    for (int qi = 0; qi < 2; qi++) {
        int q = pq + qi * 32;
        qv[qi] = (q < 50);
        int qq = qv[qi] ? q : 0;
        qrow[qi] = qq / 5;
        qx[qi]   = (qq - qrow[qi] * 5) << 2;
    }

    float acc[2][4][4];
    #pragma unroll
    for (int a = 0; a < 2; a++)
        #pragma unroll
        for (int j = 0; j < 4; j++)
            #pragma unroll
            for (int k = 0; k < 4; k++) acc[a][j][k] = 0.f;

    for (int cb = 0; cb < 128; cb += 8) {
        for (int i = tid; i < 8 * 81; i += NT) {
            int ci = i / 81; int p = i - ci * 81;
            xs[i] = in[(size_t)(b * 128 + cb + ci) * 81 + p];
        }
        for (int i = tid; i < 8 * 16 * 32; i += NT) {
            int col = i & 31; int t = i >> 5;
            int ci = t >> 4;  int tap = t & 15;
            int dy = tap >> 2; int dx = tap & 3;
            ws[i] = W[(((size_t)(cb + ci) * 128 + coB + col) * 4 + (3 - dy)) * 4 + (3 - dx)];
        }
        __syncthreads();

        for (int ci = 0; ci < 8; ci++) {
            const float* xci = xs + ci * 81;
            #pragma unroll
            for (int dy = 0; dy < 4; dy++) {
                int u0 = r0 + qrow[0] + dy - 3;
                int u1 = r0 + qrow[1] + dy - 3;
                bool va = ((u0 & 1) == 0) && u0 >= 0 && u0 <= 16;
                bool vb = ((u1 & 1) == 0) && u1 >= 0 && u1 <= 16;
                const float* ra = xci + ((va ? u0 : 0) >> 1) * 9;
                const float* rb = xci + ((vb ? u1 : 0) >> 1) * 9;
                #pragma unroll
                for (int dx = 0; dx < 4; dx++) {
                    const float* wp = ws + (ci * 16 + dy * 4 + dx) * 32 + (coq << 2);
                    float w0 = wp[0], w1 = wp[1], w2 = wp[2], w3 = wp[3];
                    #pragma unroll
                    for (int k = 0; k < 4; k++) {
                        int v0 = qx[0] + k + dx - 3;
                        if (va && ((v0 & 1) == 0) && v0 >= 0 && v0 <= 16) {
                            float xv = ra[v0 >> 1];
                            acc[0][0][k] += w0 * xv; acc[0][1][k] += w1 * xv;
                            acc[0][2][k] += w2 * xv; acc[0][3][k] += w3 * xv;
                        }
                        int v1 = qx[1] + k + dx - 3;
                        if (vb && ((v1 & 1) == 0) && v1 >= 0 && v1 <= 16) {
                            float xv = rb[v1 >> 1];
                            acc[1][0][k] += w0 * xv; acc[1][1][k] += w1 * xv;
                            acc[1][2][k] += w2 * xv; acc[1][3][k] += w3 * xv;
                        }
                    }
                }
            }
        }
        __syncthreads();
    }

    #pragma unroll
    for (int qi = 0; qi < 2; qi++) {
        if (!qv[qi]) continue;
        int oy = r0 + qrow[qi];
        #pragma unroll
        for (int j = 0; j < 4; j++) {
            int co = coB + coq * 4 + j;
            float bz = bias[co];
            __nv_bfloat16* op = out + ((size_t)b * 400 + oy * 20 + qx[qi]) * 128 + co;
            #pragma unroll
            for (int k = 0; k < 4; k++)
                op[(size_t)k * 128] = __float2bfloat16(fmaxf(acc[qi][j][k] + bz, 0.f));
        }
    }
}

// ---------------- maxpool 2x2 (NCHW fp32) -------------------------------------
__global__ void maxpool2(const float* __restrict__ in, float* __restrict__ out,
                         int planes, int H, int W)
{
    int oh = H >> 1, ow = W >> 1;
    size_t total = (size_t)planes * oh * ow;
    for (size_t i = (size_t)blockIdx.x * blockDim.x + threadIdx.x; i < total;
         i += (size_t)gridDim.x * blockDim.x) {
        int p = (int)(i % (size_t)(oh * ow));
        size_t c = i / (size_t)(oh * ow);
        int y = p / ow, x = p - y * ow;
        const float* ip = in + (c * H + 2 * y) * W + 2 * x;
        out[i] = fmaxf(fmaxf(ip[0], ip[1]), fmaxf(ip[W], ip[W + 1]));
    }
}

// ---------------- VQ: argmax(d2), gather val, dict MSE ------------------------
__global__ void __launch_bounds__(256)
vq_kernel(const float* __restrict__ z, const float* __restrict__ dict,
          float* __restrict__ val, float* __restrict__ idx_out)
{
    extern __shared__ float dsmf[];
    __shared__ float zt[36 * 128];
    __shared__ float wn[128];
    __shared__ int   sidx[36];

    const int b = blockIdx.x, tid = threadIdx.x;

    for (int i = tid; i < 128 * 128; i += NT) {
        int k = i >> 7; int c = i & 127;
        dsmf[k * 129 + c] = dict[i];
    }
    for (int i = tid; i < 36 * 128; i += NT) {
        int pos = i >> 7; int c = i & 127;
        zt[i] = z[(size_t)(b * 128 + c) * 36 + pos];
    }
    __syncthreads();
    if (tid < 128) {
        float s = 0.f;
        const float* dp = dsmf + tid * 129;
        for (int c = 0; c < 128; c++) s += dp[c] * dp[c];
        wn[tid] = s;
    }
    __syncthreads();

    const int lane = tid & 31, wid = tid >> 5;
    for (int pos = wid; pos < 36; pos += 8) {
        float d0 = 0.f, d1 = 0.f, d2s = 0.f, d3 = 0.f, zn = 0.f;
        const float* zp = zt + pos * 128;
        const float* p0 = dsmf + (lane      ) * 129;
        const float* p1 = dsmf + (lane + 32 ) * 129;
        const float* p2 = dsmf + (lane + 64 ) * 129;
        const float* p3 = dsmf + (lane + 96 ) * 129;
        for (int c = 0; c < 128; c++) {
            float zv = zp[c];
            zn += zv * zv;
            d0 += p0[c] * zv; d1 += p1[c] * zv;
            d2s += p2[c] * zv; d3 += p3[c] * zv;
        }
        float bv = zn + wn[lane] - 2.f * d0; int bk = lane;
        float v1 = zn + wn[lane + 32] - 2.f * d1; if (v1 > bv) { bv = v1; bk = lane + 32; }
        float v2 = zn + wn[lane + 64] - 2.f * d2s; if (v2 > bv) { bv = v2; bk = lane + 64; }
        float v3 = zn + wn[lane + 96] - 2.f * d3; if (v3 > bv) { bv = v3; bk = lane + 96; }
        #pragma unroll
        for (int o = 16; o; o >>= 1) {
            float ov = __shfl_xor_sync(0xffffffffu, bv, o);
            int   ok = __shfl_xor_sync(0xffffffffu, bk, o);
            if (ov > bv || (ov == bv && ok < bk)) { bv = ov; bk = ok; }
        }
        if (lane == 0) {
            sidx[pos] = bk;
            if (idx_out) idx_out[b * 36 + pos] = (float)bk;
        }
    }
    __syncthreads();

    float lsum = 0.f;
    for (int i = tid; i < 4608; i += NT) {
        int c = i / 36; int pos = i - c * 36;
        float v  = dsmf[sidx[pos] * 129 + c];
        float zv = zt[pos * 128 + c];
        val[(size_t)(b * 128 + c) * 36 + pos] = v;
        float d = v - zv;
        lsum += d * d;
    }
    lsum = warp_sum(lsum);
    if ((tid & 31) == 0) atomicAdd(&g_dict_sum, (double)lsum);
}

// ---------------- mu (1x1 conv) fused with reconstruction loss (NHWC bf16) ---
__global__ void __launch_bounds__(256)
mu_loss(const __nv_bfloat16* __restrict__ f4, const float* __restrict__ x,
        const float* __restrict__ mw, const float* __restrict__ mb)
{
    __shared__ float mws[128];
    const int b = blockIdx.x, tid = threadIdx.x;
    if (tid < 128) mws[tid] = mw[tid];
    __syncthreads();
    float lsum = 0.f;
    for (int px = tid; px < 784; px += NT) {
        const uint4* fp = (const uint4*)(f4 + ((size_t)b * 784 + px) * 128);
        float s = mb[0];
        #pragma unroll
        for (int j = 0; j < 16; j++) {
            uint4 v = fp[j];
            const __nv_bfloat16* h = (const __nv_bfloat16*)&v;
            #pragma unroll
            for (int t = 0; t < 8; t++)
                s += __bfloat162float(h[t]) * mws[j * 8 + t];
        }
        float d = s - x[(size_t)b * 784 + px];
        lsum += d * d;
    }
    lsum = warp_sum(lsum);
    if ((tid & 31) == 0) atomicAdd(&g_rec_sum, (double)lsum);
}

__global__ void finalize_kernel(float* loss_out)
{
    if (loss_out) {
        double dict_mse = g_dict_sum / 1179648.0;
        loss_out[0] = (float)(g_rec_sum / 200704.0);
        loss_out[1] = (float)(dict_mse * 5.0);
        loss_out[2] = (float)(dict_mse * 1.25);
        loss_out[3] = 0.f;
    }
}

// ---------------- host side ----------------------------------------------------
static void launch_conv(int K, const float* in, const float* W, const float* bias,
                        float* out, int Cin, int inH, int inW, int outH, int outW,
                        int pad, int relu, int trans)
{
    int CIB = (Cin >= 8) ? 8 : 1;
    int QW = (outW + 3) / 4;
    int PWA = QW * 4 + K - 1;
    int TH = RB + K - 1;
    size_t smem = (size_t)(CIB * TH * PWA + CIB * K * K * 32) * sizeof(float);
    dim3 grid(BB, 128 / 32, (outH + RB - 1) / RB);
    if (K == 5)
        conv_direct<5><<<grid, NT, smem>>>(in, W, bias, out, Cin, 128,
                                           inH, inW, outH, outW, pad, relu, trans, CIB);
    else
        conv_direct<4><<<grid, NT, smem>>>(in, W, bias, out, Cin, 128,
                                           inH, inW, outH, outW, pad, relu, trans, CIB);
}

extern "C" void kernel_launch(void* const* d_in, const int* in_sizes, int n_in,
                              void* d_out, int out_size)
{
    const float* x    = (const float*)d_in[0];
    const float* w1   = (const float*)d_in[1];
    const float* b1   = (const float*)d_in[2];
    const float* w2   = (const float*)d_in[3];
    const float* b2   = (const float*)d_in[4];
    const float* w3   = (const float*)d_in[5];
    const float* b3   = (const float*)d_in[6];
    const float* t1w  = (const float*)d_in[7];
    const float* t1b  = (const float*)d_in[8];
    const float* t2w  = (const float*)d_in[9];
    const float* t2b  = (const float*)d_in[10];
    const float* t3w  = (const float*)d_in[11];
    const float* t3b  = (const float*)d_in[12];
    const float* t4w  = (const float*)d_in[13];
    const float* t4b  = (const float*)d_in[14];
    const float* mw   = (const float*)d_in[15];
    const float* mb   = (const float*)d_in[16];
    const float* dictw= (const float*)d_in[17];

    float* outp = (float*)d_out;
    float* loss_ptr = outp;
    float* idx_ptr  = outp + 4;
    if (out_size < 9220) { loss_ptr = nullptr; idx_ptr = outp; }

    float *a1, *a2, *p1, *a3, *zb, *valb, *f1;
    __nv_bfloat16 *f2h, *f3h, *f4h, *wp3, *wp4;
    cudaGetSymbolAddress((void**)&a1, g_a1);
    cudaGetSymbolAddress((void**)&a2, g_a2);
    cudaGetSymbolAddress((void**)&p1, g_p1);
    cudaGetSymbolAddress((void**)&a3, g_a3);
    cudaGetSymbolAddress((void**)&zb, g_z);
    cudaGetSymbolAddress((void**)&valb, g_val);
    cudaGetSymbolAddress((void**)&f1, g_f1);
    cudaGetSymbolAddress((void**)&f2h, g_f2h);
    cudaGetSymbolAddress((void**)&f3h, g_f3h);
    cudaGetSymbolAddress((void**)&f4h, g_f4h);
    cudaGetSymbolAddress((void**)&wp3, g_wp3);
    cudaGetSymbolAddress((void**)&wp4, g_wp4);

    static bool attr_set = false;
    if (!attr_set) {
        cudaFuncSetAttribute(vq_kernel, cudaFuncAttributeMaxDynamicSharedMemorySize,
                             128 * 129 * (int)sizeof(float));
        cudaFuncSetAttribute(tc_conv, cudaFuncAttributeMaxDynamicSharedMemorySize,
                             2 * 128 * 272);
        attr_set = true;
    }

    init_kernel<<<1, 1>>>();

    // weight prepack for tensor-core decoder layers
    prepack_w<<<25, 256>>>(t3w, wp3);
    prepack_w<<<25, 256>>>(t4w, wp4);

    // encoder (fp32 exact — determines index output)
    launch_conv(5, x,  w1, b1, a1, 1,   28, 28, 24, 24, 0, 1, 0);
    launch_conv(5, a1, w2, b2, a2, 128, 24, 24, 24, 24, 2, 1, 0);
    maxpool2<<<1024, 256>>>(a2, p1, BB * CC, 24, 24);
    launch_conv(5, p1, w3, b3, a3, 128, 12, 12, 12, 12, 2, 0, 0);
    maxpool2<<<256, 256>>>(a3, zb, BB * CC, 12, 12);

    // VQ
    vq_kernel<<<BB, NT, 128 * 129 * sizeof(float)>>>(zb, dictw, valb, idx_ptr);

    // decoder: t1 fp32 NCHW, t2 fp32 -> NHWC bf16, t3/t4 HMMA bf16
    launch_conv(4, valb, t1w, t1b, f1, 128, 6, 6, 9, 9, 3, 1, 1);
    deconv_s2_k4<<<dim3(BB, 4, 2), NT>>>(f1, t2w, t2b, f2h);
    tc_conv<<<dim3(5, BB), 256, 2 * 128 * 272>>>(f2h, wp3, t3b, f3h, 20, 20, 24, 24);
    tc_conv<<<dim3(7, BB), 256, 2 * 128 * 272>>>(f3h, wp4, t4b, f4h, 24, 24, 28, 28);

    // mu + losses
    mu_loss<<<BB, NT>>>(f4h, x, mw, mb);
    finalize_kernel<<<1, 1>>>(loss_ptr);
}

// round 5
// speedup vs baseline: 2.6313x; 1.6402x over previous
#include <cuda_runtime.h>
#include <cuda_bf16.h>
#include <cuda_fp16.h>
#include <cstdint>

#define BB 256
#define NT 256
#define RB 8

// ---------------- scratch (device globals; no allocation APIs) ---------------
__device__ __half g_c1hi[(size_t)BB*576*128];       // conv1 out hi, NHWC fp16
__device__ __half g_c1lo[(size_t)BB*576*128];       // conv1 out lo
__device__ float  g_c2f [(size_t)BB*576*128];       // conv2 out, NHWC fp32
__device__ __half g_p1hi[(size_t)BB*144*128];       // pool1 hi, NHWC fp16
__device__ __half g_p1lo[(size_t)BB*144*128];
__device__ float  g_c3f [(size_t)BB*144*128];       // conv3 out, NHWC fp32
__device__ float  g_zn  [(size_t)BB*36*128];        // z, NHWC fp32
__device__ float  g_val [(size_t)BB*128*36];        // gathered codes, NCHW fp32
__device__ float  g_f1  [(size_t)BB*128*81];        // t1 out, NCHW fp32
__device__ __nv_bfloat16 g_f2h[(size_t)BB*400*128]; // t2 out, NHWC bf16
__device__ __nv_bfloat16 g_f3h[(size_t)BB*576*128]; // t3 out, NHWC bf16
__device__ __nv_bfloat16 g_f4h[(size_t)BB*784*128]; // t4 out, NHWC bf16
// packed weights: per tap, [co][ci] row-major, pitch 136 elems (272B)
__device__ __nv_bfloat16 g_wp3[25*128*136];
__device__ __nv_bfloat16 g_wp4[25*128*136];
__device__ __half g_w2hi[25*128*136];
__device__ __half g_w2lo[25*128*136];
__device__ __half g_w3hi[25*128*136];
__device__ __half g_w3lo[25*128*136];
__device__ double g_rec_sum;
__device__ double g_dict_sum;

__global__ void init_kernel() { g_rec_sum = 0.0; g_dict_sum = 0.0; }

__inline__ __device__ float warp_sum(float v) {
    #pragma unroll
    for (int o = 16; o; o >>= 1) v += __shfl_xor_sync(0xffffffffu, v, o);
    return v;
}

// ---------------- mma / cp.async helpers --------------------------------------
__device__ __forceinline__ uint32_t smem_u32(const void* p) {
    uint32_t a;
    asm("{ .reg .u64 t; cvta.to.shared.u64 t, %1; cvt.u32.u64 %0, t; }"
        : "=r"(a) : "l"(p));
    return a;
}

#define LDSM_X4(r0, r1, r2, r3, addr)                                          \
    asm volatile("ldmatrix.sync.aligned.m8n8.x4.shared.b16 {%0,%1,%2,%3}, [%4];" \
                 : "=r"(r0), "=r"(r1), "=r"(r2), "=r"(r3) : "r"(addr))

#define MMA_BF16(c, a0, a1, a2, a3, b0, b1)                                    \
    asm volatile("mma.sync.aligned.m16n8k16.row.col.f32.bf16.bf16.f32 "        \
                 "{%0,%1,%2,%3}, {%4,%5,%6,%7}, {%8,%9}, {%0,%1,%2,%3};"       \
                 : "+f"((c)[0]), "+f"((c)[1]), "+f"((c)[2]), "+f"((c)[3])      \
                 : "r"(a0), "r"(a1), "r"(a2), "r"(a3), "r"(b0), "r"(b1))

#define MMA_F16(c, a0, a1, a2, a3, b0, b1)                                     \
    asm volatile("mma.sync.aligned.m16n8k16.row.col.f32.f16.f16.f32 "          \
                 "{%0,%1,%2,%3}, {%4,%5,%6,%7}, {%8,%9}, {%0,%1,%2,%3};"       \
                 : "+f"((c)[0]), "+f"((c)[1]), "+f"((c)[2]), "+f"((c)[3])      \
                 : "r"(a0), "r"(a1), "r"(a2), "r"(a3), "r"(b0), "r"(b1))

#define CP16(d, s, n)                                                          \
    asm volatile("cp.async.cg.shared.global [%0], [%1], 16, %2;"               \
                 :: "r"(d), "l"(s), "r"(n))
#define CP_COMMIT() asm volatile("cp.async.commit_group;" ::: "memory")
#define CP_WAIT0()  asm volatile("cp.async.wait_group 0;" ::: "memory")

// ---------------- weight prepack (bf16, deconv flip/transpose) ----------------
__global__ void prepack_w(const float* __restrict__ W, __nv_bfloat16* __restrict__ dst)
{
    int tap = blockIdx.x;
    int ky = tap / 5, kx = tap - ky * 5;
    __nv_bfloat16* base = dst + (size_t)tap * 128 * 136;
    for (int i = threadIdx.x; i < 16384; i += blockDim.x) {
        int co = i >> 7, ci = i & 127;
        float v = W[(((size_t)ci * 128 + co) * 5 + (4 - ky)) * 5 + (4 - kx)];
        base[co * 136 + ci] = __float2bfloat16(v);
    }
}

// ---------------- weight prepack (fp16 hi/lo split, forward conv) -------------
__global__ void prepack_fwd_split(const float* __restrict__ W,
                                  __half* __restrict__ dh, __half* __restrict__ dl)
{
    int tap = blockIdx.x;
    int ky = tap / 5, kx = tap - ky * 5;
    size_t tb = (size_t)tap * 128 * 136;
    for (int i = threadIdx.x; i < 16384; i += blockDim.x) {
        int co = i >> 7, ci = i & 127;
        float v = W[(((size_t)co * 128 + ci) * 5 + ky) * 5 + kx];
        __half h = __float2half_rn(v);
        dh[tb + co * 136 + ci] = h;
        dl[tb + co * 136 + ci] = __float2half_rn(v - __half2float(h));
    }
}

// ---------------- pipelined tensor-core conv engine ---------------------------
// PASSES=1: single precision pass (bf16 data). PASSES=3: fp16 split
// (hi*Whi + lo*Whi + hi*Wlo). Grid (tiles, B), 256 thr / 8 warps.
// Per CTA: 128 output pixels x 128 couts; K=5 conv, padding 'pad'.
template<int PASSES, int FP16>
__global__ void __launch_bounds__(256)
tc_eng(const uint16_t* __restrict__ inHi, const uint16_t* __restrict__ inLo,
       const uint16_t* __restrict__ wHi,  const uint16_t* __restrict__ wLo,
       const float* __restrict__ bias, void* __restrict__ outp,
       int Hin, int Win, int Hout, int Wout, int pad, int relu, int outfp32)
{
    extern __shared__ char dsm[];
    __shared__ float sbias[128];
    const int tid  = threadIdx.x;
    const int wid  = tid >> 5;
    const int lane = tid & 31;
    const int b    = blockIdx.y;
    const int Npix = Hout * Wout;
    const int pbase = blockIdx.x * 128;

    const uint32_t smA = smem_u32(dsm);            // 2 x 34816
    const uint32_t smB = smA + 2 * 34816;          // 2 x 34816
    if (tid < 128) sbias[tid] = bias[tid];

    // A staging: 2 threads per pixel row, 128B each
    const int arow = tid >> 1, ahalf = tid & 1;
    const int ap = pbase + arow;
    const bool apv = (ap < Npix);
    const int apy = apv ? ap / Wout : 0;
    const int apx = apv ? ap - apy * Wout : 0;
    const uint32_t adst0 = smA + arow * 272 + ahalf * 128;

    float acc[16][4];
    #pragma unroll
    for (int n = 0; n < 16; n++)
        #pragma unroll
        for (int j = 0; j < 4; j++) acc[n][j] = 0.f;

    const uint32_t a_rd0 = smA + (wid * 16 + (lane & 15)) * 272 + ((lane >> 4) << 4);
    const uint32_t b_row = ((lane >> 4) << 3) + (lane & 7);
    const uint32_t b_off = ((lane >> 3) & 1) << 4;
    const int NIT = PASSES * 25;

    auto stage = [&](int it) {
        const int buf = it & 1;
        const int tap = it % 25;
        const int pass = it / 25;
        const int ky = tap / 5, kx = tap - ky * 5;
        // B tile (prepacked layout == smem layout): 2176 x 16B
        const char* wb = (const char*)(((PASSES == 3 && pass == 2) ? wLo : wHi)
                                       + (size_t)tap * 128 * 136);
        const uint32_t bd = smB + buf * 34816;
        #pragma unroll
        for (int j = 0; j < 8; ++j)
            CP16(bd + (j * 256 + tid) * 16, wb + (size_t)(j * 256 + tid) * 16, 16);
        if (tid < 128)
            CP16(bd + (2048 + tid) * 16, wb + (size_t)(2048 + tid) * 16, 16);
        // A tile: shifted window row (zero-fill OOB via src-size 0)
        const uint16_t* asb = (PASSES == 3 && pass == 1) ? inLo : inHi;
        const int iy = apy + ky - pad, ix = apx + kx - pad;
        const bool inb = apv && (unsigned)iy < (unsigned)Hin && (unsigned)ix < (unsigned)Win;
        const char* as = inb ? (const char*)(asb + ((size_t)(b * Hin + iy) * Win + ix) * 128
                                             + ahalf * 64)
                             : (const char*)asb;
        const uint32_t ad = adst0 + buf * 34816;
        const int sz = inb ? 16 : 0;
        #pragma unroll
        for (int j = 0; j < 8; ++j)
            CP16(ad + j * 16, as + (size_t)j * 16, sz);
        CP_COMMIT();
    };

    stage(0);
    for (int it = 0; it < NIT; ++it) {
        CP_WAIT0();
        __syncthreads();
        if (it + 1 < NIT) stage(it + 1);
        const uint32_t abase = a_rd0 + (it & 1) * 34816;
        const uint32_t bbase = smB + (it & 1) * 34816;
        #pragma unroll
        for (int ks = 0; ks < 8; ++ks) {
            uint32_t a0, a1, a2, a3;
            LDSM_X4(a0, a1, a2, a3, abase + ks * 32);
            #pragma unroll
            for (int p = 0; p < 8; ++p) {
                uint32_t r0, r1, r2, r3;
                LDSM_X4(r0, r1, r2, r3, bbase + (p * 16 + b_row) * 272 + ks * 32 + b_off);
                if (FP16) {
                    MMA_F16(acc[2 * p],     a0, a1, a2, a3, r0, r1);
                    MMA_F16(acc[2 * p + 1], a0, a1, a2, a3, r2, r3);
                } else {
                    MMA_BF16(acc[2 * p],     a0, a1, a2, a3, r0, r1);
                    MMA_BF16(acc[2 * p + 1], a0, a1, a2, a3, r2, r3);
                }
            }
        }
        __syncthreads();
    }

    // epilogue
    const int row0 = pbase + wid * 16 + (lane >> 2);
    const int row1 = row0 + 8;
    const bool v0 = (row0 < Npix), v1 = (row1 < Npix);
    #pragma unroll
    for (int nt = 0; nt < 16; ++nt) {
        const int co = nt * 8 + 2 * (lane & 3);
        const float bz0 = sbias[co], bz1 = sbias[co + 1];
        float p00 = acc[nt][0] + bz0, p01 = acc[nt][1] + bz1;
        float p10 = acc[nt][2] + bz0, p11 = acc[nt][3] + bz1;
        if (relu) {
            p00 = fmaxf(p00, 0.f); p01 = fmaxf(p01, 0.f);
            p10 = fmaxf(p10, 0.f); p11 = fmaxf(p11, 0.f);
        }
        if (outfp32) {
            float* of = (float*)outp;
            if (v0) *(float2*)(of + ((size_t)b * Npix + row0) * 128 + co) = make_float2(p00, p01);
            if (v1) *(float2*)(of + ((size_t)b * Npix + row1) * 128 + co) = make_float2(p10, p11);
        } else {
            __nv_bfloat16* ob = (__nv_bfloat16*)outp;
            if (v0) {
                __nv_bfloat162 h = __floats2bfloat162_rn(p00, p01);
                *(uint32_t*)(ob + ((size_t)b * Npix + row0) * 128 + co) =
                    *reinterpret_cast<uint32_t*>(&h);
            }
            if (v1) {
                __nv_bfloat162 h = __floats2bfloat162_rn(p10, p11);
                *(uint32_t*)(ob + ((size_t)b * Npix + row1) * 128 + co) =
                    *reinterpret_cast<uint32_t*>(&h);
            }
        }
    }
}

// ---------------- conv1 (Cin=1) fused with fp16 hi/lo split, NHWC -------------
__global__ void __launch_bounds__(128)
conv1_split(const float* __restrict__ x, const float* __restrict__ w1,
            const float* __restrict__ b1, __half* __restrict__ hi,
            __half* __restrict__ lo)
{
    const int b = blockIdx.x, p = blockIdx.y, co = threadIdx.x;
    const int oy = p / 24, ox = p - oy * 24;
    __shared__ float xs[25];
    if (co < 25) {
        int ky = co / 5, kx = co - (co / 5) * 5;
        xs[co] = x[(size_t)b * 784 + (oy + ky) * 28 + ox + kx];
    }
    __syncthreads();
    const float* w = w1 + co * 25;
    float v = b1[co];
    #pragma unroll
    for (int t = 0; t < 25; ++t) v += w[t] * xs[t];
    v = fmaxf(v, 0.f);
    __half h = __float2half_rn(v);
    size_t o = ((size_t)b * 576 + p) * 128 + co;
    hi[o] = h;
    lo[o] = __float2half_rn(v - __half2float(h));
}

// ---------------- NHWC maxpool 2x2: fp32 -> fp16 hi/lo -----------------------
__global__ void mp_split_nhwc(const float* __restrict__ in, __half* __restrict__ hi,
                              __half* __restrict__ lo, int Hin, int Win)
{
    const int Ho = Hin >> 1, Wo = Win >> 1;
    const size_t total = (size_t)BB * Ho * Wo * 128;
    for (size_t i = (size_t)blockIdx.x * blockDim.x + threadIdx.x; i < total;
         i += (size_t)gridDim.x * blockDim.x) {
        int c = (int)(i & 127);
        size_t r = i >> 7;
        int wo = (int)(r % Wo); r /= Wo;
        int ho = (int)(r % Ho); int b = (int)(r / Ho);
        const float* p = in + (((size_t)b * Hin + 2 * ho) * Win + 2 * wo) * 128 + c;
        float v = fmaxf(fmaxf(p[0], p[128]),
                        fmaxf(p[(size_t)Win * 128], p[(size_t)(Win + 1) * 128]));
        __half h = __float2half_rn(v);
        hi[i] = h;
        lo[i] = __float2half_rn(v - __half2float(h));
    }
}

// ---------------- NHWC maxpool 2x2: fp32 -> fp32 -----------------------------
__global__ void mp_nhwc(const float* __restrict__ in, float* __restrict__ out,
                        int Hin, int Win)
{
    const int Ho = Hin >> 1, Wo = Win >> 1;
    const size_t total = (size_t)BB * Ho * Wo * 128;
    for (size_t i = (size_t)blockIdx.x * blockDim.x + threadIdx.x; i < total;
         i += (size_t)gridDim.x * blockDim.x) {
        int c = (int)(i & 127);
        size_t r = i >> 7;
        int wo = (int)(r % Wo); r /= Wo;
        int ho = (int)(r % Ho); int b = (int)(r / Ho);
        const float* p = in + (((size_t)b * Hin + 2 * ho) * Win + 2 * wo) * 128 + c;
        out[i] = fmaxf(fmaxf(p[0], p[128]),
                       fmaxf(p[(size_t)Win * 128], p[(size_t)(Win + 1) * 128]));
    }
}

// ---------------- generic direct conv (fp32 SIMT; used for t1) ----------------
template<int K>
__global__ void __launch_bounds__(256)
conv_direct(const float* __restrict__ in, const float* __restrict__ W,
            const float* __restrict__ bias, float* __restrict__ out,
            int Cin, int Cout, int inH, int inW, int outH, int outW,
            int pad, int relu, int trans, int CIB)
{
    extern __shared__ float sm[];
    const int KK = K * K;
    const int tid = threadIdx.x;
    const int b   = blockIdx.x;
    const int coB = blockIdx.y * 32;
    const int r0  = blockIdx.z * RB;

    const int QW  = (outW + 3) >> 2;
    const int PWA = QW * 4 + K - 1;
    const int TH  = RB + K - 1;

    float* xs = sm;
    float* ws = sm + CIB * TH * PWA;

    const int coq = tid & 7;
    const int pq  = tid >> 3;

    int rbe = outH - r0; if (rbe > RB) rbe = RB;
    const int nquads = rbe * QW;

    int qrow[2], qx[2]; bool qv[2];
    #pragma unroll
    for (int qi = 0; qi < 2; qi++) {
        int q = pq + qi * 32;
        qv[qi] = (q < nquads);
        int qq = qv[qi] ? q : 0;
        qrow[qi] = qq / QW;
        qx[qi]   = (qq - qrow[qi] * QW) << 2;
    }

    float acc[2][4][4];
    #pragma unroll
    for (int a = 0; a < 2; a++)
        #pragma unroll
        for (int j = 0; j < 4; j++)
            #pragma unroll
            for (int k = 0; k < 4; k++) acc[a][j][k] = 0.f;

    const int xsN = CIB * TH * PWA;
    const int wsN = CIB * KK * 32;

    for (int cb = 0; cb < Cin; cb += CIB) {
        for (int i = tid; i < xsN; i += NT) {
            int ci = i / (TH * PWA); int r = i - ci * (TH * PWA);
            int ty = r / PWA;        int tx = r - ty * PWA;
            int iy = r0 + ty - pad;  int ix = tx - pad;
            float v = 0.f;
            if ((unsigned)iy < (unsigned)inH && (unsigned)ix < (unsigned)inW)
                v = in[((size_t)(b * Cin + cb + ci) * inH + iy) * inW + ix];
            xs[i] = v;
        }
        for (int i = tid; i < wsN; i += NT) {
            int col = i & 31; int t = i >> 5;
            int ci = t / KK;  int tap = t - ci * KK;
            int ky = tap / K; int kx = tap - ky * K;
            int cig = cb + ci; int cog = coB + col;
            float wv;
            if (trans)
                wv = W[(((size_t)cig * Cout + cog) * K + (K - 1 - ky)) * K + (K - 1 - kx)];
            else
                wv = W[(((size_t)cog * Cin + cig) * K + ky) * K + kx];
            ws[(ci * KK + tap) * 32 + col] = wv;
        }
        __syncthreads();

        int cie = Cin - cb; if (cie > CIB) cie = CIB;
        for (int ci = 0; ci < cie; ci++) {
            const float* xci = xs + ci * (TH * PWA);
            const float* wci = ws + ci * (KK * 32) + (coq << 2);
            #pragma unroll
            for (int ky = 0; ky < K; ky++) {
                float xa[K + 3], xb[K + 3];
                const float* pa = xci + (qrow[0] + ky) * PWA + qx[0];
                const float* pb = xci + (qrow[1] + ky) * PWA + qx[1];
                #pragma unroll
                for (int t = 0; t < K + 3; t++) { xa[t] = pa[t]; xb[t] = pb[t]; }
                #pragma unroll
                for (int kx = 0; kx < K; kx++) {
                    const float* wp = wci + (ky * K + kx) * 32;
                    float w0 = wp[0], w1 = wp[1], w2 = wp[2], w3 = wp[3];
                    #pragma unroll
                    for (int k = 0; k < 4; k++) {
                        float va = xa[kx + k], vb = xb[kx + k];
                        acc[0][0][k] += w0 * va; acc[0][1][k] += w1 * va;
                        acc[0][2][k] += w2 * va; acc[0][3][k] += w3 * va;
                        acc[1][0][k] += w0 * vb; acc[1][1][k] += w1 * vb;
                        acc[1][2][k] += w2 * vb; acc[1][3][k] += w3 * vb;
                    }
                }
            }
        }
        __syncthreads();
    }

    #pragma unroll
    for (int qi = 0; qi < 2; qi++) {
        if (!qv[qi]) continue;
        int oy = r0 + qrow[qi];
        #pragma unroll
        for (int j = 0; j < 4; j++) {
            int co = coB + coq * 4 + j;
            float bz = bias[co];
            float* op = out + ((size_t)(b * Cout + co) * outH + oy) * outW + qx[qi];
            #pragma unroll
            for (int k = 0; k < 4; k++) {
                int ox = qx[qi] + k;
                if (ox < outW) {
                    float v = acc[qi][j][k] + bz;
                    if (relu) v = fmaxf(v, 0.f);
                    op[k] = v;
                }
            }
        }
    }
}

// -------- stride-2 transposed conv k=4: NCHW fp32 in -> NHWC bf16 out --------
__global__ void __launch_bounds__(256)
deconv_s2_k4(const float* __restrict__ in, const float* __restrict__ W,
             const float* __restrict__ bias, __nv_bfloat16* __restrict__ out)
{
    __shared__ float xs[8 * 81];
    __shared__ float ws[8 * 16 * 32];
    const int tid = threadIdx.x;
    const int b   = blockIdx.x;
    const int coB = blockIdx.y * 32;
    const int r0  = blockIdx.z * 10;
    const int coq = tid & 7;
    const int pq  = tid >> 3;

    int qrow[2], qx[2]; bool qv[2];
    #pragma unroll
    for (int qi = 0; qi < 2; qi++) {
        int q = pq + qi * 32;
        qv[qi] = (q < 50);
        int qq = qv[qi] ? q : 0;
        qrow[qi] = qq / 5;
        qx[qi]   = (qq - qrow[qi] * 5) << 2;
    }

    float acc[2][4][4];
    #pragma unroll
    for (int a = 0; a < 2; a++)
        #pragma unroll
        for (int j = 0; j < 4; j++)
            #pragma unroll
            for (int k = 0; k < 4; k++) acc[a][j][k] = 0.f;

    for (int cb = 0; cb < 128; cb += 8) {
        for (int i = tid; i < 8 * 81; i += NT) {
            int ci = i / 81; int p = i - ci * 81;
            xs[i] = in[(size_t)(b * 128 + cb + ci) * 81 + p];
        }
        for (int i = tid; i < 8 * 16 * 32; i += NT) {
            int col = i & 31; int t = i >> 5;
            int ci = t >> 4;  int tap = t & 15;
            int dy = tap >> 2; int dx = tap & 3;
            ws[i] = W[(((size_t)(cb + ci) * 128 + coB + col) * 4 + (3 - dy)) * 4 + (3 - dx)];
        }
        __syncthreads();

        for (int ci = 0; ci < 8; ci++) {
            const float* xci = xs + ci * 81;
            #pragma unroll
            for (int dy = 0; dy < 4; dy++) {
                int u0 = r0 + qrow[0] + dy - 3;
                int u1 = r0 + qrow[1] + dy - 3;
                bool va = ((u0 & 1) == 0) && u0 >= 0 && u0 <= 16;
                bool vb = ((u1 & 1) == 0) && u1 >= 0 && u1 <= 16;
                const float* ra = xci + ((va ? u0 : 0) >> 1) * 9;
                const float* rb = xci + ((vb ? u1 : 0) >> 1) * 9;
                #pragma unroll
                for (int dx = 0; dx < 4; dx++) {
                    const float* wp = ws + (ci * 16 + dy * 4 + dx) * 32 + (coq << 2);
                    float w0 = wp[0], w1 = wp[1], w2 = wp[2], w3 = wp[3];
                    #pragma unroll
                    for (int k = 0; k < 4; k++) {
                        int v0 = qx[0] + k + dx - 3;
                        if (va && ((v0 & 1) == 0) && v0 >= 0 && v0 <= 16) {
                            float xv = ra[v0 >> 1];
                            acc[0][0][k] += w0 * xv; acc[0][1][k] += w1 * xv;
                            acc[0][2][k] += w2 * xv; acc[0][3][k] += w3 * xv;
                        }
                        int v1 = qx[1] + k + dx - 3;
                        if (vb && ((v1 & 1) == 0) && v1 >= 0 && v1 <= 16) {
                            float xv = rb[v1 >> 1];
                            acc[1][0][k] += w0 * xv; acc[1][1][k] += w1 * xv;
                            acc[1][2][k] += w2 * xv; acc[1][3][k] += w3 * xv;
                        }
                    }
                }
            }
        }
        __syncthreads();
    }

    #pragma unroll
    for (int qi = 0; qi < 2; qi++) {
        if (!qv[qi]) continue;
        int oy = r0 + qrow[qi];
        #pragma unroll
        for (int j = 0; j < 4; j++) {
            int co = coB + coq * 4 + j;
            float bz = bias[co];
            __nv_bfloat16* op = out + ((size_t)b * 400 + oy * 20 + qx[qi]) * 128 + co;
            #pragma unroll
            for (int k = 0; k < 4; k++)
                op[(size_t)k * 128] = __float2bfloat16(fmaxf(acc[qi][j][k] + bz, 0.f));
        }
    }
}

// ---------------- VQ: argmax(d2), gather val, dict MSE (z in NHWC) ------------
__global__ void __launch_bounds__(256)
vq_kernel(const float* __restrict__ z, const float* __restrict__ dict,
          float* __restrict__ val, float* __restrict__ idx_out)
{
    extern __shared__ float dsmf[];           // 128 * 129
    __shared__ float zt[36 * 128];            // zt[pos*128 + c]
    __shared__ float wn[128];
    __shared__ int   sidx[36];

    const int b = blockIdx.x, tid = threadIdx.x;

    for (int i = tid; i < 128 * 128; i += NT) {
        int k = i >> 7; int c = i & 127;
        dsmf[k * 129 + c] = dict[i];
    }
    for (int i = tid; i < 36 * 128; i += NT)
        zt[i] = z[(size_t)b * 4608 + i];
    __syncthreads();
    if (tid < 128) {
        float s = 0.f;
        const float* dp = dsmf + tid * 129;
        for (int c = 0; c < 128; c++) s += dp[c] * dp[c];
        wn[tid] = s;
    }
    __syncthreads();

    const int lane = tid & 31, wid = tid >> 5;
    for (int pos = wid; pos < 36; pos += 8) {
        float d0 = 0.f, d1 = 0.f, d2s = 0.f, d3 = 0.f, zn = 0.f;
        const float* zp = zt + pos * 128;
        const float* p0 = dsmf + (lane      ) * 129;
        const float* p1 = dsmf + (lane + 32 ) * 129;
        const float* p2 = dsmf + (lane + 64 ) * 129;
        const float* p3 = dsmf + (lane + 96 ) * 129;
        for (int c = 0; c < 128; c++) {
            float zv = zp[c];
            zn += zv * zv;
            d0 += p0[c] * zv; d1 += p1[c] * zv;
            d2s += p2[c] * zv; d3 += p3[c] * zv;
        }
        float bv = zn + wn[lane] - 2.f * d0; int bk = lane;
        float v1 = zn + wn[lane + 32] - 2.f * d1; if (v1 > bv) { bv = v1; bk = lane + 32; }
        float v2 = zn + wn[lane + 64] - 2.f * d2s; if (v2 > bv) { bv = v2; bk = lane + 64; }
        float v3 = zn + wn[lane + 96] - 2.f * d3; if (v3 > bv) { bv = v3; bk = lane + 96; }
        #pragma unroll
        for (int o = 16; o; o >>= 1) {
            float ov = __shfl_xor_sync(0xffffffffu, bv, o);
            int   ok = __shfl_xor_sync(0xffffffffu, bk, o);
            if (ov > bv || (ov == bv && ok < bk)) { bv = ov; bk = ok; }
        }
        if (lane == 0) {
            sidx[pos] = bk;
            if (idx_out) idx_out[b * 36 + pos] = (float)bk;
        }
    }
    __syncthreads();

    float lsum = 0.f;
    for (int i = tid; i < 4608; i += NT) {
        int c = i / 36; int pos = i - c * 36;
        float v  = dsmf[sidx[pos] * 129 + c];
        float zv = zt[pos * 128 + c];
        val[(size_t)(b * 128 + c) * 36 + pos] = v;
        float d = v - zv;
        lsum += d * d;
    }
    lsum = warp_sum(lsum);
    if ((tid & 31) == 0) atomicAdd(&g_dict_sum, (double)lsum);
}

// ---------------- mu (1x1 conv) fused with reconstruction loss (NHWC bf16) ---
__global__ void __launch_bounds__(256)
mu_loss(const __nv_bfloat16* __restrict__ f4, const float* __restrict__ x,
        const float* __restrict__ mw, const float* __restrict__ mb)
{
    __shared__ float mws[128];
    const int b = blockIdx.x, tid = threadIdx.x;
    if (tid < 128) mws[tid] = mw[tid];
    __syncthreads();
    float lsum = 0.f;
    for (int px = tid; px < 784; px += NT) {
        const uint4* fp = (const uint4*)(f4 + ((size_t)b * 784 + px) * 128);
        float s = mb[0];
        #pragma unroll
        for (int j = 0; j < 16; j++) {
            uint4 v = fp[j];
            const __nv_bfloat16* h = (const __nv_bfloat16*)&v;
            #pragma unroll
            for (int t = 0; t < 8; t++)
                s += __bfloat162float(h[t]) * mws[j * 8 + t];
        }
        float d = s - x[(size_t)b * 784 + px];
        lsum += d * d;
    }
    lsum = warp_sum(lsum);
    if ((tid & 31) == 0) atomicAdd(&g_rec_sum, (double)lsum);
}

__global__ void finalize_kernel(float* loss_out)
{
    if (loss_out) {
        double dict_mse = g_dict_sum / 1179648.0;
        loss_out[0] = (float)(g_rec_sum / 200704.0);
        loss_out[1] = (float)(dict_mse * 5.0);
        loss_out[2] = (float)(dict_mse * 1.25);
        loss_out[3] = 0.f;
    }
}

// ---------------- host side ----------------------------------------------------
static void launch_conv(int K, const float* in, const float* W, const float* bias,
                        float* out, int Cin, int inH, int inW, int outH, int outW,
                        int pad, int relu, int trans)
{
    int CIB = (Cin >= 8) ? 8 : 1;
    int QW = (outW + 3) / 4;
    int PWA = QW * 4 + K - 1;
    int TH = RB + K - 1;
    size_t smem = (size_t)(CIB * TH * PWA + CIB * K * K * 32) * sizeof(float);
    dim3 grid(BB, 128 / 32, (outH + RB - 1) / RB);
    if (K == 5)
        conv_direct<5><<<grid, NT, smem>>>(in, W, bias, out, Cin, 128,
                                           inH, inW, outH, outW, pad, relu, trans, CIB);
    else
        conv_direct<4><<<grid, NT, smem>>>(in, W, bias, out, Cin, 128,
                                           inH, inW, outH, outW, pad, relu, trans, CIB);
}

extern "C" void kernel_launch(void* const* d_in, const int* in_sizes, int n_in,
                              void* d_out, int out_size)
{
    const float* x    = (const float*)d_in[0];
    const float* w1   = (const float*)d_in[1];
    const float* b1   = (const float*)d_in[2];
    const float* w2   = (const float*)d_in[3];
    const float* b2   = (const float*)d_in[4];
    const float* w3   = (const float*)d_in[5];
    const float* b3   = (const float*)d_in[6];
    const float* t1w  = (const float*)d_in[7];
    const float* t1b  = (const float*)d_in[8];
    const float* t2w  = (const float*)d_in[9];
    const float* t2b  = (const float*)d_in[10];
    const float* t3w  = (const float*)d_in[11];
    const float* t3b  = (const float*)d_in[12];
    const float* t4w  = (const float*)d_in[13];
    const float* t4b  = (const float*)d_in[14];
    const float* mw   = (const float*)d_in[15];
    const float* mb   = (const float*)d_in[16];
    const float* dictw= (const float*)d_in[17];

    float* outp = (float*)d_out;
    float* loss_ptr = outp;
    float* idx_ptr  = outp + 4;
    if (out_size < 9220) { loss_ptr = nullptr; idx_ptr = outp; }

    __half *c1hi, *c1lo, *p1hi, *p1lo, *w2hi, *w2lo, *w3hi, *w3lo;
    float *c2f, *c3f, *zn, *valb, *f1;
    __nv_bfloat16 *f2h, *f3h, *f4h, *wp3, *wp4;
    cudaGetSymbolAddress((void**)&c1hi, g_c1hi);
    cudaGetSymbolAddress((void**)&c1lo, g_c1lo);
    cudaGetSymbolAddress((void**)&c2f,  g_c2f);
    cudaGetSymbolAddress((void**)&p1hi, g_p1hi);
    cudaGetSymbolAddress((void**)&p1lo, g_p1lo);
    cudaGetSymbolAddress((void**)&c3f,  g_c3f);
    cudaGetSymbolAddress((void**)&zn,   g_zn);
    cudaGetSymbolAddress((void**)&valb, g_val);
    cudaGetSymbolAddress((void**)&f1,   g_f1);
    cudaGetSymbolAddress((void**)&f2h,  g_f2h);
    cudaGetSymbolAddress((void**)&f3h,  g_f3h);
    cudaGetSymbolAddress((void**)&f4h,  g_f4h);
    cudaGetSymbolAddress((void**)&wp3,  g_wp3);
    cudaGetSymbolAddress((void**)&wp4,  g_wp4);
    cudaGetSymbolAddress((void**)&w2hi, g_w2hi);
    cudaGetSymbolAddress((void**)&w2lo, g_w2lo);
    cudaGetSymbolAddress((void**)&w3hi, g_w3hi);
    cudaGetSymbolAddress((void**)&w3lo, g_w3lo);

    static bool attr_set = false;
    if (!attr_set) {
        cudaFuncSetAttribute(vq_kernel, cudaFuncAttributeMaxDynamicSharedMemorySize,
                             128 * 129 * (int)sizeof(float));
        cudaFuncSetAttribute(tc_eng<1, 0>, cudaFuncAttributeMaxDynamicSharedMemorySize,
                             4 * 34816);
        cudaFuncSetAttribute(tc_eng<3, 1>, cudaFuncAttributeMaxDynamicSharedMemorySize,
                             4 * 34816);
        attr_set = true;
    }

    init_kernel<<<1, 1>>>();

    // weight prepacks
    prepack_w<<<25, 256>>>(t3w, wp3);
    prepack_w<<<25, 256>>>(t4w, wp4);
    prepack_fwd_split<<<25, 256>>>(w2, w2hi, w2lo);
    prepack_fwd_split<<<25, 256>>>(w3, w3hi, w3lo);

    // encoder: conv1 fp32 exact, conv2/conv3 fp16-split tensor path
    conv1_split<<<dim3(BB, 576), 128>>>(x, w1, b1, c1hi, c1lo);
    tc_eng<3, 1><<<dim3(5, BB), 256, 4 * 34816>>>(
        (const uint16_t*)c1hi, (const uint16_t*)c1lo,
        (const uint16_t*)w2hi, (const uint16_t*)w2lo,
        b2, c2f, 24, 24, 24, 24, 2, 1, 1);
    mp_split_nhwc<<<4096, 256>>>(c2f, p1hi, p1lo, 24, 24);
    tc_eng<3, 1><<<dim3(2, BB), 256, 4 * 34816>>>(
        (const uint16_t*)p1hi, (const uint16_t*)p1lo,
        (const uint16_t*)w3hi, (const uint16_t*)w3lo,
        b3, c3f, 12, 12, 12, 12, 2, 0, 1);
    mp_nhwc<<<2048, 256>>>(c3f, zn, 12, 12);

    // VQ
    vq_kernel<<<BB, NT, 128 * 129 * sizeof(float)>>>(zn, dictw, valb, idx_ptr);

    // decoder: t1 fp32, t2 fp32 -> NHWC bf16, t3/t4 pipelined bf16 tensor path
    launch_conv(4, valb, t1w, t1b, f1, 128, 6, 6, 9, 9, 3, 1, 1);
    deconv_s2_k4<<<dim3(BB, 4, 2), NT>>>(f1, t2w, t2b, f2h);
    tc_eng<1, 0><<<dim3(5, BB), 256, 4 * 34816>>>(
        (const uint16_t*)f2h, nullptr, (const uint16_t*)wp3, nullptr,
        t3b, f3h, 20, 20, 24, 24, 4, 1, 0);
    tc_eng<1, 0><<<dim3(7, BB), 256, 4 * 34816>>>(
        (const uint16_t*)f3h, nullptr, (const uint16_t*)wp4, nullptr,
        t4b, f4h, 24, 24, 28, 28, 4, 1, 0);

    // mu + losses
    mu_loss<<<BB, NT>>>(f4h, x, mw, mb);
    finalize_kernel<<<1, 1>>>(loss_ptr);
}

// round 6
// speedup vs baseline: 3.6529x; 1.3882x over previous
#include <cuda_runtime.h>
#include <cuda_bf16.h>
#include <cuda_fp16.h>
#include <cstdint>

#define BB 256
#define NT 256
#define TILE 34816

// ---------------- scratch (device globals; no allocation APIs) ---------------
__device__ __half g_c1hi[(size_t)BB*576*128];       // conv1 out hi, NHWC fp16
__device__ __half g_c1lo[(size_t)BB*576*128];       // conv1 out lo
__device__ float  g_c2f [(size_t)BB*576*128];       // conv2 out, NHWC fp32
__device__ __half g_p1hi[(size_t)BB*144*128];       // pool1 hi, NHWC fp16
__device__ __half g_p1lo[(size_t)BB*144*128];
__device__ float  g_c3f [(size_t)BB*144*128];       // conv3 out, NHWC fp32
__device__ float  g_zn  [(size_t)BB*36*128];        // z, NHWC fp32
__device__ __nv_bfloat16 g_valh[(size_t)BB*36*128]; // gathered codes, NHWC bf16
__device__ float  g_f1  [(size_t)BB*128*81];        // t1 out, NCHW fp32
__device__ __nv_bfloat16 g_f2h[(size_t)BB*400*128]; // t2 out, NHWC bf16
__device__ __nv_bfloat16 g_f3h[(size_t)BB*576*128]; // t3 out, NHWC bf16
__device__ __nv_bfloat16 g_f4h[(size_t)BB*784*128]; // t4 out, NHWC bf16
// packed weights: per tap, [co][ci] row-major, pitch 136 elems (272B)
__device__ __nv_bfloat16 g_wp1[16*128*136];
__device__ __nv_bfloat16 g_wp3[25*128*136];
__device__ __nv_bfloat16 g_wp4[25*128*136];
__device__ __half g_w2hi[25*128*136];
__device__ __half g_w2lo[25*128*136];
__device__ __half g_w3hi[25*128*136];
__device__ __half g_w3lo[25*128*136];
__device__ double g_rec_sum;
__device__ double g_dict_sum;

__global__ void init_kernel() { g_rec_sum = 0.0; g_dict_sum = 0.0; }

__inline__ __device__ float warp_sum(float v) {
    #pragma unroll
    for (int o = 16; o; o >>= 1) v += __shfl_xor_sync(0xffffffffu, v, o);
    return v;
}

// ---------------- mma / cp.async helpers --------------------------------------
__device__ __forceinline__ uint32_t smem_u32(const void* p) {
    uint32_t a;
    asm("{ .reg .u64 t; cvta.to.shared.u64 t, %1; cvt.u32.u64 %0, t; }"
        : "=r"(a) : "l"(p));
    return a;
}

#define LDSM_X4(r0, r1, r2, r3, addr)                                          \
    asm volatile("ldmatrix.sync.aligned.m8n8.x4.shared.b16 {%0,%1,%2,%3}, [%4];" \
                 : "=r"(r0), "=r"(r1), "=r"(r2), "=r"(r3) : "r"(addr))

#define MMA_BF16(c, a0, a1, a2, a3, b0, b1)                                    \
    asm volatile("mma.sync.aligned.m16n8k16.row.col.f32.bf16.bf16.f32 "        \
                 "{%0,%1,%2,%3}, {%4,%5,%6,%7}, {%8,%9}, {%0,%1,%2,%3};"       \
                 : "+f"((c)[0]), "+f"((c)[1]), "+f"((c)[2]), "+f"((c)[3])      \
                 : "r"(a0), "r"(a1), "r"(a2), "r"(a3), "r"(b0), "r"(b1))

#define MMA_F16(c, a0, a1, a2, a3, b0, b1)                                     \
    asm volatile("mma.sync.aligned.m16n8k16.row.col.f32.f16.f16.f32 "          \
                 "{%0,%1,%2,%3}, {%4,%5,%6,%7}, {%8,%9}, {%0,%1,%2,%3};"       \
                 : "+f"((c)[0]), "+f"((c)[1]), "+f"((c)[2]), "+f"((c)[3])      \
                 : "r"(a0), "r"(a1), "r"(a2), "r"(a3), "r"(b0), "r"(b1))

#define CP16(d, s, n)                                                          \
    asm volatile("cp.async.cg.shared.global [%0], [%1], 16, %2;"               \
                 :: "r"(d), "l"(s), "r"(n))
#define CP_COMMIT() asm volatile("cp.async.commit_group;" ::: "memory")
#define CP_WAIT0()  asm volatile("cp.async.wait_group 0;" ::: "memory")
#define CP_WAIT1()  asm volatile("cp.async.wait_group 1;" ::: "memory")

// ---------------- weight prepack (bf16, deconv flip/transpose, runtime K) -----
__global__ void prepack_w(const float* __restrict__ W, __nv_bfloat16* __restrict__ dst,
                          int K)
{
    int tap = blockIdx.x;
    int ky = tap / K, kx = tap - ky * K;
    __nv_bfloat16* base = dst + (size_t)tap * 128 * 136;
    for (int i = threadIdx.x; i < 16384; i += blockDim.x) {
        int co = i >> 7, ci = i & 127;
        float v = W[(((size_t)ci * 128 + co) * K + (K - 1 - ky)) * K + (K - 1 - kx)];
        base[co * 136 + ci] = __float2bfloat16(v);
    }
}

// ---------------- weight prepack (fp16 hi/lo split, forward conv k=5) ---------
__global__ void prepack_fwd_split(const float* __restrict__ W,
                                  __half* __restrict__ dh, __half* __restrict__ dl)
{
    int tap = blockIdx.x;
    int ky = tap / 5, kx = tap - ky * 5;
    size_t tb = (size_t)tap * 128 * 136;
    for (int i = threadIdx.x; i < 16384; i += blockDim.x) {
        int co = i >> 7, ci = i & 127;
        float v = W[(((size_t)co * 128 + ci) * 5 + ky) * 5 + kx];
        __half h = __float2half_rn(v);
        dh[tb + co * 136 + ci] = h;
        dl[tb + co * 136 + ci] = __float2half_rn(v - __half2float(h));
    }
}

// ================= fused 3-pass fp16-split encoder conv (K=5) =================
// acc = A_hi*W_hi + A_lo*W_hi + A_hi*W_lo  (~22-bit mantissa, fp32-equivalent)
// SMEM: Ahi[2], Bhi[2], Alo, Blo  = 6 * TILE = 208896 B. Grid (tiles, B).
__global__ void __launch_bounds__(256)
tc_enc3(const uint16_t* __restrict__ inHi, const uint16_t* __restrict__ inLo,
        const uint16_t* __restrict__ wHi,  const uint16_t* __restrict__ wLo,
        const float* __restrict__ bias, float* __restrict__ outp,
        int Hin, int Win, int Hout, int Wout, int pad, int relu)
{
    extern __shared__ char dsm[];
    __shared__ float sbias[128];
    const int tid  = threadIdx.x;
    const int wid  = tid >> 5;
    const int lane = tid & 31;
    const int b    = blockIdx.y;
    const int Npix = Hout * Wout;
    const int pbase = blockIdx.x * 128;

    const uint32_t smAhi = smem_u32(dsm);           // 2 * TILE
    const uint32_t smBhi = smAhi + 2 * TILE;        // 2 * TILE
    const uint32_t smAlo = smAhi + 4 * TILE;        // TILE
    const uint32_t smBlo = smAhi + 5 * TILE;        // TILE
    if (tid < 128) sbias[tid] = bias[tid];

    const int arow = tid >> 1, ahalf = tid & 1;
    const int ap = pbase + arow;
    const bool apv = (ap < Npix);
    const int apy = apv ? ap / Wout : 0;
    const int apx = apv ? ap - apy * Wout : 0;
    const uint32_t aoff = arow * 272 + ahalf * 128;

    float acc[16][4];
    #pragma unroll
    for (int n = 0; n < 16; n++)
        #pragma unroll
        for (int j = 0; j < 4; j++) acc[n][j] = 0.f;

    const uint32_t a_rdoff = (wid * 16 + (lane & 15)) * 272 + ((lane >> 4) << 4);
    const uint32_t b_row = ((lane >> 4) << 3) + (lane & 7);
    const uint32_t b_off = ((lane >> 3) & 1) << 4;

    auto stage_pair = [&](const uint16_t* abuf, const uint16_t* wbuf, int tap,
                          uint32_t adst, uint32_t bdst) {
        const int ky = tap / 5, kx = tap - ky * 5;
        const char* wb = (const char*)(wbuf + (size_t)tap * 128 * 136);
        #pragma unroll
        for (int j = 0; j < 8; ++j)
            CP16(bdst + (j * 256 + tid) * 16, wb + (size_t)(j * 256 + tid) * 16, 16);
        if (tid < 128)
            CP16(bdst + (2048 + tid) * 16, wb + (size_t)(2048 + tid) * 16, 16);
        const int iy = apy + ky - pad, ix = apx + kx - pad;
        const bool inb = apv && (unsigned)iy < (unsigned)Hin && (unsigned)ix < (unsigned)Win;
        const char* as = inb ? (const char*)(abuf + ((size_t)(b * Hin + iy) * Win + ix) * 128
                                             + ahalf * 64)
                             : (const char*)abuf;
        const int sz = inb ? 16 : 0;
        const uint32_t ad = adst + aoff;
        #pragma unroll
        for (int j = 0; j < 8; ++j)
            CP16(ad + j * 16, as + (size_t)j * 16, sz);
    };

    auto mma_pass = [&](uint32_t abase, uint32_t bbase) {
        #pragma unroll
        for (int ks = 0; ks < 8; ++ks) {
            uint32_t a0, a1, a2, a3;
            LDSM_X4(a0, a1, a2, a3, abase + a_rdoff + ks * 32);
            #pragma unroll
            for (int p = 0; p < 8; ++p) {
                uint32_t r0, r1, r2, r3;
                LDSM_X4(r0, r1, r2, r3, bbase + (p * 16 + b_row) * 272 + ks * 32 + b_off);
                MMA_F16(acc[2 * p],     a0, a1, a2, a3, r0, r1);
                MMA_F16(acc[2 * p + 1], a0, a1, a2, a3, r2, r3);
            }
        }
    };

    stage_pair(inHi, wHi, 0, smAhi, smBhi);
    CP_COMMIT();

    for (int tap = 0; tap < 25; ++tap) {
        const int buf = tap & 1;
        CP_WAIT0();
        __syncthreads();
        // lo tiles for this tap (single-buffered; prev pass2/3 done at sync)
        stage_pair(inLo, wLo, tap, smAlo, smBlo);
        CP_COMMIT();
        if (tap < 24) {
            stage_pair(inHi, wHi, tap + 1, smAhi + (buf ^ 1) * TILE,
                       smBhi + (buf ^ 1) * TILE);
            CP_COMMIT();
        }
        mma_pass(smAhi + buf * TILE, smBhi + buf * TILE);   // pass 1: hi*Whi
        if (tap < 24) CP_WAIT1(); else CP_WAIT0();
        __syncthreads();
        mma_pass(smAlo, smBhi + buf * TILE);                // pass 2: lo*Whi
        mma_pass(smAhi + buf * TILE, smBlo);                // pass 3: hi*Wlo
    }

    // epilogue: fp32 NHWC out
    const int row0 = pbase + wid * 16 + (lane >> 2);
    const int row1 = row0 + 8;
    const bool v0 = (row0 < Npix), v1 = (row1 < Npix);
    #pragma unroll
    for (int nt = 0; nt < 16; ++nt) {
        const int co = nt * 8 + 2 * (lane & 3);
        const float bz0 = sbias[co], bz1 = sbias[co + 1];
        float p00 = acc[nt][0] + bz0, p01 = acc[nt][1] + bz1;
        float p10 = acc[nt][2] + bz0, p11 = acc[nt][3] + bz1;
        if (relu) {
            p00 = fmaxf(p00, 0.f); p01 = fmaxf(p01, 0.f);
            p10 = fmaxf(p10, 0.f); p11 = fmaxf(p11, 0.f);
        }
        if (v0) *(float2*)(outp + ((size_t)b * Npix + row0) * 128 + co) = make_float2(p00, p01);
        if (v1) *(float2*)(outp + ((size_t)b * Npix + row1) * 128 + co) = make_float2(p10, p11);
    }
}

// ================= 1-pass bf16 pipelined conv engine (runtime K) ===============
// outfmt: 0 = NHWC bf16, 2 = NCHW fp32. Grid (tiles, B). SMEM 4*TILE.
__global__ void __launch_bounds__(256)
tc_eng1(const uint16_t* __restrict__ in, const uint16_t* __restrict__ wpack,
        const float* __restrict__ bias, void* __restrict__ outp,
        int Hin, int Win, int Hout, int Wout, int pad, int relu, int K, int outfmt)
{
    extern __shared__ char dsm[];
    __shared__ float sbias[128];
    const int tid  = threadIdx.x;
    const int wid  = tid >> 5;
    const int lane = tid & 31;
    const int b    = blockIdx.y;
    const int Npix = Hout * Wout;
    const int pbase = blockIdx.x * 128;

    const uint32_t smA = smem_u32(dsm);
    const uint32_t smB = smA + 2 * TILE;
    if (tid < 128) sbias[tid] = bias[tid];

    const int arow = tid >> 1, ahalf = tid & 1;
    const int ap = pbase + arow;
    const bool apv = (ap < Npix);
    const int apy = apv ? ap / Wout : 0;
    const int apx = apv ? ap - apy * Wout : 0;
    const uint32_t adst0 = smA + arow * 272 + ahalf * 128;

    float acc[16][4];
    #pragma unroll
    for (int n = 0; n < 16; n++)
        #pragma unroll
        for (int j = 0; j < 4; j++) acc[n][j] = 0.f;

    const uint32_t a_rd0 = smA + (wid * 16 + (lane & 15)) * 272 + ((lane >> 4) << 4);
    const uint32_t b_row = ((lane >> 4) << 3) + (lane & 7);
    const uint32_t b_off = ((lane >> 3) & 1) << 4;
    const int NIT = K * K;

    auto stage = [&](int tap) {
        const int buf = tap & 1;
        const int ky = tap / K, kx = tap - ky * K;
        const char* wb = (const char*)(wpack + (size_t)tap * 128 * 136);
        const uint32_t bd = smB + buf * TILE;
        #pragma unroll
        for (int j = 0; j < 8; ++j)
            CP16(bd + (j * 256 + tid) * 16, wb + (size_t)(j * 256 + tid) * 16, 16);
        if (tid < 128)
            CP16(bd + (2048 + tid) * 16, wb + (size_t)(2048 + tid) * 16, 16);
        const int iy = apy + ky - pad, ix = apx + kx - pad;
        const bool inb = apv && (unsigned)iy < (unsigned)Hin && (unsigned)ix < (unsigned)Win;
        const char* as = inb ? (const char*)(in + ((size_t)(b * Hin + iy) * Win + ix) * 128
                                             + ahalf * 64)
                             : (const char*)in;
        const uint32_t ad = adst0 + buf * TILE;
        const int sz = inb ? 16 : 0;
        #pragma unroll
        for (int j = 0; j < 8; ++j)
            CP16(ad + j * 16, as + (size_t)j * 16, sz);
        CP_COMMIT();
    };

    stage(0);
    for (int it = 0; it < NIT; ++it) {
        CP_WAIT0();
        __syncthreads();
        if (it + 1 < NIT) stage(it + 1);
        const uint32_t abase = a_rd0 + (it & 1) * TILE;
        const uint32_t bbase = smB + (it & 1) * TILE;
        #pragma unroll
        for (int ks = 0; ks < 8; ++ks) {
            uint32_t a0, a1, a2, a3;
            LDSM_X4(a0, a1, a2, a3, abase + ks * 32);
            #pragma unroll
            for (int p = 0; p < 8; ++p) {
                uint32_t r0, r1, r2, r3;
                LDSM_X4(r0, r1, r2, r3, bbase + (p * 16 + b_row) * 272 + ks * 32 + b_off);
                MMA_BF16(acc[2 * p],     a0, a1, a2, a3, r0, r1);
                MMA_BF16(acc[2 * p + 1], a0, a1, a2, a3, r2, r3);
            }
        }
        __syncthreads();
    }

    const int row0 = pbase + wid * 16 + (lane >> 2);
    const int row1 = row0 + 8;
    const bool v0 = (row0 < Npix), v1 = (row1 < Npix);
    #pragma unroll
    for (int nt = 0; nt < 16; ++nt) {
        const int co = nt * 8 + 2 * (lane & 3);
        const float bz0 = sbias[co], bz1 = sbias[co + 1];
        float p00 = acc[nt][0] + bz0, p01 = acc[nt][1] + bz1;
        float p10 = acc[nt][2] + bz0, p11 = acc[nt][3] + bz1;
        if (relu) {
            p00 = fmaxf(p00, 0.f); p01 = fmaxf(p01, 0.f);
            p10 = fmaxf(p10, 0.f); p11 = fmaxf(p11, 0.f);
        }
        if (outfmt == 0) {
            __nv_bfloat16* ob = (__nv_bfloat16*)outp;
            if (v0) {
                __nv_bfloat162 h = __floats2bfloat162_rn(p00, p01);
                *(uint32_t*)(ob + ((size_t)b * Npix + row0) * 128 + co) =
                    *reinterpret_cast<uint32_t*>(&h);
            }
            if (v1) {
                __nv_bfloat162 h = __floats2bfloat162_rn(p10, p11);
                *(uint32_t*)(ob + ((size_t)b * Npix + row1) * 128 + co) =
                    *reinterpret_cast<uint32_t*>(&h);
            }
        } else {
            float* of = (float*)outp;
            if (v0) {
                of[((size_t)b * 128 + co) * Npix + row0]     = p00;
                of[((size_t)b * 128 + co + 1) * Npix + row0] = p01;
            }
            if (v1) {
                of[((size_t)b * 128 + co) * Npix + row1]     = p10;
                of[((size_t)b * 128 + co + 1) * Npix + row1] = p11;
            }
        }
    }
}

// ---------------- conv1 (Cin=1) fused with fp16 hi/lo split, NHWC -------------
__global__ void __launch_bounds__(128)
conv1_split(const float* __restrict__ x, const float* __restrict__ w1,
            const float* __restrict__ b1, __half* __restrict__ hi,
            __half* __restrict__ lo)
{
    const int b = blockIdx.x, p = blockIdx.y, co = threadIdx.x;
    const int oy = p / 24, ox = p - oy * 24;
    __shared__ float xs[25];
    if (co < 25) {
        int ky = co / 5, kx = co - (co / 5) * 5;
        xs[co] = x[(size_t)b * 784 + (oy + ky) * 28 + ox + kx];
    }
    __syncthreads();
    const float* w = w1 + co * 25;
    float v = b1[co];
    #pragma unroll
    for (int t = 0; t < 25; ++t) v += w[t] * xs[t];
    v = fmaxf(v, 0.f);
    __half h = __float2half_rn(v);
    size_t o = ((size_t)b * 576 + p) * 128 + co;
    hi[o] = h;
    lo[o] = __float2half_rn(v - __half2float(h));
}

// ---------------- NHWC maxpool 2x2: fp32 -> fp16 hi/lo -----------------------
__global__ void mp_split_nhwc(const float* __restrict__ in, __half* __restrict__ hi,
                              __half* __restrict__ lo, int Hin, int Win)
{
    const int Ho = Hin >> 1, Wo = Win >> 1;
    const size_t total = (size_t)BB * Ho * Wo * 128;
    for (size_t i = (size_t)blockIdx.x * blockDim.x + threadIdx.x; i < total;
         i += (size_t)gridDim.x * blockDim.x) {
        int c = (int)(i & 127);
        size_t r = i >> 7;
        int wo = (int)(r % Wo); r /= Wo;
        int ho = (int)(r % Ho); int b = (int)(r / Ho);
        const float* p = in + (((size_t)b * Hin + 2 * ho) * Win + 2 * wo) * 128 + c;
        float v = fmaxf(fmaxf(p[0], p[128]),
                        fmaxf(p[(size_t)Win * 128], p[(size_t)(Win + 1) * 128]));
        __half h = __float2half_rn(v);
        hi[i] = h;
        lo[i] = __float2half_rn(v - __half2float(h));
    }
}

// ---------------- NHWC maxpool 2x2: fp32 -> fp32 -----------------------------
__global__ void mp_nhwc(const float* __restrict__ in, float* __restrict__ out,
                        int Hin, int Win)
{
    const int Ho = Hin >> 1, Wo = Win >> 1;
    const size_t total = (size_t)BB * Ho * Wo * 128;
    for (size_t i = (size_t)blockIdx.x * blockDim.x + threadIdx.x; i < total;
         i += (size_t)gridDim.x * blockDim.x) {
        int c = (int)(i & 127);
        size_t r = i >> 7;
        int wo = (int)(r % Wo); r /= Wo;
        int ho = (int)(r % Ho); int b = (int)(r / Ho);
        const float* p = in + (((size_t)b * Hin + 2 * ho) * Win + 2 * wo) * 128 + c;
        out[i] = fmaxf(fmaxf(p[0], p[128]),
                       fmaxf(p[(size_t)Win * 128], p[(size_t)(Win + 1) * 128]));
    }
}

// -------- stride-2 transposed conv k=4: NCHW fp32 in -> NHWC bf16 out --------
__global__ void __launch_bounds__(256)
deconv_s2_k4(const float* __restrict__ in, const float* __restrict__ W,
             const float* __restrict__ bias, __nv_bfloat16* __restrict__ out)
{
    __shared__ float xs[8 * 81];
    __shared__ float ws[8 * 16 * 32];
    const int tid = threadIdx.x;
    const int b   = blockIdx.x;
    const int coB = blockIdx.y * 32;
    const int r0  = blockIdx.z * 10;
    const int coq = tid & 7;
    const int pq  = tid >> 3;

    int qrow[2], qx[2]; bool qv[2];
    #pragma unroll
    for (int qi = 0; qi < 2; qi++) {
        int q = pq + qi * 32;
        qv[qi] = (q < 50);
        int qq = qv[qi] ? q : 0;
        qrow[qi] = qq / 5;
        qx[qi]   = (qq - qrow[qi] * 5) << 2;
    }

    float acc[2][4][4];
    #pragma unroll
    for (int a = 0; a < 2; a++)
        #pragma unroll
        for (int j = 0; j < 4; j++)
            #pragma unroll
            for (int k = 0; k < 4; k++) acc[a][j][k] = 0.f;

    for (int cb = 0; cb < 128; cb += 8) {
        for (int i = tid; i < 8 * 81; i += NT) {
            int ci = i / 81; int p = i - ci * 81;
            xs[i] = in[(size_t)(b * 128 + cb + ci) * 81 + p];
        }
        for (int i = tid; i < 8 * 16 * 32; i += NT) {
            int col = i & 31; int t = i >> 5;
            int ci = t >> 4;  int tap = t & 15;
            int dy = tap >> 2; int dx = tap & 3;
            ws[i] = W[(((size_t)(cb + ci) * 128 + coB + col) * 4 + (3 - dy)) * 4 + (3 - dx)];
        }
        __syncthreads();

        for (int ci = 0; ci < 8; ci++) {
            const float* xci = xs + ci * 81;
            #pragma unroll
            for (int dy = 0; dy < 4; dy++) {
                int u0 = r0 + qrow[0] + dy - 3;
                int u1 = r0 + qrow[1] + dy - 3;
                bool va = ((u0 & 1) == 0) && u0 >= 0 && u0 <= 16;
                bool vb = ((u1 & 1) == 0) && u1 >= 0 && u1 <= 16;
                const float* ra = xci + ((va ? u0 : 0) >> 1) * 9;
                const float* rb = xci + ((vb ? u1 : 0) >> 1) * 9;
                #pragma unroll
                for (int dx = 0; dx < 4; dx++) {
                    const float* wp = ws + (ci * 16 + dy * 4 + dx) * 32 + (coq << 2);
                    float w0 = wp[0], w1 = wp[1], w2 = wp[2], w3 = wp[3];
                    #pragma unroll
                    for (int k = 0; k < 4; k++) {
                        int v0 = qx[0] + k + dx - 3;
                        if (va && ((v0 & 1) == 0) && v0 >= 0 && v0 <= 16) {
                            float xv = ra[v0 >> 1];
                            acc[0][0][k] += w0 * xv; acc[0][1][k] += w1 * xv;
                            acc[0][2][k] += w2 * xv; acc[0][3][k] += w3 * xv;
                        }
                        int v1 = qx[1] + k + dx - 3;
                        if (vb && ((v1 & 1) == 0) && v1 >= 0 && v1 <= 16) {
                            float xv = rb[v1 >> 1];
                            acc[1][0][k] += w0 * xv; acc[1][1][k] += w1 * xv;
                            acc[1][2][k] += w2 * xv; acc[1][3][k] += w3 * xv;
                        }
                    }
                }
            }
        }
        __syncthreads();
    }

    #pragma unroll
    for (int qi = 0; qi < 2; qi++) {
        if (!qv[qi]) continue;
        int oy = r0 + qrow[qi];
        #pragma unroll
        for (int j = 0; j < 4; j++) {
            int co = coB + coq * 4 + j;
            float bz = bias[co];
            __nv_bfloat16* op = out + ((size_t)b * 400 + oy * 20 + qx[qi]) * 128 + co;
            #pragma unroll
            for (int k = 0; k < 4; k++)
                op[(size_t)k * 128] = __float2bfloat16(fmaxf(acc[qi][j][k] + bz, 0.f));
        }
    }
}

// ---------------- VQ: argmax(d2), gather val (NHWC bf16), dict MSE ------------
__global__ void __launch_bounds__(256)
vq_kernel(const float* __restrict__ z, const float* __restrict__ dict,
          __nv_bfloat16* __restrict__ valh, float* __restrict__ idx_out)
{
    extern __shared__ float dsmf[];           // 128 * 129
    __shared__ float zt[36 * 128];            // zt[pos*128 + c]
    __shared__ float wn[128];
    __shared__ int   sidx[36];

    const int b = blockIdx.x, tid = threadIdx.x;

    for (int i = tid; i < 128 * 128; i += NT) {
        int k = i >> 7; int c = i & 127;
        dsmf[k * 129 + c] = dict[i];
    }
    for (int i = tid; i < 36 * 128; i += NT)
        zt[i] = z[(size_t)b * 4608 + i];
    __syncthreads();
    if (tid < 128) {
        float s = 0.f;
        const float* dp = dsmf + tid * 129;
        for (int c = 0; c < 128; c++) s += dp[c] * dp[c];
        wn[tid] = s;
    }
    __syncthreads();

    const int lane = tid & 31, wid = tid >> 5;
    for (int pos = wid; pos < 36; pos += 8) {
        float d0 = 0.f, d1 = 0.f, d2s = 0.f, d3 = 0.f, zn = 0.f;
        const float* zp = zt + pos * 128;
        const float* p0 = dsmf + (lane      ) * 129;
        const float* p1 = dsmf + (lane + 32 ) * 129;
        const float* p2 = dsmf + (lane + 64 ) * 129;
        const float* p3 = dsmf + (lane + 96 ) * 129;
        for (int c = 0; c < 128; c++) {
            float zv = zp[c];
            zn += zv * zv;
            d0 += p0[c] * zv; d1 += p1[c] * zv;
            d2s += p2[c] * zv; d3 += p3[c] * zv;
        }
        float bv = zn + wn[lane] - 2.f * d0; int bk = lane;
        float v1 = zn + wn[lane + 32] - 2.f * d1; if (v1 > bv) { bv = v1; bk = lane + 32; }
        float v2 = zn + wn[lane + 64] - 2.f * d2s; if (v2 > bv) { bv = v2; bk = lane + 64; }
        float v3 = zn + wn[lane + 96] - 2.f * d3; if (v3 > bv) { bv = v3; bk = lane + 96; }
        #pragma unroll
        for (int o = 16; o; o >>= 1) {
            float ov = __shfl_xor_sync(0xffffffffu, bv, o);
            int   ok = __shfl_xor_sync(0xffffffffu, bk, o);
            if (ov > bv || (ov == bv && ok < bk)) { bv = ov; bk = ok; }
        }
        if (lane == 0) {
            sidx[pos] = bk;
            if (idx_out) idx_out[b * 36 + pos] = (float)bk;
        }
    }
    __syncthreads();

    float lsum = 0.f;
    for (int i = tid; i < 4608; i += NT) {
        int pos = i >> 7; int c = i & 127;
        float v  = dsmf[sidx[pos] * 129 + c];
        float zv = zt[i];
        valh[(size_t)b * 4608 + i] = __float2bfloat16(v);
        float d = v - zv;
        lsum += d * d;
    }
    lsum = warp_sum(lsum);
    if ((tid & 31) == 0) atomicAdd(&g_dict_sum, (double)lsum);
}

// ---------------- mu (1x1 conv) fused with reconstruction loss (NHWC bf16) ---
__global__ void __launch_bounds__(256)
mu_loss(const __nv_bfloat16* __restrict__ f4, const float* __restrict__ x,
        const float* __restrict__ mw, const float* __restrict__ mb)
{
    __shared__ float mws[128];
    const int b = blockIdx.x, tid = threadIdx.x;
    if (tid < 128) mws[tid] = mw[tid];
    __syncthreads();
    float lsum = 0.f;
    for (int px = tid; px < 784; px += NT) {
        const uint4* fp = (const uint4*)(f4 + ((size_t)b * 784 + px) * 128);
        float s = mb[0];
        #pragma unroll
        for (int j = 0; j < 16; j++) {
            uint4 v = fp[j];
            const __nv_bfloat16* h = (const __nv_bfloat16*)&v;
            #pragma unroll
            for (int t = 0; t < 8; t++)
                s += __bfloat162float(h[t]) * mws[j * 8 + t];
        }
        float d = s - x[(size_t)b * 784 + px];
        lsum += d * d;
    }
    lsum = warp_sum(lsum);
    if ((tid & 31) == 0) atomicAdd(&g_rec_sum, (double)lsum);
}

__global__ void finalize_kernel(float* loss_out)
{
    if (loss_out) {
        double dict_mse = g_dict_sum / 1179648.0;
        loss_out[0] = (float)(g_rec_sum / 200704.0);
        loss_out[1] = (float)(dict_mse * 5.0);
        loss_out[2] = (float)(dict_mse * 1.25);
        loss_out[3] = 0.f;
    }
}

// ---------------- host side ----------------------------------------------------
extern "C" void kernel_launch(void* const* d_in, const int* in_sizes, int n_in,
                              void* d_out, int out_size)
{
    const float* x    = (const float*)d_in[0];
    const float* w1   = (const float*)d_in[1];
    const float* b1   = (const float*)d_in[2];
    const float* w2   = (const float*)d_in[3];
    const float* b2   = (const float*)d_in[4];
    const float* w3   = (const float*)d_in[5];
    const float* b3   = (const float*)d_in[6];
    const float* t1w  = (const float*)d_in[7];
    const float* t1b  = (const float*)d_in[8];
    const float* t2w  = (const float*)d_in[9];
    const float* t2b  = (const float*)d_in[10];
    const float* t3w  = (const float*)d_in[11];
    const float* t3b  = (const float*)d_in[12];
    const float* t4w  = (const float*)d_in[13];
    const float* t4b  = (const float*)d_in[14];
    const float* mw   = (const float*)d_in[15];
    const float* mb   = (const float*)d_in[16];
    const float* dictw= (const float*)d_in[17];

    float* outp = (float*)d_out;
    float* loss_ptr = outp;
    float* idx_ptr  = outp + 4;
    if (out_size < 9220) { loss_ptr = nullptr; idx_ptr = outp; }

    __half *c1hi, *c1lo, *p1hi, *p1lo, *w2hi, *w2lo, *w3hi, *w3lo;
    float *c2f, *c3f, *zn, *f1;
    __nv_bfloat16 *valh, *f2h, *f3h, *f4h, *wp1, *wp3, *wp4;
    cudaGetSymbolAddress((void**)&c1hi, g_c1hi);
    cudaGetSymbolAddress((void**)&c1lo, g_c1lo);
    cudaGetSymbolAddress((void**)&c2f,  g_c2f);
    cudaGetSymbolAddress((void**)&p1hi, g_p1hi);
    cudaGetSymbolAddress((void**)&p1lo, g_p1lo);
    cudaGetSymbolAddress((void**)&c3f,  g_c3f);
    cudaGetSymbolAddress((void**)&zn,   g_zn);
    cudaGetSymbolAddress((void**)&valh, g_valh);
    cudaGetSymbolAddress((void**)&f1,   g_f1);
    cudaGetSymbolAddress((void**)&f2h,  g_f2h);
    cudaGetSymbolAddress((void**)&f3h,  g_f3h);
    cudaGetSymbolAddress((void**)&f4h,  g_f4h);
    cudaGetSymbolAddress((void**)&wp1,  g_wp1);
    cudaGetSymbolAddress((void**)&wp3,  g_wp3);
    cudaGetSymbolAddress((void**)&wp4,  g_wp4);
    cudaGetSymbolAddress((void**)&w2hi, g_w2hi);
    cudaGetSymbolAddress((void**)&w2lo, g_w2lo);
    cudaGetSymbolAddress((void**)&w3hi, g_w3hi);
    cudaGetSymbolAddress((void**)&w3lo, g_w3lo);

    static bool attr_set = false;
    if (!attr_set) {
        cudaFuncSetAttribute(vq_kernel, cudaFuncAttributeMaxDynamicSharedMemorySize,
                             128 * 129 * (int)sizeof(float));
        cudaFuncSetAttribute(tc_eng1, cudaFuncAttributeMaxDynamicSharedMemorySize,
                             4 * TILE);
        cudaFuncSetAttribute(tc_enc3, cudaFuncAttributeMaxDynamicSharedMemorySize,
                             6 * TILE);
        attr_set = true;
    }

    init_kernel<<<1, 1>>>();

    // weight prepacks
    prepack_w<<<16, 256>>>(t1w, wp1, 4);
    prepack_w<<<25, 256>>>(t3w, wp3, 5);
    prepack_w<<<25, 256>>>(t4w, wp4, 5);
    prepack_fwd_split<<<25, 256>>>(w2, w2hi, w2lo);
    prepack_fwd_split<<<25, 256>>>(w3, w3hi, w3lo);

    // encoder: conv1 fp32 exact, conv2/conv3 fused fp16-split tensor path
    conv1_split<<<dim3(BB, 576), 128>>>(x, w1, b1, c1hi, c1lo);
    tc_enc3<<<dim3(5, BB), 256, 6 * TILE>>>(
        (const uint16_t*)c1hi, (const uint16_t*)c1lo,
        (const uint16_t*)w2hi, (const uint16_t*)w2lo,
        b2, c2f, 24, 24, 24, 24, 2, 1);
    mp_split_nhwc<<<4096, 256>>>(c2f, p1hi, p1lo, 24, 24);
    tc_enc3<<<dim3(2, BB), 256, 6 * TILE>>>(
        (const uint16_t*)p1hi, (const uint16_t*)p1lo,
        (const uint16_t*)w3hi, (const uint16_t*)w3lo,
        b3, c3f, 12, 12, 12, 12, 2, 0);
    mp_nhwc<<<2048, 256>>>(c3f, zn, 12, 12);

    // VQ (emits val as NHWC bf16)
    vq_kernel<<<BB, NT, 128 * 129 * sizeof(float)>>>(zn, dictw, valh, idx_ptr);

    // decoder: t1 tensor engine (K=4) -> NCHW fp32; t2 fp32 SIMT; t3/t4 bf16 tc
    tc_eng1<<<dim3(1, BB), 256, 4 * TILE>>>(
        (const uint16_t*)valh, (const uint16_t*)wp1, t1b, f1,
        6, 6, 9, 9, 3, 1, 4, 2);
    deconv_s2_k4<<<dim3(BB, 4, 2), NT>>>(f1, t2w, t2b, f2h);
    tc_eng1<<<dim3(5, BB), 256, 4 * TILE>>>(
        (const uint16_t*)f2h, (const uint16_t*)wp3, t3b, f3h,
        20, 20, 24, 24, 4, 1, 5, 0);
    tc_eng1<<<dim3(7, BB), 256, 4 * TILE>>>(
        (const uint16_t*)f3h, (const uint16_t*)wp4, t4b, f4h,
        24, 24, 28, 28, 4, 1, 5, 0);

    // mu + losses
    mu_loss<<<BB, NT>>>(f4h, x, mw, mb);
    finalize_kernel<<<1, 1>>>(loss_ptr);
}

// round 7
// speedup vs baseline: 5.0231x; 1.3751x over previous
#include <cuda_runtime.h>
#include <cuda_bf16.h>
#include <cuda_fp16.h>
#include <cstdint>

#define BB 256
#define NT 256
#define TILE 34816

// ---------------- scratch (device globals; no allocation APIs) ---------------
__device__ __half g_c1hi[(size_t)BB*576*128];       // conv1 out hi, NHWC fp16
__device__ __half g_c1lo[(size_t)BB*576*128];       // conv1 out lo
__device__ float  g_c2f [(size_t)BB*576*128];       // conv2 out, NHWC fp32
__device__ __half g_p1hi[(size_t)BB*144*128];       // pool1 hi, NHWC fp16
__device__ __half g_p1lo[(size_t)BB*144*128];
__device__ float  g_c3f [(size_t)BB*144*128];       // conv3 out, NHWC fp32
__device__ float  g_zn  [(size_t)BB*36*128];        // z, NHWC fp32
__device__ __nv_bfloat16 g_valh[(size_t)BB*36*128]; // codes, NHWC bf16
__device__ __nv_bfloat16 g_f1h[(size_t)BB*81*128];  // t1 out, NHWC bf16
__device__ __nv_bfloat16 g_f2h[(size_t)BB*400*128]; // t2 out, NHWC bf16
__device__ __nv_bfloat16 g_f3h[(size_t)BB*576*128]; // t3 out, NHWC bf16
__device__ __nv_bfloat16 g_f4h[(size_t)BB*784*128]; // t4 out, NHWC bf16
// packed weights: per tap, [co][ci] row-major, pitch 136 elems (272B)
__device__ __nv_bfloat16 g_wp1[16*128*136];
__device__ __nv_bfloat16 g_wpt2[16*128*136];        // [parity][tap] 4x4
__device__ __nv_bfloat16 g_wp3[25*128*136];
__device__ __nv_bfloat16 g_wp4[25*128*136];
__device__ __half g_w2hi[25*128*136];
__device__ __half g_w2lo[25*128*136];
__device__ __half g_w3hi[25*128*136];
__device__ __half g_w3lo[25*128*136];
__device__ double g_rec_sum;
__device__ double g_dict_sum;

__global__ void init_kernel() { g_rec_sum = 0.0; g_dict_sum = 0.0; }

__inline__ __device__ float warp_sum(float v) {
    #pragma unroll
    for (int o = 16; o; o >>= 1) v += __shfl_xor_sync(0xffffffffu, v, o);
    return v;
}

// ---------------- mma / cp.async helpers --------------------------------------
__device__ __forceinline__ uint32_t smem_u32(const void* p) {
    uint32_t a;
    asm("{ .reg .u64 t; cvta.to.shared.u64 t, %1; cvt.u32.u64 %0, t; }"
        : "=r"(a) : "l"(p));
    return a;
}

#define LDSM_X4(r0, r1, r2, r3, addr)                                          \
    asm volatile("ldmatrix.sync.aligned.m8n8.x4.shared.b16 {%0,%1,%2,%3}, [%4];" \
                 : "=r"(r0), "=r"(r1), "=r"(r2), "=r"(r3) : "r"(addr))

#define MMA_BF16(c, a0, a1, a2, a3, b0, b1)                                    \
    asm volatile("mma.sync.aligned.m16n8k16.row.col.f32.bf16.bf16.f32 "        \
                 "{%0,%1,%2,%3}, {%4,%5,%6,%7}, {%8,%9}, {%0,%1,%2,%3};"       \
                 : "+f"((c)[0]), "+f"((c)[1]), "+f"((c)[2]), "+f"((c)[3])      \
                 : "r"(a0), "r"(a1), "r"(a2), "r"(a3), "r"(b0), "r"(b1))

#define MMA_F16(c, a0, a1, a2, a3, b0, b1)                                     \
    asm volatile("mma.sync.aligned.m16n8k16.row.col.f32.f16.f16.f32 "          \
                 "{%0,%1,%2,%3}, {%4,%5,%6,%7}, {%8,%9}, {%0,%1,%2,%3};"       \
                 : "+f"((c)[0]), "+f"((c)[1]), "+f"((c)[2]), "+f"((c)[3])      \
                 : "r"(a0), "r"(a1), "r"(a2), "r"(a3), "r"(b0), "r"(b1))

#define CP16(d, s, n)                                                          \
    asm volatile("cp.async.cg.shared.global [%0], [%1], 16, %2;"               \
                 :: "r"(d), "l"(s), "r"(n))
#define CP_COMMIT() asm volatile("cp.async.commit_group;" ::: "memory")
#define CP_WAIT0()  asm volatile("cp.async.wait_group 0;" ::: "memory")
#define CP_WAIT1()  asm volatile("cp.async.wait_group 1;" ::: "memory")

// warp tile constants: warp = 32 pixels x 64 couts
// pxg = wid>>1 (4 groups of 32 px), cog = wid&1 (2 groups of 64 co)

// ---------------- weight prepack (bf16, deconv flip/transpose, runtime K) -----
__global__ void prepack_w(const float* __restrict__ W, __nv_bfloat16* __restrict__ dst,
                          int K)
{
    int tap = blockIdx.x;
    int ky = tap / K, kx = tap - ky * K;
    __nv_bfloat16* base = dst + (size_t)tap * 128 * 136;
    for (int i = threadIdx.x; i < 16384; i += blockDim.x) {
        int co = i >> 7, ci = i & 127;
        float v = W[(((size_t)ci * 128 + co) * K + (K - 1 - ky)) * K + (K - 1 - kx)];
        base[co * 136 + ci] = __float2bfloat16(v);
    }
}

// ---------------- weight prepack for stride-2 deconv parity decomposition -----
// blockIdx.x = parity*4 + tap; parity=(py,px), tap=(ti,tj); ky=py+2ti, kx=px+2tj
__global__ void prepack_t2(const float* __restrict__ W, __nv_bfloat16* __restrict__ dst)
{
    int par = blockIdx.x >> 2, tap = blockIdx.x & 3;
    int py = par >> 1, px = par & 1;
    int ti = tap >> 1, tj = tap & 1;
    int ky = py + 2 * ti, kx = px + 2 * tj;
    __nv_bfloat16* base = dst + (size_t)blockIdx.x * 128 * 136;
    for (int i = threadIdx.x; i < 16384; i += blockDim.x) {
        int co = i >> 7, ci = i & 127;
        float v = W[(((size_t)ci * 128 + co) * 4 + ky) * 4 + kx];
        base[co * 136 + ci] = __float2bfloat16(v);
    }
}

// ---------------- weight prepack (fp16 hi/lo split, forward conv k=5) ---------
__global__ void prepack_fwd_split(const float* __restrict__ W,
                                  __half* __restrict__ dh, __half* __restrict__ dl)
{
    int tap = blockIdx.x;
    int ky = tap / 5, kx = tap - ky * 5;
    size_t tb = (size_t)tap * 128 * 136;
    for (int i = threadIdx.x; i < 16384; i += blockDim.x) {
        int co = i >> 7, ci = i & 127;
        float v = W[(((size_t)co * 128 + ci) * 5 + ky) * 5 + kx];
        __half h = __float2half_rn(v);
        dh[tb + co * 136 + ci] = h;
        dl[tb + co * 136 + ci] = __float2half_rn(v - __half2float(h));
    }
}

// ================= fused 3-pass fp16-split encoder conv (K=5) =================
__global__ void __launch_bounds__(256)
tc_enc3(const uint16_t* __restrict__ inHi, const uint16_t* __restrict__ inLo,
        const uint16_t* __restrict__ wHi,  const uint16_t* __restrict__ wLo,
        const float* __restrict__ bias, float* __restrict__ outp,
        int Hin, int Win, int Hout, int Wout, int pad, int relu)
{
    extern __shared__ char dsm[];
    __shared__ float sbias[128];
    const int tid  = threadIdx.x;
    const int wid  = tid >> 5;
    const int lane = tid & 31;
    const int b    = blockIdx.y;
    const int Npix = Hout * Wout;
    const int pbase = blockIdx.x * 128;

    const uint32_t smAhi = smem_u32(dsm);
    const uint32_t smBhi = smAhi + 2 * TILE;
    const uint32_t smAlo = smAhi + 4 * TILE;
    const uint32_t smBlo = smAhi + 5 * TILE;
    if (tid < 128) sbias[tid] = bias[tid];

    const int arow = tid >> 1, ahalf = tid & 1;
    const int ap = pbase + arow;
    const bool apv = (ap < Npix);
    const int apy = apv ? ap / Wout : 0;
    const int apx = apv ? ap - apy * Wout : 0;
    const uint32_t aoff = arow * 272 + ahalf * 128;

    const int pxg = wid >> 1, cog = wid & 1;
    float acc[2][8][4];
    #pragma unroll
    for (int m = 0; m < 2; m++)
        #pragma unroll
        for (int n = 0; n < 8; n++)
            #pragma unroll
            for (int j = 0; j < 4; j++) acc[m][n][j] = 0.f;

    const uint32_t a_rd0 = (pxg * 32 + (lane & 15)) * 272 + ((lane >> 4) << 4);
    const uint32_t a_rd1 = a_rd0 + 16 * 272;
    const uint32_t b_rdb = (cog * 64 + ((lane >> 4) << 3) + (lane & 7)) * 272
                         + (((lane >> 3) & 1) << 4);

    auto stage_pair = [&](const uint16_t* abuf, const uint16_t* wbuf, int tap,
                          uint32_t adst, uint32_t bdst) {
        const int ky = tap / 5, kx = tap - ky * 5;
        const char* wb = (const char*)(wbuf + (size_t)tap * 128 * 136);
        #pragma unroll
        for (int j = 0; j < 8; ++j)
            CP16(bdst + (j * 256 + tid) * 16, wb + (size_t)(j * 256 + tid) * 16, 16);
        if (tid < 128)
            CP16(bdst + (2048 + tid) * 16, wb + (size_t)(2048 + tid) * 16, 16);
        const int iy = apy + ky - pad, ix = apx + kx - pad;
        const bool inb = apv && (unsigned)iy < (unsigned)Hin && (unsigned)ix < (unsigned)Win;
        const char* as = inb ? (const char*)(abuf + ((size_t)(b * Hin + iy) * Win + ix) * 128
                                             + ahalf * 64)
                             : (const char*)abuf;
        const int sz = inb ? 16 : 0;
        const uint32_t ad = adst + aoff;
        #pragma unroll
        for (int j = 0; j < 8; ++j)
            CP16(ad + j * 16, as + (size_t)j * 16, sz);
    };

    auto mma_pass = [&](uint32_t abase, uint32_t bbase) {
        #pragma unroll
        for (int ks = 0; ks < 8; ++ks) {
            uint32_t a0[4], a1[4];
            LDSM_X4(a0[0], a0[1], a0[2], a0[3], abase + a_rd0 + ks * 32);
            LDSM_X4(a1[0], a1[1], a1[2], a1[3], abase + a_rd1 + ks * 32);
            #pragma unroll
            for (int nb = 0; nb < 4; ++nb) {
                uint32_t r0, r1, r2, r3;
                LDSM_X4(r0, r1, r2, r3, bbase + b_rdb + nb * 16 * 272 + ks * 32);
                MMA_F16(acc[0][2 * nb],     a0[0], a0[1], a0[2], a0[3], r0, r1);
                MMA_F16(acc[0][2 * nb + 1], a0[0], a0[1], a0[2], a0[3], r2, r3);
                MMA_F16(acc[1][2 * nb],     a1[0], a1[1], a1[2], a1[3], r0, r1);
                MMA_F16(acc[1][2 * nb + 1], a1[0], a1[1], a1[2], a1[3], r2, r3);
            }
        }
    };

    stage_pair(inHi, wHi, 0, smAhi, smBhi);
    CP_COMMIT();

    for (int tap = 0; tap < 25; ++tap) {
        const int buf = tap & 1;
        CP_WAIT0();
        __syncthreads();
        stage_pair(inLo, wLo, tap, smAlo, smBlo);
        CP_COMMIT();
        if (tap < 24) {
            stage_pair(inHi, wHi, tap + 1, smAhi + (buf ^ 1) * TILE,
                       smBhi + (buf ^ 1) * TILE);
            CP_COMMIT();
        }
        mma_pass(smAhi + buf * TILE, smBhi + buf * TILE);
        if (tap < 24) CP_WAIT1(); else CP_WAIT0();
        __syncthreads();
        mma_pass(smAlo, smBhi + buf * TILE);
        mma_pass(smAhi + buf * TILE, smBlo);
    }

    #pragma unroll
    for (int mb = 0; mb < 2; ++mb) {
        const int row0 = pbase + pxg * 32 + mb * 16 + (lane >> 2);
        const int row1 = row0 + 8;
        const bool v0 = (row0 < Npix), v1 = (row1 < Npix);
        #pragma unroll
        for (int nt = 0; nt < 8; ++nt) {
            const int co = cog * 64 + nt * 8 + 2 * (lane & 3);
            const float bz0 = sbias[co], bz1 = sbias[co + 1];
            float p00 = acc[mb][nt][0] + bz0, p01 = acc[mb][nt][1] + bz1;
            float p10 = acc[mb][nt][2] + bz0, p11 = acc[mb][nt][3] + bz1;
            if (relu) {
                p00 = fmaxf(p00, 0.f); p01 = fmaxf(p01, 0.f);
                p10 = fmaxf(p10, 0.f); p11 = fmaxf(p11, 0.f);
            }
            if (v0) *(float2*)(outp + ((size_t)b * Npix + row0) * 128 + co) = make_float2(p00, p01);
            if (v1) *(float2*)(outp + ((size_t)b * Npix + row1) * 128 + co) = make_float2(p10, p11);
        }
    }
}

// ================= 1-pass bf16 pipelined conv engine (runtime K) ===============
__global__ void __launch_bounds__(256)
tc_eng1(const uint16_t* __restrict__ in, const uint16_t* __restrict__ wpack,
        const float* __restrict__ bias, __nv_bfloat16* __restrict__ outp,
        int Hin, int Win, int Hout, int Wout, int pad, int K)
{
    extern __shared__ char dsm[];
    __shared__ float sbias[128];
    const int tid  = threadIdx.x;
    const int wid  = tid >> 5;
    const int lane = tid & 31;
    const int b    = blockIdx.y;
    const int Npix = Hout * Wout;
    const int pbase = blockIdx.x * 128;

    const uint32_t smA = smem_u32(dsm);
    const uint32_t smB = smA + 2 * TILE;
    if (tid < 128) sbias[tid] = bias[tid];

    const int arow = tid >> 1, ahalf = tid & 1;
    const int ap = pbase + arow;
    const bool apv = (ap < Npix);
    const int apy = apv ? ap / Wout : 0;
    const int apx = apv ? ap - apy * Wout : 0;
    const uint32_t adst0 = smA + arow * 272 + ahalf * 128;

    const int pxg = wid >> 1, cog = wid & 1;
    float acc[2][8][4];
    #pragma unroll
    for (int m = 0; m < 2; m++)
        #pragma unroll
        for (int n = 0; n < 8; n++)
            #pragma unroll
            for (int j = 0; j < 4; j++) acc[m][n][j] = 0.f;

    const uint32_t a_rd0 = smA + (pxg * 32 + (lane & 15)) * 272 + ((lane >> 4) << 4);
    const uint32_t a_rd1 = a_rd0 + 16 * 272;
    const uint32_t b_rdb = (cog * 64 + ((lane >> 4) << 3) + (lane & 7)) * 272
                         + (((lane >> 3) & 1) << 4);
    const int NIT = K * K;

    auto stage = [&](int tap) {
        const int buf = tap & 1;
        const int ky = tap / K, kx = tap - ky * K;
        const char* wb = (const char*)(wpack + (size_t)tap * 128 * 136);
        const uint32_t bd = smB + buf * TILE;
        #pragma unroll
        for (int j = 0; j < 8; ++j)
            CP16(bd + (j * 256 + tid) * 16, wb + (size_t)(j * 256 + tid) * 16, 16);
        if (tid < 128)
            CP16(bd + (2048 + tid) * 16, wb + (size_t)(2048 + tid) * 16, 16);
        const int iy = apy + ky - pad, ix = apx + kx - pad;
        const bool inb = apv && (unsigned)iy < (unsigned)Hin && (unsigned)ix < (unsigned)Win;
        const char* as = inb ? (const char*)(in + ((size_t)(b * Hin + iy) * Win + ix) * 128
                                             + ahalf * 64)
                             : (const char*)in;
        const uint32_t ad = adst0 + buf * TILE;
        const int sz = inb ? 16 : 0;
        #pragma unroll
        for (int j = 0; j < 8; ++j)
            CP16(ad + j * 16, as + (size_t)j * 16, sz);
        CP_COMMIT();
    };

    stage(0);
    for (int it = 0; it < NIT; ++it) {
        CP_WAIT0();
        __syncthreads();
        if (it + 1 < NIT) stage(it + 1);
        const uint32_t abase = (it & 1) * TILE;
        const uint32_t bbase = smB + (it & 1) * TILE;
        #pragma unroll
        for (int ks = 0; ks < 8; ++ks) {
            uint32_t a0[4], a1[4];
            LDSM_X4(a0[0], a0[1], a0[2], a0[3], a_rd0 + abase + ks * 32);
            LDSM_X4(a1[0], a1[1], a1[2], a1[3], a_rd1 + abase + ks * 32);
            #pragma unroll
            for (int nb = 0; nb < 4; ++nb) {
                uint32_t r0, r1, r2, r3;
                LDSM_X4(r0, r1, r2, r3, bbase + b_rdb + nb * 16 * 272 + ks * 32);
                MMA_BF16(acc[0][2 * nb],     a0[0], a0[1], a0[2], a0[3], r0, r1);
                MMA_BF16(acc[0][2 * nb + 1], a0[0], a0[1], a0[2], a0[3], r2, r3);
                MMA_BF16(acc[1][2 * nb],     a1[0], a1[1], a1[2], a1[3], r0, r1);
                MMA_BF16(acc[1][2 * nb + 1], a1[0], a1[1], a1[2], a1[3], r2, r3);
            }
        }
        __syncthreads();
    }

    #pragma unroll
    for (int mb = 0; mb < 2; ++mb) {
        const int row0 = pbase + pxg * 32 + mb * 16 + (lane >> 2);
        const int row1 = row0 + 8;
        const bool v0 = (row0 < Npix), v1 = (row1 < Npix);
        #pragma unroll
        for (int nt = 0; nt < 8; ++nt) {
            const int co = cog * 64 + nt * 8 + 2 * (lane & 3);
            const float bz0 = sbias[co], bz1 = sbias[co + 1];
            float p00 = fmaxf(acc[mb][nt][0] + bz0, 0.f);
            float p01 = fmaxf(acc[mb][nt][1] + bz1, 0.f);
            float p10 = fmaxf(acc[mb][nt][2] + bz0, 0.f);
            float p11 = fmaxf(acc[mb][nt][3] + bz1, 0.f);
            if (v0) {
                __nv_bfloat162 h = __floats2bfloat162_rn(p00, p01);
                *(uint32_t*)(outp + ((size_t)b * Npix + row0) * 128 + co) =
                    *reinterpret_cast<uint32_t*>(&h);
            }
            if (v1) {
                __nv_bfloat162 h = __floats2bfloat162_rn(p10, p11);
                *(uint32_t*)(outp + ((size_t)b * Npix + row1) * 128 + co) =
                    *reinterpret_cast<uint32_t*>(&h);
            }
        }
    }
}

// ================= t2 stride-2 deconv via parity decomposition ================
// grid (1, BB, 4): z = parity (py,px). 100 out px per parity, 4 taps of 2x2.
// in: t1 out NHWC bf16 (9x9). out: NHWC bf16 (20x20) at (2y+py, 2x+px).
__global__ void __launch_bounds__(256)
tc_t2(const uint16_t* __restrict__ in, const uint16_t* __restrict__ wpack,
      const float* __restrict__ bias, __nv_bfloat16* __restrict__ outp)
{
    extern __shared__ char dsm[];
    __shared__ float sbias[128];
    const int tid  = threadIdx.x;
    const int wid  = tid >> 5;
    const int lane = tid & 31;
    const int b    = blockIdx.y;
    const int par  = blockIdx.z;
    const int py   = par >> 1, px = par & 1;

    const uint32_t smA = smem_u32(dsm);
    const uint32_t smB = smA + 2 * TILE;
    if (tid < 128) sbias[tid] = bias[tid];

    const int arow = tid >> 1, ahalf = tid & 1;
    const bool apv = (arow < 100);
    const int apy = apv ? arow / 10 : 0;
    const int apx = apv ? arow - apy * 10 : 0;
    const uint32_t adst0 = smA + arow * 272 + ahalf * 128;

    const int pxg = wid >> 1, cog = wid & 1;
    float acc[2][8][4];
    #pragma unroll
    for (int m = 0; m < 2; m++)
        #pragma unroll
        for (int n = 0; n < 8; n++)
            #pragma unroll
            for (int j = 0; j < 4; j++) acc[m][n][j] = 0.f;

    const uint32_t a_rd0 = smA + (pxg * 32 + (lane & 15)) * 272 + ((lane >> 4) << 4);
    const uint32_t a_rd1 = a_rd0 + 16 * 272;
    const uint32_t b_rdb = (cog * 64 + ((lane >> 4) << 3) + (lane & 7)) * 272
                         + (((lane >> 3) & 1) << 4);

    auto stage = [&](int tap) {
        const int buf = tap & 1;
        const int ti = tap >> 1, tj = tap & 1;
        const char* wb = (const char*)(wpack + (size_t)(par * 4 + tap) * 128 * 136);
        const uint32_t bd = smB + buf * TILE;
        #pragma unroll
        for (int j = 0; j < 8; ++j)
            CP16(bd + (j * 256 + tid) * 16, wb + (size_t)(j * 256 + tid) * 16, 16);
        if (tid < 128)
            CP16(bd + (2048 + tid) * 16, wb + (size_t)(2048 + tid) * 16, 16);
        const int iy = apy - ti, ix = apx - tj;
        const bool inb = apv && (unsigned)iy < 9u && (unsigned)ix < 9u;
        const char* as = inb ? (const char*)(in + ((size_t)(b * 9 + iy) * 9 + ix) * 128
                                             + ahalf * 64)
                             : (const char*)in;
        const uint32_t ad = adst0 + buf * TILE;
        const int sz = inb ? 16 : 0;
        #pragma unroll
        for (int j = 0; j < 8; ++j)
            CP16(ad + j * 16, as + (size_t)j * 16, sz);
        CP_COMMIT();
    };

    stage(0);
    for (int it = 0; it < 4; ++it) {
        CP_WAIT0();
        __syncthreads();
        if (it + 1 < 4) stage(it + 1);
        const uint32_t abase = (it & 1) * TILE;
        const uint32_t bbase = smB + (it & 1) * TILE;
        #pragma unroll
        for (int ks = 0; ks < 8; ++ks) {
            uint32_t a0[4], a1[4];
            LDSM_X4(a0[0], a0[1], a0[2], a0[3], a_rd0 + abase + ks * 32);
            LDSM_X4(a1[0], a1[1], a1[2], a1[3], a_rd1 + abase + ks * 32);
            #pragma unroll
            for (int nb = 0; nb < 4; ++nb) {
                uint32_t r0, r1, r2, r3;
                LDSM_X4(r0, r1, r2, r3, bbase + b_rdb + nb * 16 * 272 + ks * 32);
                MMA_BF16(acc[0][2 * nb],     a0[0], a0[1], a0[2], a0[3], r0, r1);
                MMA_BF16(acc[0][2 * nb + 1], a0[0], a0[1], a0[2], a0[3], r2, r3);
                MMA_BF16(acc[1][2 * nb],     a1[0], a1[1], a1[2], a1[3], r0, r1);
                MMA_BF16(acc[1][2 * nb + 1], a1[0], a1[1], a1[2], a1[3], r2, r3);
            }
        }
        __syncthreads();
    }

    #pragma unroll
    for (int mb = 0; mb < 2; ++mb) {
        const int r0i = pxg * 32 + mb * 16 + (lane >> 2);
        const int r1i = r0i + 8;
        #pragma unroll
        for (int nt = 0; nt < 8; ++nt) {
            const int co = cog * 64 + nt * 8 + 2 * (lane & 3);
            const float bz0 = sbias[co], bz1 = sbias[co + 1];
            float p00 = fmaxf(acc[mb][nt][0] + bz0, 0.f);
            float p01 = fmaxf(acc[mb][nt][1] + bz1, 0.f);
            float p10 = fmaxf(acc[mb][nt][2] + bz0, 0.f);
            float p11 = fmaxf(acc[mb][nt][3] + bz1, 0.f);
            if (r0i < 100) {
                int y = r0i / 10, x = r0i - y * 10;
                int op = (2 * y + py) * 20 + 2 * x + px;
                __nv_bfloat162 h = __floats2bfloat162_rn(p00, p01);
                *(uint32_t*)(outp + ((size_t)b * 400 + op) * 128 + co) =
                    *reinterpret_cast<uint32_t*>(&h);
            }
            if (r1i < 100) {
                int y = r1i / 10, x = r1i - y * 10;
                int op = (2 * y + py) * 20 + 2 * x + px;
                __nv_bfloat162 h = __floats2bfloat162_rn(p10, p11);
                *(uint32_t*)(outp + ((size_t)b * 400 + op) * 128 + co) =
                    *reinterpret_cast<uint32_t*>(&h);
            }
        }
    }
}

// ---------------- conv1 (Cin=1) fused with fp16 hi/lo split, NHWC -------------
__global__ void __launch_bounds__(128)
conv1_split(const float* __restrict__ x, const float* __restrict__ w1,
            const float* __restrict__ b1, __half* __restrict__ hi,
            __half* __restrict__ lo)
{
    const int b = blockIdx.x, p = blockIdx.y, co = threadIdx.x;
    const int oy = p / 24, ox = p - oy * 24;
    __shared__ float xs[25];
    if (co < 25) {
        int ky = co / 5, kx = co - (co / 5) * 5;
        xs[co] = x[(size_t)b * 784 + (oy + ky) * 28 + ox + kx];
    }
    __syncthreads();
    const float* w = w1 + co * 25;
    float v = b1[co];
    #pragma unroll
    for (int t = 0; t < 25; ++t) v += w[t] * xs[t];
    v = fmaxf(v, 0.f);
    __half h = __float2half_rn(v);
    size_t o = ((size_t)b * 576 + p) * 128 + co;
    hi[o] = h;
    lo[o] = __float2half_rn(v - __half2float(h));
}

// ---------------- NHWC maxpool 2x2: fp32 -> fp16 hi/lo -----------------------
__global__ void mp_split_nhwc(const float* __restrict__ in, __half* __restrict__ hi,
                              __half* __restrict__ lo, int Hin, int Win)
{
    const int Ho = Hin >> 1, Wo = Win >> 1;
    const size_t total = (size_t)BB * Ho * Wo * 128;
    for (size_t i = (size_t)blockIdx.x * blockDim.x + threadIdx.x; i < total;
         i += (size_t)gridDim.x * blockDim.x) {
        int c = (int)(i & 127);
        size_t r = i >> 7;
        int wo = (int)(r % Wo); r /= Wo;
        int ho = (int)(r % Ho); int b = (int)(r / Ho);
        const float* p = in + (((size_t)b * Hin + 2 * ho) * Win + 2 * wo) * 128 + c;
        float v = fmaxf(fmaxf(p[0], p[128]),
                        fmaxf(p[(size_t)Win * 128], p[(size_t)(Win + 1) * 128]));
        __half h = __float2half_rn(v);
        hi[i] = h;
        lo[i] = __float2half_rn(v - __half2float(h));
    }
}

// ---------------- NHWC maxpool 2x2: fp32 -> fp32 -----------------------------
__global__ void mp_nhwc(const float* __restrict__ in, float* __restrict__ out,
                        int Hin, int Win)
{
    const int Ho = Hin >> 1, Wo = Win >> 1;
    const size_t total = (size_t)BB * Ho * Wo * 128;
    for (size_t i = (size_t)blockIdx.x * blockDim.x + threadIdx.x; i < total;
         i += (size_t)gridDim.x * blockDim.x) {
        int c = (int)(i & 127);
        size_t r = i >> 7;
        int wo = (int)(r % Wo); r /= Wo;
        int ho = (int)(r % Ho); int b = (int)(r / Ho);
        const float* p = in + (((size_t)b * Hin + 2 * ho) * Win + 2 * wo) * 128 + c;
        out[i] = fmaxf(fmaxf(p[0], p[128]),
                       fmaxf(p[(size_t)Win * 128], p[(size_t)(Win + 1) * 128]));
    }
}

// ---------------- VQ: argmax(d2), gather val (NHWC bf16), dict MSE ------------
__global__ void __launch_bounds__(256)
vq_kernel(const float* __restrict__ z, const float* __restrict__ dict,
          __nv_bfloat16* __restrict__ valh, float* __restrict__ idx_out)
{
    extern __shared__ float dsmf[];
    __shared__ float zt[36 * 128];
    __shared__ float wn[128];
    __shared__ int   sidx[36];

    const int b = blockIdx.x, tid = threadIdx.x;

    for (int i = tid; i < 128 * 128; i += NT) {
        int k = i >> 7; int c = i & 127;
        dsmf[k * 129 + c] = dict[i];
    }
    for (int i = tid; i < 36 * 128; i += NT)
        zt[i] = z[(size_t)b * 4608 + i];
    __syncthreads();
    if (tid < 128) {
        float s = 0.f;
        const float* dp = dsmf + tid * 129;
        for (int c = 0; c < 128; c++) s += dp[c] * dp[c];
        wn[tid] = s;
    }
    __syncthreads();

    const int lane = tid & 31, wid = tid >> 5;
    for (int pos = wid; pos < 36; pos += 8) {
        float d0 = 0.f, d1 = 0.f, d2s = 0.f, d3 = 0.f, zn = 0.f;
        const float* zp = zt + pos * 128;
        const float* p0 = dsmf + (lane      ) * 129;
        const float* p1 = dsmf + (lane + 32 ) * 129;
        const float* p2 = dsmf + (lane + 64 ) * 129;
        const float* p3 = dsmf + (lane + 96 ) * 129;
        for (int c = 0; c < 128; c++) {
            float zv = zp[c];
            zn += zv * zv;
            d0 += p0[c] * zv; d1 += p1[c] * zv;
            d2s += p2[c] * zv; d3 += p3[c] * zv;
        }
        float bv = zn + wn[lane] - 2.f * d0; int bk = lane;
        float v1 = zn + wn[lane + 32] - 2.f * d1; if (v1 > bv) { bv = v1; bk = lane + 32; }
        float v2 = zn + wn[lane + 64] - 2.f * d2s; if (v2 > bv) { bv = v2; bk = lane + 64; }
        float v3 = zn + wn[lane + 96] - 2.f * d3; if (v3 > bv) { bv = v3; bk = lane + 96; }
        #pragma unroll
        for (int o = 16; o; o >>= 1) {
            float ov = __shfl_xor_sync(0xffffffffu, bv, o);
            int   ok = __shfl_xor_sync(0xffffffffu, bk, o);
            if (ov > bv || (ov == bv && ok < bk)) { bv = ov; bk = ok; }
        }
        if (lane == 0) {
            sidx[pos] = bk;
            if (idx_out) idx_out[b * 36 + pos] = (float)bk;
        }
    }
    __syncthreads();

    float lsum = 0.f;
    for (int i = tid; i < 4608; i += NT) {
        int pos = i >> 7; int c = i & 127;
        float v  = dsmf[sidx[pos] * 129 + c];
        float zv = zt[i];
        valh[(size_t)b * 4608 + i] = __float2bfloat16(v);
        float d = v - zv;
        lsum += d * d;
    }
    lsum = warp_sum(lsum);
    if ((tid & 31) == 0) atomicAdd(&g_dict_sum, (double)lsum);
}

// ---------------- mu (1x1 conv) fused with reconstruction loss (NHWC bf16) ---
__global__ void __launch_bounds__(256)
mu_loss(const __nv_bfloat16* __restrict__ f4, const float* __restrict__ x,
        const float* __restrict__ mw, const float* __restrict__ mb)
{
    __shared__ float mws[128];
    const int b = blockIdx.x, tid = threadIdx.x;
    if (tid < 128) mws[tid] = mw[tid];
    __syncthreads();
    float lsum = 0.f;
    for (int px = tid; px < 784; px += NT) {
        const uint4* fp = (const uint4*)(f4 + ((size_t)b * 784 + px) * 128);
        float s = mb[0];
        #pragma unroll
        for (int j = 0; j < 16; j++) {
            uint4 v = fp[j];
            const __nv_bfloat16* h = (const __nv_bfloat16*)&v;
            #pragma unroll
            for (int t = 0; t < 8; t++)
                s += __bfloat162float(h[t]) * mws[j * 8 + t];
        }
        float d = s - x[(size_t)b * 784 + px];
        lsum += d * d;
    }
    lsum = warp_sum(lsum);
    if ((tid & 31) == 0) atomicAdd(&g_rec_sum, (double)lsum);
}

__global__ void finalize_kernel(float* loss_out)
{
    if (loss_out) {
        double dict_mse = g_dict_sum / 1179648.0;
        loss_out[0] = (float)(g_rec_sum / 200704.0);
        loss_out[1] = (float)(dict_mse * 5.0);
        loss_out[2] = (float)(dict_mse * 1.25);
        loss_out[3] = 0.f;
    }
}

// ---------------- host side ----------------------------------------------------
extern "C" void kernel_launch(void* const* d_in, const int* in_sizes, int n_in,
                              void* d_out, int out_size)
{
    const float* x    = (const float*)d_in[0];
    const float* w1   = (const float*)d_in[1];
    const float* b1   = (const float*)d_in[2];
    const float* w2   = (const float*)d_in[3];
    const float* b2   = (const float*)d_in[4];
    const float* w3   = (const float*)d_in[5];
    const float* b3   = (const float*)d_in[6];
    const float* t1w  = (const float*)d_in[7];
    const float* t1b  = (const float*)d_in[8];
    const float* t2w  = (const float*)d_in[9];
    const float* t2b  = (const float*)d_in[10];
    const float* t3w  = (const float*)d_in[11];
    const float* t3b  = (const float*)d_in[12];
    const float* t4w  = (const float*)d_in[13];
    const float* t4b  = (const float*)d_in[14];
    const float* mw   = (const float*)d_in[15];
    const float* mb   = (const float*)d_in[16];
    const float* dictw= (const float*)d_in[17];

    float* outp = (float*)d_out;
    float* loss_ptr = outp;
    float* idx_ptr  = outp + 4;
    if (out_size < 9220) { loss_ptr = nullptr; idx_ptr = outp; }

    __half *c1hi, *c1lo, *p1hi, *p1lo, *w2hi, *w2lo, *w3hi, *w3lo;
    float *c2f, *c3f, *zn;
    __nv_bfloat16 *valh, *f1h, *f2h, *f3h, *f4h, *wp1, *wpt2, *wp3, *wp4;
    cudaGetSymbolAddress((void**)&c1hi, g_c1hi);
    cudaGetSymbolAddress((void**)&c1lo, g_c1lo);
    cudaGetSymbolAddress((void**)&c2f,  g_c2f);
    cudaGetSymbolAddress((void**)&p1hi, g_p1hi);
    cudaGetSymbolAddress((void**)&p1lo, g_p1lo);
    cudaGetSymbolAddress((void**)&c3f,  g_c3f);
    cudaGetSymbolAddress((void**)&zn,   g_zn);
    cudaGetSymbolAddress((void**)&valh, g_valh);
    cudaGetSymbolAddress((void**)&f1h,  g_f1h);
    cudaGetSymbolAddress((void**)&f2h,  g_f2h);
    cudaGetSymbolAddress((void**)&f3h,  g_f3h);
    cudaGetSymbolAddress((void**)&f4h,  g_f4h);
    cudaGetSymbolAddress((void**)&wp1,  g_wp1);
    cudaGetSymbolAddress((void**)&wpt2, g_wpt2);
    cudaGetSymbolAddress((void**)&wp3,  g_wp3);
    cudaGetSymbolAddress((void**)&wp4,  g_wp4);
    cudaGetSymbolAddress((void**)&w2hi, g_w2hi);
    cudaGetSymbolAddress((void**)&w2lo, g_w2lo);
    cudaGetSymbolAddress((void**)&w3hi, g_w3hi);
    cudaGetSymbolAddress((void**)&w3lo, g_w3lo);

    static bool attr_set = false;
    if (!attr_set) {
        cudaFuncSetAttribute(vq_kernel, cudaFuncAttributeMaxDynamicSharedMemorySize,
                             128 * 129 * (int)sizeof(float));
        cudaFuncSetAttribute(tc_eng1, cudaFuncAttributeMaxDynamicSharedMemorySize,
                             4 * TILE);
        cudaFuncSetAttribute(tc_t2, cudaFuncAttributeMaxDynamicSharedMemorySize,
                             4 * TILE);
        cudaFuncSetAttribute(tc_enc3, cudaFuncAttributeMaxDynamicSharedMemorySize,
                             6 * TILE);
        attr_set = true;
    }

    // launch order chosen so ncu (-s 5 -c 1) captures tc_enc3 conv2 (index 5)
    init_kernel<<<1, 1>>>();                                    // 0
    prepack_fwd_split<<<25, 256>>>(w2, w2hi, w2lo);             // 1
    conv1_split<<<dim3(BB, 576), 128>>>(x, w1, b1, c1hi, c1lo); // 2
    prepack_fwd_split<<<25, 256>>>(w3, w3hi, w3lo);             // 3
    prepack_w<<<16, 256>>>(t1w, wp1, 4);                        // 4
    tc_enc3<<<dim3(5, BB), 256, 6 * TILE>>>(                    // 5 <- profiled
        (const uint16_t*)c1hi, (const uint16_t*)c1lo,
        (const uint16_t*)w2hi, (const uint16_t*)w2lo,
        b2, c2f, 24, 24, 24, 24, 2, 1);
    mp_split_nhwc<<<4096, 256>>>(c2f, p1hi, p1lo, 24, 24);
    tc_enc3<<<dim3(2, BB), 256, 6 * TILE>>>(
        (const uint16_t*)p1hi, (const uint16_t*)p1lo,
        (const uint16_t*)w3hi, (const uint16_t*)w3lo,
        b3, c3f, 12, 12, 12, 12, 2, 0);
    mp_nhwc<<<2048, 256>>>(c3f, zn, 12, 12);
    prepack_t2<<<16, 256>>>(t2w, wpt2);
    prepack_w<<<25, 256>>>(t3w, wp3, 5);
    prepack_w<<<25, 256>>>(t4w, wp4, 5);

    vq_kernel<<<BB, NT, 128 * 129 * sizeof(float)>>>(zn, dictw, valh, idx_ptr);

    tc_eng1<<<dim3(1, BB), 256, 4 * TILE>>>(
        (const uint16_t*)valh, (const uint16_t*)wp1, t1b, f1h, 6, 6, 9, 9, 3, 4);
    tc_t2<<<dim3(1, BB, 4), 256, 4 * TILE>>>(
        (const uint16_t*)f1h, (const uint16_t*)wpt2, t2b, f2h);
    tc_eng1<<<dim3(5, BB), 256, 4 * TILE>>>(
        (const uint16_t*)f2h, (const uint16_t*)wp3, t3b, f3h, 20, 20, 24, 24, 4, 5);
    tc_eng1<<<dim3(7, BB), 256, 4 * TILE>>>(
        (const uint16_t*)f3h, (const uint16_t*)wp4, t4b, f4h, 24, 24, 28, 28, 4, 5);

    mu_loss<<<BB, NT>>>(f4h, x, mw, mb);
    finalize_kernel<<<1, 1>>>(loss_ptr);
}

// round 8
// speedup vs baseline: 5.8261x; 1.1599x over previous
#include <cuda_runtime.h>
#include <cuda_bf16.h>
#include <cuda_fp16.h>
#include <cstdint>

#define BB 256
#define NT 256
#define TILE 34816          // 128 rows x 272B
#define TILEA 69632         // 256 rows x 272B

// ---------------- scratch (device globals; no allocation APIs) ---------------
__device__ __half g_c1hi[(size_t)BB*576*128];
__device__ __half g_c1lo[(size_t)BB*576*128];
__device__ float  g_c2f [(size_t)BB*576*128];
__device__ __half g_p1hi[(size_t)BB*144*128];
__device__ __half g_p1lo[(size_t)BB*144*128];
__device__ float  g_c3f [(size_t)BB*144*128];
__device__ float  g_zn  [(size_t)BB*36*128];
__device__ __nv_bfloat16 g_valh[(size_t)BB*36*128];
__device__ __nv_bfloat16 g_f1h[(size_t)BB*81*128];
__device__ __nv_bfloat16 g_f2h[(size_t)BB*400*128];
__device__ __nv_bfloat16 g_f3h[(size_t)BB*576*128];
__device__ __nv_bfloat16 g_f4h[(size_t)BB*784*128];
__device__ __nv_bfloat16 g_wp1[16*128*136];
__device__ __nv_bfloat16 g_wpt2[16*128*136];
__device__ __nv_bfloat16 g_wp3[25*128*136];
__device__ __nv_bfloat16 g_wp4[25*128*136];
__device__ __half g_w2hi[25*128*136];
__device__ __half g_w2lo[25*128*136];
__device__ __half g_w3hi[25*128*136];
__device__ __half g_w3lo[25*128*136];
__device__ double g_rec_sum;
__device__ double g_dict_sum;

__global__ void init_kernel() { g_rec_sum = 0.0; g_dict_sum = 0.0; }

__inline__ __device__ float warp_sum(float v) {
    #pragma unroll
    for (int o = 16; o; o >>= 1) v += __shfl_xor_sync(0xffffffffu, v, o);
    return v;
}

// ---------------- mma / cp.async helpers --------------------------------------
__device__ __forceinline__ uint32_t smem_u32(const void* p) {
    uint32_t a;
    asm("{ .reg .u64 t; cvta.to.shared.u64 t, %1; cvt.u32.u64 %0, t; }"
        : "=r"(a) : "l"(p));
    return a;
}

#define LDSM_X4(r0, r1, r2, r3, addr)                                          \
    asm volatile("ldmatrix.sync.aligned.m8n8.x4.shared.b16 {%0,%1,%2,%3}, [%4];" \
                 : "=r"(r0), "=r"(r1), "=r"(r2), "=r"(r3) : "r"(addr))

#define MMA_BF16(c, a0, a1, a2, a3, b0, b1)                                    \
    asm volatile("mma.sync.aligned.m16n8k16.row.col.f32.bf16.bf16.f32 "        \
                 "{%0,%1,%2,%3}, {%4,%5,%6,%7}, {%8,%9}, {%0,%1,%2,%3};"       \
                 : "+f"((c)[0]), "+f"((c)[1]), "+f"((c)[2]), "+f"((c)[3])      \
                 : "r"(a0), "r"(a1), "r"(a2), "r"(a3), "r"(b0), "r"(b1))

#define MMA_F16(c, a0, a1, a2, a3, b0, b1)                                     \
    asm volatile("mma.sync.aligned.m16n8k16.row.col.f32.f16.f16.f32 "          \
                 "{%0,%1,%2,%3}, {%4,%5,%6,%7}, {%8,%9}, {%0,%1,%2,%3};"       \
                 : "+f"((c)[0]), "+f"((c)[1]), "+f"((c)[2]), "+f"((c)[3])      \
                 : "r"(a0), "r"(a1), "r"(a2), "r"(a3), "r"(b0), "r"(b1))

#define CP16(d, s, n)                                                          \
    asm volatile("cp.async.cg.shared.global [%0], [%1], 16, %2;"               \
                 :: "r"(d), "l"(s), "r"(n))
#define CP_COMMIT() asm volatile("cp.async.commit_group;" ::: "memory")
#define CP_WAIT0()  asm volatile("cp.async.wait_group 0;" ::: "memory")
#define CP_WAIT1()  asm volatile("cp.async.wait_group 1;" ::: "memory")

// ---------------- weight prepacks ---------------------------------------------
__global__ void prepack_w(const float* __restrict__ W, __nv_bfloat16* __restrict__ dst,
                          int K)
{
    int tap = blockIdx.x;
    int ky = tap / K, kx = tap - ky * K;
    __nv_bfloat16* base = dst + (size_t)tap * 128 * 136;
    for (int i = threadIdx.x; i < 16384; i += blockDim.x) {
        int co = i >> 7, ci = i & 127;
        float v = W[(((size_t)ci * 128 + co) * K + (K - 1 - ky)) * K + (K - 1 - kx)];
        base[co * 136 + ci] = __float2bfloat16(v);
    }
}

__global__ void prepack_t2(const float* __restrict__ W, __nv_bfloat16* __restrict__ dst)
{
    int par = blockIdx.x >> 2, tap = blockIdx.x & 3;
    int py = par >> 1, px = par & 1;
    int ti = tap >> 1, tj = tap & 1;
    int ky = py + 2 * ti, kx = px + 2 * tj;
    __nv_bfloat16* base = dst + (size_t)blockIdx.x * 128 * 136;
    for (int i = threadIdx.x; i < 16384; i += blockDim.x) {
        int co = i >> 7, ci = i & 127;
        float v = W[(((size_t)ci * 128 + co) * 4 + ky) * 4 + kx];
        base[co * 136 + ci] = __float2bfloat16(v);
    }
}

__global__ void prepack_fwd_split(const float* __restrict__ W,
                                  __half* __restrict__ dh, __half* __restrict__ dl)
{
    int tap = blockIdx.x;
    int ky = tap / 5, kx = tap - ky * 5;
    size_t tb = (size_t)tap * 128 * 136;
    for (int i = threadIdx.x; i < 16384; i += blockDim.x) {
        int co = i >> 7, ci = i & 127;
        float v = W[(((size_t)co * 128 + ci) * 5 + ky) * 5 + kx];
        __half h = __float2half_rn(v);
        dh[tb + co * 136 + ci] = h;
        dl[tb + co * 136 + ci] = __float2half_rn(v - __half2float(h));
    }
}

// ================= fused 3-pass fp16-split encoder conv (K=5, M=128) ==========
// flattened (batch,pixel) tiling: grid.x tiles of 128 rows over BB*Npix
__global__ void __launch_bounds__(256)
tc_enc3(const uint16_t* __restrict__ inHi, const uint16_t* __restrict__ inLo,
        const uint16_t* __restrict__ wHi,  const uint16_t* __restrict__ wLo,
        const float* __restrict__ bias, float* __restrict__ outp,
        int Hin, int Win, int Hout, int Wout, int pad, int relu)
{
    extern __shared__ char dsm[];
    __shared__ float sbias[128];
    const int tid  = threadIdx.x;
    const int wid  = tid >> 5;
    const int lane = tid & 31;
    const int Npix = Hout * Wout;
    const int totalPx = BB * Npix;
    const int pbase = blockIdx.x * 128;

    const uint32_t smAhi = smem_u32(dsm);
    const uint32_t smBhi = smAhi + 2 * TILE;
    const uint32_t smAlo = smAhi + 4 * TILE;
    const uint32_t smBlo = smAhi + 5 * TILE;
    if (tid < 128) sbias[tid] = bias[tid];

    const int arow = tid >> 1, ahalf = tid & 1;
    const int ap = pbase + arow;
    const bool apv = (ap < totalPx);
    const int bA  = apv ? ap / Npix : 0;
    const int apn = apv ? ap - bA * Npix : 0;
    const int apy = apn / Wout;
    const int apx = apn - apy * Wout;
    const uint32_t aoff = arow * 272 + ahalf * 128;

    const int pxg = wid >> 1, cog = wid & 1;
    float acc[2][8][4];
    #pragma unroll
    for (int m = 0; m < 2; m++)
        #pragma unroll
        for (int n = 0; n < 8; n++)
            #pragma unroll
            for (int j = 0; j < 4; j++) acc[m][n][j] = 0.f;

    const uint32_t a_rd0 = (pxg * 32 + (lane & 15)) * 272 + ((lane >> 4) << 4);
    const uint32_t a_rd1 = a_rd0 + 16 * 272;
    const uint32_t b_rdb = (cog * 64 + ((lane >> 4) << 3) + (lane & 7)) * 272
                         + (((lane >> 3) & 1) << 4);

    auto stage_pair = [&](const uint16_t* abuf, const uint16_t* wbuf, int tap,
                          uint32_t adst, uint32_t bdst) {
        const int ky = tap / 5, kx = tap - ky * 5;
        const char* wb = (const char*)(wbuf + (size_t)tap * 128 * 136);
        #pragma unroll
        for (int j = 0; j < 8; ++j)
            CP16(bdst + (j * 256 + tid) * 16, wb + (size_t)(j * 256 + tid) * 16, 16);
        if (tid < 128)
            CP16(bdst + (2048 + tid) * 16, wb + (size_t)(2048 + tid) * 16, 16);
        const int iy = apy + ky - pad, ix = apx + kx - pad;
        const bool inb = apv && (unsigned)iy < (unsigned)Hin && (unsigned)ix < (unsigned)Win;
        const char* as = inb ? (const char*)(abuf + ((size_t)(bA * Hin + iy) * Win + ix) * 128
                                             + ahalf * 64)
                             : (const char*)abuf;
        const int sz = inb ? 16 : 0;
        const uint32_t ad = adst + aoff;
        #pragma unroll
        for (int j = 0; j < 8; ++j)
            CP16(ad + j * 16, as + (size_t)j * 16, sz);
    };

    auto mma_pass = [&](uint32_t abase, uint32_t bbase) {
        #pragma unroll
        for (int ks = 0; ks < 8; ++ks) {
            uint32_t a0[4], a1[4];
            LDSM_X4(a0[0], a0[1], a0[2], a0[3], abase + a_rd0 + ks * 32);
            LDSM_X4(a1[0], a1[1], a1[2], a1[3], abase + a_rd1 + ks * 32);
            #pragma unroll
            for (int nb = 0; nb < 4; ++nb) {
                uint32_t r0, r1, r2, r3;
                LDSM_X4(r0, r1, r2, r3, bbase + b_rdb + nb * 16 * 272 + ks * 32);
                MMA_F16(acc[0][2 * nb],     a0[0], a0[1], a0[2], a0[3], r0, r1);
                MMA_F16(acc[0][2 * nb + 1], a0[0], a0[1], a0[2], a0[3], r2, r3);
                MMA_F16(acc[1][2 * nb],     a1[0], a1[1], a1[2], a1[3], r0, r1);
                MMA_F16(acc[1][2 * nb + 1], a1[0], a1[1], a1[2], a1[3], r2, r3);
            }
        }
    };

    stage_pair(inHi, wHi, 0, smAhi, smBhi);
    CP_COMMIT();

    for (int tap = 0; tap < 25; ++tap) {
        const int buf = tap & 1;
        CP_WAIT0();
        __syncthreads();
        stage_pair(inLo, wLo, tap, smAlo, smBlo);
        CP_COMMIT();
        if (tap < 24) {
            stage_pair(inHi, wHi, tap + 1, smAhi + (buf ^ 1) * TILE,
                       smBhi + (buf ^ 1) * TILE);
            CP_COMMIT();
        }
        mma_pass(smAhi + buf * TILE, smBhi + buf * TILE);
        if (tap < 24) CP_WAIT1(); else CP_WAIT0();
        __syncthreads();
        mma_pass(smAlo, smBhi + buf * TILE);
        mma_pass(smAhi + buf * TILE, smBlo);
    }

    // epilogue: flattened NHWC => address = rowGlobal*128 + co
    #pragma unroll
    for (int mb = 0; mb < 2; ++mb) {
        const int row0 = pbase + pxg * 32 + mb * 16 + (lane >> 2);
        const int row1 = row0 + 8;
        const bool v0 = (row0 < totalPx), v1 = (row1 < totalPx);
        #pragma unroll
        for (int nt = 0; nt < 8; ++nt) {
            const int co = cog * 64 + nt * 8 + 2 * (lane & 3);
            const float bz0 = sbias[co], bz1 = sbias[co + 1];
            float p00 = acc[mb][nt][0] + bz0, p01 = acc[mb][nt][1] + bz1;
            float p10 = acc[mb][nt][2] + bz0, p11 = acc[mb][nt][3] + bz1;
            if (relu) {
                p00 = fmaxf(p00, 0.f); p01 = fmaxf(p01, 0.f);
                p10 = fmaxf(p10, 0.f); p11 = fmaxf(p11, 0.f);
            }
            if (v0) *(float2*)(outp + (size_t)row0 * 128 + co) = make_float2(p00, p01);
            if (v1) *(float2*)(outp + (size_t)row1 * 128 + co) = make_float2(p10, p11);
        }
    }
}

// ================= 1-pass bf16 engine, M=256, flattened tiling ================
// warp tile: 64 px x 64 co. SMEM: A[2]=2*TILEA + B[2]=2*TILE = 208896 B.
__global__ void __launch_bounds__(256, 1)
tc_eng1(const uint16_t* __restrict__ in, const uint16_t* __restrict__ wpack,
        const float* __restrict__ bias, __nv_bfloat16* __restrict__ outp,
        int Hin, int Win, int Hout, int Wout, int pad, int K)
{
    extern __shared__ char dsm[];
    __shared__ float sbias[128];
    const int tid  = threadIdx.x;
    const int wid  = tid >> 5;
    const int lane = tid & 31;
    const int Npix = Hout * Wout;
    const int totalPx = BB * Npix;
    const int pbase = blockIdx.x * 256;

    const uint32_t smA = smem_u32(dsm);              // 2 * TILEA
    const uint32_t smB = smA + 2 * TILEA;            // 2 * TILE
    if (tid < 128) sbias[tid] = bias[tid];

    // A staging: 1 thread per row (256B = 16 x CP16)
    const int ap = pbase + tid;
    const bool apv = (ap < totalPx);
    const int bA  = apv ? ap / Npix : 0;
    const int apn = apv ? ap - bA * Npix : 0;
    const int apy = apn / Wout;
    const int apx = apn - apy * Wout;
    const uint32_t adst0 = smA + tid * 272;

    const int pxg = wid >> 1, cog = wid & 1;
    float acc[4][8][4];
    #pragma unroll
    for (int m = 0; m < 4; m++)
        #pragma unroll
        for (int n = 0; n < 8; n++)
            #pragma unroll
            for (int j = 0; j < 4; j++) acc[m][n][j] = 0.f;

    const uint32_t a_rd0 = smA + (pxg * 64 + (lane & 15)) * 272 + ((lane >> 4) << 4);
    const uint32_t b_rdb = (cog * 64 + ((lane >> 4) << 3) + (lane & 7)) * 272
                         + (((lane >> 3) & 1) << 4);
    const int NIT = K * K;

    auto stage = [&](int tap) {
        const int buf = tap & 1;
        const int ky = tap / K, kx = tap - ky * K;
        const char* wb = (const char*)(wpack + (size_t)tap * 128 * 136);
        const uint32_t bd = smB + buf * TILE;
        #pragma unroll
        for (int j = 0; j < 8; ++j)
            CP16(bd + (j * 256 + tid) * 16, wb + (size_t)(j * 256 + tid) * 16, 16);
        if (tid < 128)
            CP16(bd + (2048 + tid) * 16, wb + (size_t)(2048 + tid) * 16, 16);
        const int iy = apy + ky - pad, ix = apx + kx - pad;
        const bool inb = apv && (unsigned)iy < (unsigned)Hin && (unsigned)ix < (unsigned)Win;
        const char* as = inb ? (const char*)(in + ((size_t)(bA * Hin + iy) * Win + ix) * 128)
                             : (const char*)in;
        const uint32_t ad = adst0 + buf * TILEA;
        const int sz = inb ? 16 : 0;
        #pragma unroll
        for (int j = 0; j < 16; ++j)
            CP16(ad + j * 16, as + (size_t)j * 16, sz);
        CP_COMMIT();
    };

    stage(0);
    for (int it = 0; it < NIT; ++it) {
        CP_WAIT0();
        __syncthreads();
        if (it + 1 < NIT) stage(it + 1);
        const uint32_t abase = (it & 1) * TILEA;
        const uint32_t bbase = smB + (it & 1) * TILE;
        #pragma unroll
        for (int ks = 0; ks < 8; ++ks) {
            uint32_t a[4][4];
            #pragma unroll
            for (int i = 0; i < 4; ++i)
                LDSM_X4(a[i][0], a[i][1], a[i][2], a[i][3],
                        a_rd0 + abase + i * 16 * 272 + ks * 32);
            #pragma unroll
            for (int nb = 0; nb < 4; ++nb) {
                uint32_t r0, r1, r2, r3;
                LDSM_X4(r0, r1, r2, r3, bbase + b_rdb + nb * 16 * 272 + ks * 32);
                #pragma unroll
                for (int i = 0; i < 4; ++i) {
                    MMA_BF16(acc[i][2 * nb],     a[i][0], a[i][1], a[i][2], a[i][3], r0, r1);
                    MMA_BF16(acc[i][2 * nb + 1], a[i][0], a[i][1], a[i][2], a[i][3], r2, r3);
                }
            }
        }
        __syncthreads();
    }

    #pragma unroll
    for (int mb = 0; mb < 4; ++mb) {
        const int row0 = pbase + pxg * 64 + mb * 16 + (lane >> 2);
        const int row1 = row0 + 8;
        const bool v0 = (row0 < totalPx), v1 = (row1 < totalPx);
        #pragma unroll
        for (int nt = 0; nt < 8; ++nt) {
            const int co = cog * 64 + nt * 8 + 2 * (lane & 3);
            const float bz0 = sbias[co], bz1 = sbias[co + 1];
            float p00 = fmaxf(acc[mb][nt][0] + bz0, 0.f);
            float p01 = fmaxf(acc[mb][nt][1] + bz1, 0.f);
            float p10 = fmaxf(acc[mb][nt][2] + bz0, 0.f);
            float p11 = fmaxf(acc[mb][nt][3] + bz1, 0.f);
            if (v0) {
                __nv_bfloat162 h = __floats2bfloat162_rn(p00, p01);
                *(uint32_t*)(outp + (size_t)row0 * 128 + co) = *reinterpret_cast<uint32_t*>(&h);
            }
            if (v1) {
                __nv_bfloat162 h = __floats2bfloat162_rn(p10, p11);
                *(uint32_t*)(outp + (size_t)row1 * 128 + co) = *reinterpret_cast<uint32_t*>(&h);
            }
        }
    }
}

// ================= t2 stride-2 deconv, parity decomposition, M=256 ============
// grid (100, 1, 4): 25600 rows per parity, flattened (b, 100px).
__global__ void __launch_bounds__(256, 1)
tc_t2(const uint16_t* __restrict__ in, const uint16_t* __restrict__ wpack,
      const float* __restrict__ bias, __nv_bfloat16* __restrict__ outp)
{
    extern __shared__ char dsm[];
    __shared__ float sbias[128];
    const int tid  = threadIdx.x;
    const int wid  = tid >> 5;
    const int lane = tid & 31;
    const int par  = blockIdx.z;
    const int py   = par >> 1, px = par & 1;
    const int totalPx = BB * 100;
    const int pbase = blockIdx.x * 256;

    const uint32_t smA = smem_u32(dsm);
    const uint32_t smB = smA + 2 * TILEA;
    if (tid < 128) sbias[tid] = bias[tid];

    const int ap = pbase + tid;
    const bool apv = (ap < totalPx);
    const int bA  = apv ? ap / 100 : 0;
    const int apn = apv ? ap - bA * 100 : 0;
    const int apy = apn / 10;
    const int apx = apn - apy * 10;
    const uint32_t adst0 = smA + tid * 272;

    const int pxg = wid >> 1, cog = wid & 1;
    float acc[4][8][4];
    #pragma unroll
    for (int m = 0; m < 4; m++)
        #pragma unroll
        for (int n = 0; n < 8; n++)
            #pragma unroll
            for (int j = 0; j < 4; j++) acc[m][n][j] = 0.f;

    const uint32_t a_rd0 = smA + (pxg * 64 + (lane & 15)) * 272 + ((lane >> 4) << 4);
    const uint32_t b_rdb = (cog * 64 + ((lane >> 4) << 3) + (lane & 7)) * 272
                         + (((lane >> 3) & 1) << 4);

    auto stage = [&](int tap) {
        const int buf = tap & 1;
        const int ti = tap >> 1, tj = tap & 1;
        const char* wb = (const char*)(wpack + (size_t)(par * 4 + tap) * 128 * 136);
        const uint32_t bd = smB + buf * TILE;
        #pragma unroll
        for (int j = 0; j < 8; ++j)
            CP16(bd + (j * 256 + tid) * 16, wb + (size_t)(j * 256 + tid) * 16, 16);
        if (tid < 128)
            CP16(bd + (2048 + tid) * 16, wb + (size_t)(2048 + tid) * 16, 16);
        const int iy = apy - ti, ix = apx - tj;
        const bool inb = apv && (unsigned)iy < 9u && (unsigned)ix < 9u;
        const char* as = inb ? (const char*)(in + ((size_t)(bA * 9 + iy) * 9 + ix) * 128)
                             : (const char*)in;
        const uint32_t ad = adst0 + buf * TILEA;
        const int sz = inb ? 16 : 0;
        #pragma unroll
        for (int j = 0; j < 16; ++j)
            CP16(ad + j * 16, as + (size_t)j * 16, sz);
        CP_COMMIT();
    };

    stage(0);
    for (int it = 0; it < 4; ++it) {
        CP_WAIT0();
        __syncthreads();
        if (it + 1 < 4) stage(it + 1);
        const uint32_t abase = (it & 1) * TILEA;
        const uint32_t bbase = smB + (it & 1) * TILE;
        #pragma unroll
        for (int ks = 0; ks < 8; ++ks) {
            uint32_t a[4][4];
            #pragma unroll
            for (int i = 0; i < 4; ++i)
                LDSM_X4(a[i][0], a[i][1], a[i][2], a[i][3],
                        a_rd0 + abase + i * 16 * 272 + ks * 32);
            #pragma unroll
            for (int nb = 0; nb < 4; ++nb) {
                uint32_t r0, r1, r2, r3;
                LDSM_X4(r0, r1, r2, r3, bbase + b_rdb + nb * 16 * 272 + ks * 32);
                #pragma unroll
                for (int i = 0; i < 4; ++i) {
                    MMA_BF16(acc[i][2 * nb],     a[i][0], a[i][1], a[i][2], a[i][3], r0, r1);
                    MMA_BF16(acc[i][2 * nb + 1], a[i][0], a[i][1], a[i][2], a[i][3], r2, r3);
                }
            }
        }
        __syncthreads();
    }

    #pragma unroll
    for (int mb = 0; mb < 4; ++mb) {
        const int r0g = pbase + pxg * 64 + mb * 16 + (lane >> 2);
        const int r1g = r0g + 8;
        int b0 = r0g / 100, q0 = r0g - b0 * 100, y0 = q0 / 10, x0 = q0 - y0 * 10;
        int b1 = r1g / 100, q1 = r1g - b1 * 100, y1 = q1 / 10, x1 = q1 - y1 * 10;
        size_t o0 = ((size_t)b0 * 400 + (2 * y0 + py) * 20 + 2 * x0 + px) * 128;
        size_t o1 = ((size_t)b1 * 400 + (2 * y1 + py) * 20 + 2 * x1 + px) * 128;
        #pragma unroll
        for (int nt = 0; nt < 8; ++nt) {
            const int co = cog * 64 + nt * 8 + 2 * (lane & 3);
            const float bz0 = sbias[co], bz1 = sbias[co + 1];
            float p00 = fmaxf(acc[mb][nt][0] + bz0, 0.f);
            float p01 = fmaxf(acc[mb][nt][1] + bz1, 0.f);
            float p10 = fmaxf(acc[mb][nt][2] + bz0, 0.f);
            float p11 = fmaxf(acc[mb][nt][3] + bz1, 0.f);
            if (r0g < totalPx) {
                __nv_bfloat162 h = __floats2bfloat162_rn(p00, p01);
                *(uint32_t*)(outp + o0 + co) = *reinterpret_cast<uint32_t*>(&h);
            }
            if (r1g < totalPx) {
                __nv_bfloat162 h = __floats2bfloat162_rn(p10, p11);
                *(uint32_t*)(outp + o1 + co) = *reinterpret_cast<uint32_t*>(&h);
            }
        }
    }
}

// ---------------- conv1 (Cin=1) fused with fp16 hi/lo split, NHWC -------------
__global__ void __launch_bounds__(128)
conv1_split(const float* __restrict__ x, const float* __restrict__ w1,
            const float* __restrict__ b1, __half* __restrict__ hi,
            __half* __restrict__ lo)
{
    const int b = blockIdx.x, p = blockIdx.y, co = threadIdx.x;
    const int oy = p / 24, ox = p - oy * 24;
    __shared__ float xs[25];
    if (co < 25) {
        int ky = co / 5, kx = co - (co / 5) * 5;
        xs[co] = x[(size_t)b * 784 + (oy + ky) * 28 + ox + kx];
    }
    __syncthreads();
    const float* w = w1 + co * 25;
    float v = b1[co];
    #pragma unroll
    for (int t = 0; t < 25; ++t) v += w[t] * xs[t];
    v = fmaxf(v, 0.f);
    __half h = __float2half_rn(v);
    size_t o = ((size_t)b * 576 + p) * 128 + co;
    hi[o] = h;
    lo[o] = __float2half_rn(v - __half2float(h));
}

// ---------------- NHWC maxpool 2x2: fp32 -> fp16 hi/lo -----------------------
__global__ void mp_split_nhwc(const float* __restrict__ in, __half* __restrict__ hi,
                              __half* __restrict__ lo, int Hin, int Win)
{
    const int Ho = Hin >> 1, Wo = Win >> 1;
    const size_t total = (size_t)BB * Ho * Wo * 128;
    for (size_t i = (size_t)blockIdx.x * blockDim.x + threadIdx.x; i < total;
         i += (size_t)gridDim.x * blockDim.x) {
        int c = (int)(i & 127);
        size_t r = i >> 7;
        int wo = (int)(r % Wo); r /= Wo;
        int ho = (int)(r % Ho); int b = (int)(r / Ho);
        const float* p = in + (((size_t)b * Hin + 2 * ho) * Win + 2 * wo) * 128 + c;
        float v = fmaxf(fmaxf(p[0], p[128]),
                        fmaxf(p[(size_t)Win * 128], p[(size_t)(Win + 1) * 128]));
        __half h = __float2half_rn(v);
        hi[i] = h;
        lo[i] = __float2half_rn(v - __half2float(h));
    }
}

// ---------------- NHWC maxpool 2x2: fp32 -> fp32 -----------------------------
__global__ void mp_nhwc(const float* __restrict__ in, float* __restrict__ out,
                        int Hin, int Win)
{
    const int Ho = Hin >> 1, Wo = Win >> 1;
    const size_t total = (size_t)BB * Ho * Wo * 128;
    for (size_t i = (size_t)blockIdx.x * blockDim.x + threadIdx.x; i < total;
         i += (size_t)gridDim.x * blockDim.x) {
        int c = (int)(i & 127);
        size_t r = i >> 7;
        int wo = (int)(r % Wo); r /= Wo;
        int ho = (int)(r % Ho); int b = (int)(r / Ho);
        const float* p = in + (((size_t)b * Hin + 2 * ho) * Win + 2 * wo) * 128 + c;
        out[i] = fmaxf(fmaxf(p[0], p[128]),
                       fmaxf(p[(size_t)Win * 128], p[(size_t)(Win + 1) * 128]));
    }
}

// ---------------- VQ: argmax(d2), gather val (NHWC bf16), dict MSE ------------
__global__ void __launch_bounds__(256)
vq_kernel(const float* __restrict__ z, const float* __restrict__ dict,
          __nv_bfloat16* __restrict__ valh, float* __restrict__ idx_out)
{
    extern __shared__ float dsmf[];
    __shared__ float zt[36 * 128];
    __shared__ float wn[128];
    __shared__ int   sidx[36];

    const int b = blockIdx.x, tid = threadIdx.x;

    for (int i = tid; i < 128 * 128; i += NT) {
        int k = i >> 7; int c = i & 127;
        dsmf[k * 129 + c] = dict[i];
    }
    for (int i = tid; i < 36 * 128; i += NT)
        zt[i] = z[(size_t)b * 4608 + i];
    __syncthreads();
    if (tid < 128) {
        float s = 0.f;
        const float* dp = dsmf + tid * 129;
        for (int c = 0; c < 128; c++) s += dp[c] * dp[c];
        wn[tid] = s;
    }
    __syncthreads();

    const int lane = tid & 31, wid = tid >> 5;
    for (int pos = wid; pos < 36; pos += 8) {
        float d0 = 0.f, d1 = 0.f, d2s = 0.f, d3 = 0.f, zn = 0.f;
        const float* zp = zt + pos * 128;
        const float* p0 = dsmf + (lane      ) * 129;
        const float* p1 = dsmf + (lane + 32 ) * 129;
        const float* p2 = dsmf + (lane + 64 ) * 129;
        const float* p3 = dsmf + (lane + 96 ) * 129;
        for (int c = 0; c < 128; c++) {
            float zv = zp[c];
            zn += zv * zv;
            d0 += p0[c] * zv; d1 += p1[c] * zv;
            d2s += p2[c] * zv; d3 += p3[c] * zv;
        }
        float bv = zn + wn[lane] - 2.f * d0; int bk = lane;
        float v1 = zn + wn[lane + 32] - 2.f * d1; if (v1 > bv) { bv = v1; bk = lane + 32; }
        float v2 = zn + wn[lane + 64] - 2.f * d2s; if (v2 > bv) { bv = v2; bk = lane + 64; }
        float v3 = zn + wn[lane + 96] - 2.f * d3; if (v3 > bv) { bv = v3; bk = lane + 96; }
        #pragma unroll
        for (int o = 16; o; o >>= 1) {
            float ov = __shfl_xor_sync(0xffffffffu, bv, o);
            int   ok = __shfl_xor_sync(0xffffffffu, bk, o);
            if (ov > bv || (ov == bv && ok < bk)) { bv = ov; bk = ok; }
        }
        if (lane == 0) {
            sidx[pos] = bk;
            if (idx_out) idx_out[b * 36 + pos] = (float)bk;
        }
    }
    __syncthreads();

    float lsum = 0.f;
    for (int i = tid; i < 4608; i += NT) {
        int pos = i >> 7; int c = i & 127;
        float v  = dsmf[sidx[pos] * 129 + c];
        float zv = zt[i];
        valh[(size_t)b * 4608 + i] = __float2bfloat16(v);
        float d = v - zv;
        lsum += d * d;
    }
    lsum = warp_sum(lsum);
    if ((tid & 31) == 0) atomicAdd(&g_dict_sum, (double)lsum);
}

// ---------------- mu (1x1 conv) fused with reconstruction loss (NHWC bf16) ---
__global__ void __launch_bounds__(256)
mu_loss(const __nv_bfloat16* __restrict__ f4, const float* __restrict__ x,
        const float* __restrict__ mw, const float* __restrict__ mb)
{
    __shared__ float mws[128];
    const int b = blockIdx.x, tid = threadIdx.x;
    if (tid < 128) mws[tid] = mw[tid];
    __syncthreads();
    float lsum = 0.f;
    for (int px = tid; px < 784; px += NT) {
        const uint4* fp = (const uint4*)(f4 + ((size_t)b * 784 + px) * 128);
        float s = mb[0];
        #pragma unroll
        for (int j = 0; j < 16; j++) {
            uint4 v = fp[j];
            const __nv_bfloat16* h = (const __nv_bfloat16*)&v;
            #pragma unroll
            for (int t = 0; t < 8; t++)
                s += __bfloat162float(h[t]) * mws[j * 8 + t];
        }
        float d = s - x[(size_t)b * 784 + px];
        lsum += d * d;
    }
    lsum = warp_sum(lsum);
    if ((tid & 31) == 0) atomicAdd(&g_rec_sum, (double)lsum);
}

__global__ void finalize_kernel(float* loss_out)
{
    if (loss_out) {
        double dict_mse = g_dict_sum / 1179648.0;
        loss_out[0] = (float)(g_rec_sum / 200704.0);
        loss_out[1] = (float)(dict_mse * 5.0);
        loss_out[2] = (float)(dict_mse * 1.25);
        loss_out[3] = 0.f;
    }
}

// ---------------- host side ----------------------------------------------------
extern "C" void kernel_launch(void* const* d_in, const int* in_sizes, int n_in,
                              void* d_out, int out_size)
{
    const float* x    = (const float*)d_in[0];
    const float* w1   = (const float*)d_in[1];
    const float* b1   = (const float*)d_in[2];
    const float* w2   = (const float*)d_in[3];
    const float* b2   = (const float*)d_in[4];
    const float* w3   = (const float*)d_in[5];
    const float* b3   = (const float*)d_in[6];
    const float* t1w  = (const float*)d_in[7];
    const float* t1b  = (const float*)d_in[8];
    const float* t2w  = (const float*)d_in[9];
    const float* t2b  = (const float*)d_in[10];
    const float* t3w  = (const float*)d_in[11];
    const float* t3b  = (const float*)d_in[12];
    const float* t4w  = (const float*)d_in[13];
    const float* t4b  = (const float*)d_in[14];
    const float* mw   = (const float*)d_in[15];
    const float* mb   = (const float*)d_in[16];
    const float* dictw= (const float*)d_in[17];

    float* outp = (float*)d_out;
    float* loss_ptr = outp;
    float* idx_ptr  = outp + 4;
    if (out_size < 9220) { loss_ptr = nullptr; idx_ptr = outp; }

    __half *c1hi, *c1lo, *p1hi, *p1lo, *w2hi, *w2lo, *w3hi, *w3lo;
    float *c2f, *c3f, *zn;
    __nv_bfloat16 *valh, *f1h, *f2h, *f3h, *f4h, *wp1, *wpt2, *wp3, *wp4;
    cudaGetSymbolAddress((void**)&c1hi, g_c1hi);
    cudaGetSymbolAddress((void**)&c1lo, g_c1lo);
    cudaGetSymbolAddress((void**)&c2f,  g_c2f);
    cudaGetSymbolAddress((void**)&p1hi, g_p1hi);
    cudaGetSymbolAddress((void**)&p1lo, g_p1lo);
    cudaGetSymbolAddress((void**)&c3f,  g_c3f);
    cudaGetSymbolAddress((void**)&zn,   g_zn);
    cudaGetSymbolAddress((void**)&valh, g_valh);
    cudaGetSymbolAddress((void**)&f1h,  g_f1h);
    cudaGetSymbolAddress((void**)&f2h,  g_f2h);
    cudaGetSymbolAddress((void**)&f3h,  g_f3h);
    cudaGetSymbolAddress((void**)&f4h,  g_f4h);
    cudaGetSymbolAddress((void**)&wp1,  g_wp1);
    cudaGetSymbolAddress((void**)&wpt2, g_wpt2);
    cudaGetSymbolAddress((void**)&wp3,  g_wp3);
    cudaGetSymbolAddress((void**)&wp4,  g_wp4);
    cudaGetSymbolAddress((void**)&w2hi, g_w2hi);
    cudaGetSymbolAddress((void**)&w2lo, g_w2lo);
    cudaGetSymbolAddress((void**)&w3hi, g_w3hi);
    cudaGetSymbolAddress((void**)&w3lo, g_w3lo);

    static bool attr_set = false;
    if (!attr_set) {
        cudaFuncSetAttribute(vq_kernel, cudaFuncAttributeMaxDynamicSharedMemorySize,
                             128 * 129 * (int)sizeof(float));
        cudaFuncSetAttribute(tc_eng1, cudaFuncAttributeMaxDynamicSharedMemorySize,
                             2 * TILEA + 2 * TILE);
        cudaFuncSetAttribute(tc_t2, cudaFuncAttributeMaxDynamicSharedMemorySize,
                             2 * TILEA + 2 * TILE);
        cudaFuncSetAttribute(tc_enc3, cudaFuncAttributeMaxDynamicSharedMemorySize,
                             6 * TILE);
        attr_set = true;
    }

    init_kernel<<<1, 1>>>();                                    // 0
    prepack_fwd_split<<<25, 256>>>(w2, w2hi, w2lo);             // 1
    conv1_split<<<dim3(BB, 576), 128>>>(x, w1, b1, c1hi, c1lo); // 2
    prepack_fwd_split<<<25, 256>>>(w3, w3hi, w3lo);             // 3
    prepack_w<<<16, 256>>>(t1w, wp1, 4);                        // 4
    tc_enc3<<<1152, 256, 6 * TILE>>>(                           // 5
        (const uint16_t*)c1hi, (const uint16_t*)c1lo,
        (const uint16_t*)w2hi, (const uint16_t*)w2lo,
        b2, c2f, 24, 24, 24, 24, 2, 1);
    mp_split_nhwc<<<4096, 256>>>(c2f, p1hi, p1lo, 24, 24);
    tc_enc3<<<288, 256, 6 * TILE>>>(
        (const uint16_t*)p1hi, (const uint16_t*)p1lo,
        (const uint16_t*)w3hi, (const uint16_t*)w3lo,
        b3, c3f, 12, 12, 12, 12, 2, 0);
    mp_nhwc<<<2048, 256>>>(c3f, zn, 12, 12);
    prepack_t2<<<16, 256>>>(t2w, wpt2);
    prepack_w<<<25, 256>>>(t3w, wp3, 5);
    prepack_w<<<25, 256>>>(t4w, wp4, 5);

    vq_kernel<<<BB, NT, 128 * 129 * sizeof(float)>>>(zn, dictw, valh, idx_ptr);

    tc_eng1<<<81, 256, 2 * TILEA + 2 * TILE>>>(
        (const uint16_t*)valh, (const uint16_t*)wp1, t1b, f1h, 6, 6, 9, 9, 3, 4);
    tc_t2<<<dim3(100, 1, 4), 256, 2 * TILEA + 2 * TILE>>>(
        (const uint16_t*)f1h, (const uint16_t*)wpt2, t2b, f2h);
    tc_eng1<<<576, 256, 2 * TILEA + 2 * TILE>>>(
        (const uint16_t*)f2h, (const uint16_t*)wp3, t3b, f3h, 20, 20, 24, 24, 4, 5);
    tc_eng1<<<784, 256, 2 * TILEA + 2 * TILE>>>(
        (const uint16_t*)f3h, (const uint16_t*)wp4, t4b, f4h, 24, 24, 28, 28, 4, 5);

    mu_loss<<<BB, NT>>>(f4h, x, mw, mb);
    finalize_kernel<<<1, 1>>>(loss_ptr);
}

// round 9
// speedup vs baseline: 6.0255x; 1.0342x over previous
#include <cuda_runtime.h>
#include <cuda_bf16.h>
#include <cuda_fp16.h>
#include <cstdint>

#define BB 256
#define NT 256
#define TILE 34816          // 128 rows x 272B
#define TILEA 69632         // 256 rows x 272B

// ---------------- scratch (device globals; no allocation APIs) ---------------
__device__ __half g_c1hi[(size_t)BB*576*128];
__device__ __half g_c1lo[(size_t)BB*576*128];
__device__ float  g_c2f [(size_t)BB*576*128];
__device__ __half g_p1hi[(size_t)BB*144*128];
__device__ __half g_p1lo[(size_t)BB*144*128];
__device__ float  g_c3f [(size_t)BB*144*128];
__device__ float  g_zn  [(size_t)BB*36*128];
__device__ __nv_bfloat16 g_valh[(size_t)BB*36*128];
__device__ __nv_bfloat16 g_f1h[(size_t)BB*81*128];
__device__ __nv_bfloat16 g_f2h[(size_t)BB*400*128];
__device__ __nv_bfloat16 g_f3h[(size_t)BB*576*128];
__device__ __nv_bfloat16 g_f4h[(size_t)BB*784*128];
__device__ __nv_bfloat16 g_wp1[16*128*136];
__device__ __nv_bfloat16 g_wpt2[16*128*136];
__device__ __nv_bfloat16 g_wp3[25*128*136];
__device__ __nv_bfloat16 g_wp4[25*128*136];
__device__ __half g_w2hi[25*128*136];
__device__ __half g_w2lo[25*128*136];
__device__ __half g_w3hi[25*128*136];
__device__ __half g_w3lo[25*128*136];
__device__ double g_rec_sum;
__device__ double g_dict_sum;

__global__ void init_kernel() { g_rec_sum = 0.0; g_dict_sum = 0.0; }

__inline__ __device__ float warp_sum(float v) {
    #pragma unroll
    for (int o = 16; o; o >>= 1) v += __shfl_xor_sync(0xffffffffu, v, o);
    return v;
}

// ---------------- mma / cp.async helpers --------------------------------------
__device__ __forceinline__ uint32_t smem_u32(const void* p) {
    uint32_t a;
    asm("{ .reg .u64 t; cvta.to.shared.u64 t, %1; cvt.u32.u64 %0, t; }"
        : "=r"(a) : "l"(p));
    return a;
}

#define LDSM_X4(r0, r1, r2, r3, addr)                                          \
    asm volatile("ldmatrix.sync.aligned.m8n8.x4.shared.b16 {%0,%1,%2,%3}, [%4];" \
                 : "=r"(r0), "=r"(r1), "=r"(r2), "=r"(r3) : "r"(addr))

#define MMA_BF16(c, a0, a1, a2, a3, b0, b1)                                    \
    asm volatile("mma.sync.aligned.m16n8k16.row.col.f32.bf16.bf16.f32 "        \
                 "{%0,%1,%2,%3}, {%4,%5,%6,%7}, {%8,%9}, {%0,%1,%2,%3};"       \
                 : "+f"((c)[0]), "+f"((c)[1]), "+f"((c)[2]), "+f"((c)[3])      \
                 : "r"(a0), "r"(a1), "r"(a2), "r"(a3), "r"(b0), "r"(b1))

#define MMA_F16(c, a0, a1, a2, a3, b0, b1)                                     \
    asm volatile("mma.sync.aligned.m16n8k16.row.col.f32.f16.f16.f32 "          \
                 "{%0,%1,%2,%3}, {%4,%5,%6,%7}, {%8,%9}, {%0,%1,%2,%3};"       \
                 : "+f"((c)[0]), "+f"((c)[1]), "+f"((c)[2]), "+f"((c)[3])      \
                 : "r"(a0), "r"(a1), "r"(a2), "r"(a3), "r"(b0), "r"(b1))

#define CP16(d, s, n)                                                          \
    asm volatile("cp.async.cg.shared.global [%0], [%1], 16, %2;"               \
                 :: "r"(d), "l"(s), "r"(n))
#define CP_COMMIT() asm volatile("cp.async.commit_group;" ::: "memory")
#define CP_WAIT0()  asm volatile("cp.async.wait_group 0;" ::: "memory")
#define CP_WAIT1()  asm volatile("cp.async.wait_group 1;" ::: "memory")

// ---------------- weight prepacks ---------------------------------------------
__global__ void prepack_w(const float* __restrict__ W, __nv_bfloat16* __restrict__ dst,
                          int K)
{
    int tap = blockIdx.x;
    int ky = tap / K, kx = tap - ky * K;
    __nv_bfloat16* base = dst + (size_t)tap * 128 * 136;
    for (int i = threadIdx.x; i < 16384; i += blockDim.x) {
        int co = i >> 7, ci = i & 127;
        float v = W[(((size_t)ci * 128 + co) * K + (K - 1 - ky)) * K + (K - 1 - kx)];
        base[co * 136 + ci] = __float2bfloat16(v);
    }
}

__global__ void prepack_t2(const float* __restrict__ W, __nv_bfloat16* __restrict__ dst)
{
    int par = blockIdx.x >> 2, tap = blockIdx.x & 3;
    int py = par >> 1, px = par & 1;
    int ti = tap >> 1, tj = tap & 1;
    int ky = py + 2 * ti, kx = px + 2 * tj;
    __nv_bfloat16* base = dst + (size_t)blockIdx.x * 128 * 136;
    for (int i = threadIdx.x; i < 16384; i += blockDim.x) {
        int co = i >> 7, ci = i & 127;
        float v = W[(((size_t)ci * 128 + co) * 4 + ky) * 4 + kx];
        base[co * 136 + ci] = __float2bfloat16(v);
    }
}

__global__ void prepack_fwd_split(const float* __restrict__ W,
                                  __half* __restrict__ dh, __half* __restrict__ dl)
{
    int tap = blockIdx.x;
    int ky = tap / 5, kx = tap - ky * 5;
    size_t tb = (size_t)tap * 128 * 136;
    for (int i = threadIdx.x; i < 16384; i += blockDim.x) {
        int co = i >> 7, ci = i & 127;
        float v = W[(((size_t)co * 128 + ci) * 5 + ky) * 5 + kx];
        __half h = __float2half_rn(v);
        dh[tb + co * 136 + ci] = h;
        dl[tb + co * 136 + ci] = __float2half_rn(v - __half2float(h));
    }
}

// ====== fused 3-pass fp16-split encoder conv, M=256, pass-reordered ===========
// it = 0..49: phase = it/25 (0: A=hi, passes Whi+Wlo; 1: A=lo, pass Whi)
// SMEM: A[2]*TILEA + Bhi TILE + Blo TILE = 208896 B.
__global__ void __launch_bounds__(256, 1)
tc_enc3(const uint16_t* __restrict__ inHi, const uint16_t* __restrict__ inLo,
        const uint16_t* __restrict__ wHi,  const uint16_t* __restrict__ wLo,
        const float* __restrict__ bias, float* __restrict__ outp,
        int Hin, int Win, int Hout, int Wout, int pad, int relu)
{
    extern __shared__ char dsm[];
    __shared__ float sbias[128];
    const int tid  = threadIdx.x;
    const int wid  = tid >> 5;
    const int lane = tid & 31;
    const int Npix = Hout * Wout;
    const int totalPx = BB * Npix;
    const int pbase = blockIdx.x * 256;

    const uint32_t smA   = smem_u32(dsm);           // 2 * TILEA
    const uint32_t smBhi = smA + 2 * TILEA;         // TILE
    const uint32_t smBlo = smBhi + TILE;            // TILE
    if (tid < 128) sbias[tid] = bias[tid];

    const int ap = pbase + tid;
    const bool apv = (ap < totalPx);
    const int bA  = apv ? ap / Npix : 0;
    const int apn = apv ? ap - bA * Npix : 0;
    const int apy = apn / Wout;
    const int apx = apn - apy * Wout;
    const uint32_t adst0 = smA + tid * 272;

    const int pxg = wid >> 1, cog = wid & 1;
    float acc[4][8][4];
    #pragma unroll
    for (int m = 0; m < 4; m++)
        #pragma unroll
        for (int n = 0; n < 8; n++)
            #pragma unroll
            for (int j = 0; j < 4; j++) acc[m][n][j] = 0.f;

    const uint32_t a_rd0 = smA + (pxg * 64 + (lane & 15)) * 272 + ((lane >> 4) << 4);
    const uint32_t b_rdb = (cog * 64 + ((lane >> 4) << 3) + (lane & 7)) * 272
                         + (((lane >> 3) & 1) << 4);

    auto stage_A = [&](int it) {
        const int tap = (it < 25) ? it : it - 25;
        const uint16_t* abuf = (it < 25) ? inHi : inLo;
        const int ky = tap / 5, kx = tap - ky * 5;
        const int iy = apy + ky - pad, ix = apx + kx - pad;
        const bool inb = apv && (unsigned)iy < (unsigned)Hin && (unsigned)ix < (unsigned)Win;
        const char* as = inb ? (const char*)(abuf + ((size_t)(bA * Hin + iy) * Win + ix) * 128)
                             : (const char*)abuf;
        const uint32_t ad = adst0 + (it & 1) * TILEA;
        const int sz = inb ? 16 : 0;
        #pragma unroll
        for (int j = 0; j < 16; ++j)
            CP16(ad + j * 16, as + (size_t)j * 16, sz);
    };

    auto stage_Btile = [&](const uint16_t* wbuf, int tap, uint32_t bd) {
        const char* wb = (const char*)(wbuf + (size_t)tap * 128 * 136);
        #pragma unroll
        for (int j = 0; j < 8; ++j)
            CP16(bd + (j * 256 + tid) * 16, wb + (size_t)(j * 256 + tid) * 16, 16);
        if (tid < 128)
            CP16(bd + (2048 + tid) * 16, wb + (size_t)(2048 + tid) * 16, 16);
    };

    auto mma_pass = [&](uint32_t abase, uint32_t bbase) {
        #pragma unroll
        for (int ks = 0; ks < 8; ++ks) {
            uint32_t a[4][4];
            #pragma unroll
            for (int i = 0; i < 4; ++i)
                LDSM_X4(a[i][0], a[i][1], a[i][2], a[i][3],
                        a_rd0 + abase + i * 16 * 272 + ks * 32);
            #pragma unroll
            for (int nb = 0; nb < 4; ++nb) {
                uint32_t r0, r1, r2, r3;
                LDSM_X4(r0, r1, r2, r3, bbase + b_rdb + nb * 16 * 272 + ks * 32);
                #pragma unroll
                for (int i = 0; i < 4; ++i) {
                    MMA_F16(acc[i][2 * nb],     a[i][0], a[i][1], a[i][2], a[i][3], r0, r1);
                    MMA_F16(acc[i][2 * nb + 1], a[i][0], a[i][1], a[i][2], a[i][3], r2, r3);
                }
            }
        }
    };

    stage_A(0);
    CP_COMMIT();

    for (int it = 0; it < 50; ++it) {
        const int tap = (it < 25) ? it : it - 25;
        const int ph  = (it < 25) ? 0 : 1;
        // stage B for this iteration (single-buffered; prev MMA done at trailing sync)
        stage_Btile(wHi, tap, smBhi);
        if (ph == 0) stage_Btile(wLo, tap, smBlo);
        CP_COMMIT();
        if (it < 49) {
            stage_A(it + 1);
            CP_COMMIT();
            CP_WAIT1();
        } else {
            CP_WAIT0();
        }
        __syncthreads();
        const uint32_t abase = (it & 1) * TILEA;
        mma_pass(abase, smBhi);                    // A*Whi (both phases)
        if (ph == 0) mma_pass(abase, smBlo);       // Ahi*Wlo
        __syncthreads();
    }

    // epilogue: flattened NHWC fp32
    #pragma unroll
    for (int mb = 0; mb < 4; ++mb) {
        const int row0 = pbase + pxg * 64 + mb * 16 + (lane >> 2);
        const int row1 = row0 + 8;
        const bool v0 = (row0 < totalPx), v1 = (row1 < totalPx);
        #pragma unroll
        for (int nt = 0; nt < 8; ++nt) {
            const int co = cog * 64 + nt * 8 + 2 * (lane & 3);
            const float bz0 = sbias[co], bz1 = sbias[co + 1];
            float p00 = acc[mb][nt][0] + bz0, p01 = acc[mb][nt][1] + bz1;
            float p10 = acc[mb][nt][2] + bz0, p11 = acc[mb][nt][3] + bz1;
            if (relu) {
                p00 = fmaxf(p00, 0.f); p01 = fmaxf(p01, 0.f);
                p10 = fmaxf(p10, 0.f); p11 = fmaxf(p11, 0.f);
            }
            if (v0) *(float2*)(outp + (size_t)row0 * 128 + co) = make_float2(p00, p01);
            if (v1) *(float2*)(outp + (size_t)row1 * 128 + co) = make_float2(p10, p11);
        }
    }
}

// ================= 1-pass bf16 engine, M=256, flattened tiling ================
__global__ void __launch_bounds__(256, 1)
tc_eng1(const uint16_t* __restrict__ in, const uint16_t* __restrict__ wpack,
        const float* __restrict__ bias, __nv_bfloat16* __restrict__ outp,
        int Hin, int Win, int Hout, int Wout, int pad, int K)
{
    extern __shared__ char dsm[];
    __shared__ float sbias[128];
    const int tid  = threadIdx.x;
    const int wid  = tid >> 5;
    const int lane = tid & 31;
    const int Npix = Hout * Wout;
    const int totalPx = BB * Npix;
    const int pbase = blockIdx.x * 256;

    const uint32_t smA = smem_u32(dsm);
    const uint32_t smB = smA + 2 * TILEA;
    if (tid < 128) sbias[tid] = bias[tid];

    const int ap = pbase + tid;
    const bool apv = (ap < totalPx);
    const int bA  = apv ? ap / Npix : 0;
    const int apn = apv ? ap - bA * Npix : 0;
    const int apy = apn / Wout;
    const int apx = apn - apy * Wout;
    const uint32_t adst0 = smA + tid * 272;

    const int pxg = wid >> 1, cog = wid & 1;
    float acc[4][8][4];
    #pragma unroll
    for (int m = 0; m < 4; m++)
        #pragma unroll
        for (int n = 0; n < 8; n++)
            #pragma unroll
            for (int j = 0; j < 4; j++) acc[m][n][j] = 0.f;

    const uint32_t a_rd0 = smA + (pxg * 64 + (lane & 15)) * 272 + ((lane >> 4) << 4);
    const uint32_t b_rdb = (cog * 64 + ((lane >> 4) << 3) + (lane & 7)) * 272
                         + (((lane >> 3) & 1) << 4);
    const int NIT = K * K;

    auto stage = [&](int tap) {
        const int buf = tap & 1;
        const int ky = tap / K, kx = tap - ky * K;
        const char* wb = (const char*)(wpack + (size_t)tap * 128 * 136);
        const uint32_t bd = smB + buf * TILE;
        #pragma unroll
        for (int j = 0; j < 8; ++j)
            CP16(bd + (j * 256 + tid) * 16, wb + (size_t)(j * 256 + tid) * 16, 16);
        if (tid < 128)
            CP16(bd + (2048 + tid) * 16, wb + (size_t)(2048 + tid) * 16, 16);
        const int iy = apy + ky - pad, ix = apx + kx - pad;
        const bool inb = apv && (unsigned)iy < (unsigned)Hin && (unsigned)ix < (unsigned)Win;
        const char* as = inb ? (const char*)(in + ((size_t)(bA * Hin + iy) * Win + ix) * 128)
                             : (const char*)in;
        const uint32_t ad = adst0 + buf * TILEA;
        const int sz = inb ? 16 : 0;
        #pragma unroll
        for (int j = 0; j < 16; ++j)
            CP16(ad + j * 16, as + (size_t)j * 16, sz);
        CP_COMMIT();
    };

    stage(0);
    for (int it = 0; it < NIT; ++it) {
        CP_WAIT0();
        __syncthreads();
        if (it + 1 < NIT) stage(it + 1);
        const uint32_t abase = (it & 1) * TILEA;
        const uint32_t bbase = smB + (it & 1) * TILE;
        #pragma unroll
        for (int ks = 0; ks < 8; ++ks) {
            uint32_t a[4][4];
            #pragma unroll
            for (int i = 0; i < 4; ++i)
                LDSM_X4(a[i][0], a[i][1], a[i][2], a[i][3],
                        a_rd0 + abase + i * 16 * 272 + ks * 32);
            #pragma unroll
            for (int nb = 0; nb < 4; ++nb) {
                uint32_t r0, r1, r2, r3;
                LDSM_X4(r0, r1, r2, r3, bbase + b_rdb + nb * 16 * 272 + ks * 32);
                #pragma unroll
                for (int i = 0; i < 4; ++i) {
                    MMA_BF16(acc[i][2 * nb],     a[i][0], a[i][1], a[i][2], a[i][3], r0, r1);
                    MMA_BF16(acc[i][2 * nb + 1], a[i][0], a[i][1], a[i][2], a[i][3], r2, r3);
                }
            }
        }
        __syncthreads();
    }

    #pragma unroll
    for (int mb = 0; mb < 4; ++mb) {
        const int row0 = pbase + pxg * 64 + mb * 16 + (lane >> 2);
        const int row1 = row0 + 8;
        const bool v0 = (row0 < totalPx), v1 = (row1 < totalPx);
        #pragma unroll
        for (int nt = 0; nt < 8; ++nt) {
            const int co = cog * 64 + nt * 8 + 2 * (lane & 3);
            const float bz0 = sbias[co], bz1 = sbias[co + 1];
            float p00 = fmaxf(acc[mb][nt][0] + bz0, 0.f);
            float p01 = fmaxf(acc[mb][nt][1] + bz1, 0.f);
            float p10 = fmaxf(acc[mb][nt][2] + bz0, 0.f);
            float p11 = fmaxf(acc[mb][nt][3] + bz1, 0.f);
            if (v0) {
                __nv_bfloat162 h = __floats2bfloat162_rn(p00, p01);
                *(uint32_t*)(outp + (size_t)row0 * 128 + co) = *reinterpret_cast<uint32_t*>(&h);
            }
            if (v1) {
                __nv_bfloat162 h = __floats2bfloat162_rn(p10, p11);
                *(uint32_t*)(outp + (size_t)row1 * 128 + co) = *reinterpret_cast<uint32_t*>(&h);
            }
        }
    }
}

// ================= t2 stride-2 deconv, parity decomposition, M=256 ============
__global__ void __launch_bounds__(256, 1)
tc_t2(const uint16_t* __restrict__ in, const uint16_t* __restrict__ wpack,
      const float* __restrict__ bias, __nv_bfloat16* __restrict__ outp)
{
    extern __shared__ char dsm[];
    __shared__ float sbias[128];
    const int tid  = threadIdx.x;
    const int wid  = tid >> 5;
    const int lane = tid & 31;
    const int par  = blockIdx.z;
    const int py   = par >> 1, px = par & 1;
    const int totalPx = BB * 100;
    const int pbase = blockIdx.x * 256;

    const uint32_t smA = smem_u32(dsm);
    const uint32_t smB = smA + 2 * TILEA;
    if (tid < 128) sbias[tid] = bias[tid];

    const int ap = pbase + tid;
    const bool apv = (ap < totalPx);
    const int bA  = apv ? ap / 100 : 0;
    const int apn = apv ? ap - bA * 100 : 0;
    const int apy = apn / 10;
    const int apx = apn - apy * 10;
    const uint32_t adst0 = smA + tid * 272;

    const int pxg = wid >> 1, cog = wid & 1;
    float acc[4][8][4];
    #pragma unroll
    for (int m = 0; m < 4; m++)
        #pragma unroll
        for (int n = 0; n < 8; n++)
            #pragma unroll
            for (int j = 0; j < 4; j++) acc[m][n][j] = 0.f;

    const uint32_t a_rd0 = smA + (pxg * 64 + (lane & 15)) * 272 + ((lane >> 4) << 4);
    const uint32_t b_rdb = (cog * 64 + ((lane >> 4) << 3) + (lane & 7)) * 272
                         + (((lane >> 3) & 1) << 4);

    auto stage = [&](int tap) {
        const int buf = tap & 1;
        const int ti = tap >> 1, tj = tap & 1;
        const char* wb = (const char*)(wpack + (size_t)(par * 4 + tap) * 128 * 136);
        const uint32_t bd = smB + buf * TILE;
        #pragma unroll
        for (int j = 0; j < 8; ++j)
            CP16(bd + (j * 256 + tid) * 16, wb + (size_t)(j * 256 + tid) * 16, 16);
        if (tid < 128)
            CP16(bd + (2048 + tid) * 16, wb + (size_t)(2048 + tid) * 16, 16);
        const int iy = apy - ti, ix = apx - tj;
        const bool inb = apv && (unsigned)iy < 9u && (unsigned)ix < 9u;
        const char* as = inb ? (const char*)(in + ((size_t)(bA * 9 + iy) * 9 + ix) * 128)
                             : (const char*)in;
        const uint32_t ad = adst0 + buf * TILEA;
        const int sz = inb ? 16 : 0;
        #pragma unroll
        for (int j = 0; j < 16; ++j)
            CP16(ad + j * 16, as + (size_t)j * 16, sz);
        CP_COMMIT();
    };

    stage(0);
    for (int it = 0; it < 4; ++it) {
        CP_WAIT0();
        __syncthreads();
        if (it + 1 < 4) stage(it + 1);
        const uint32_t abase = (it & 1) * TILEA;
        const uint32_t bbase = smB + (it & 1) * TILE;
        #pragma unroll
        for (int ks = 0; ks < 8; ++ks) {
            uint32_t a[4][4];
            #pragma unroll
            for (int i = 0; i < 4; ++i)
                LDSM_X4(a[i][0], a[i][1], a[i][2], a[i][3],
                        a_rd0 + abase + i * 16 * 272 + ks * 32);
            #pragma unroll
            for (int nb = 0; nb < 4; ++nb) {
                uint32_t r0, r1, r2, r3;
                LDSM_X4(r0, r1, r2, r3, bbase + b_rdb + nb * 16 * 272 + ks * 32);
                #pragma unroll
                for (int i = 0; i < 4; ++i) {
                    MMA_BF16(acc[i][2 * nb],     a[i][0], a[i][1], a[i][2], a[i][3], r0, r1);
                    MMA_BF16(acc[i][2 * nb + 1], a[i][0], a[i][1], a[i][2], a[i][3], r2, r3);
                }
            }
        }
        __syncthreads();
    }

    #pragma unroll
    for (int mb = 0; mb < 4; ++mb) {
        const int r0g = pbase + pxg * 64 + mb * 16 + (lane >> 2);
        const int r1g = r0g + 8;
        int b0 = r0g / 100, q0 = r0g - b0 * 100, y0 = q0 / 10, x0 = q0 - y0 * 10;
        int b1 = r1g / 100, q1 = r1g - b1 * 100, y1 = q1 / 10, x1 = q1 - y1 * 10;
        size_t o0 = ((size_t)b0 * 400 + (2 * y0 + py) * 20 + 2 * x0 + px) * 128;
        size_t o1 = ((size_t)b1 * 400 + (2 * y1 + py) * 20 + 2 * x1 + px) * 128;
        #pragma unroll
        for (int nt = 0; nt < 8; ++nt) {
            const int co = cog * 64 + nt * 8 + 2 * (lane & 3);
            const float bz0 = sbias[co], bz1 = sbias[co + 1];
            float p00 = fmaxf(acc[mb][nt][0] + bz0, 0.f);
            float p01 = fmaxf(acc[mb][nt][1] + bz1, 0.f);
            float p10 = fmaxf(acc[mb][nt][2] + bz0, 0.f);
            float p11 = fmaxf(acc[mb][nt][3] + bz1, 0.f);
            if (r0g < totalPx) {
                __nv_bfloat162 h = __floats2bfloat162_rn(p00, p01);
                *(uint32_t*)(outp + o0 + co) = *reinterpret_cast<uint32_t*>(&h);
            }
            if (r1g < totalPx) {
                __nv_bfloat162 h = __floats2bfloat162_rn(p10, p11);
                *(uint32_t*)(outp + o1 + co) = *reinterpret_cast<uint32_t*>(&h);
            }
        }
    }
}

// ---------------- conv1 (Cin=1) fused with fp16 hi/lo split, NHWC -------------
__global__ void __launch_bounds__(128)
conv1_split(const float* __restrict__ x, const float* __restrict__ w1,
            const float* __restrict__ b1, __half* __restrict__ hi,
            __half* __restrict__ lo)
{
    const int b = blockIdx.x, p = blockIdx.y, co = threadIdx.x;
    const int oy = p / 24, ox = p - oy * 24;
    __shared__ float xs[25];
    if (co < 25) {
        int ky = co / 5, kx = co - (co / 5) * 5;
        xs[co] = x[(size_t)b * 784 + (oy + ky) * 28 + ox + kx];
    }
    __syncthreads();
    const float* w = w1 + co * 25;
    float v = b1[co];
    #pragma unroll
    for (int t = 0; t < 25; ++t) v += w[t] * xs[t];
    v = fmaxf(v, 0.f);
    __half h = __float2half_rn(v);
    size_t o = ((size_t)b * 576 + p) * 128 + co;
    hi[o] = h;
    lo[o] = __float2half_rn(v - __half2float(h));
}

// ---------------- NHWC maxpool 2x2: fp32 -> fp16 hi/lo -----------------------
__global__ void mp_split_nhwc(const float* __restrict__ in, __half* __restrict__ hi,
                              __half* __restrict__ lo, int Hin, int Win)
{
    const int Ho = Hin >> 1, Wo = Win >> 1;
    const size_t total = (size_t)BB * Ho * Wo * 128;
    for (size_t i = (size_t)blockIdx.x * blockDim.x + threadIdx.x; i < total;
         i += (size_t)gridDim.x * blockDim.x) {
        int c = (int)(i & 127);
        size_t r = i >> 7;
        int wo = (int)(r % Wo); r /= Wo;
        int ho = (int)(r % Ho); int b = (int)(r / Ho);
        const float* p = in + (((size_t)b * Hin + 2 * ho) * Win + 2 * wo) * 128 + c;
        float v = fmaxf(fmaxf(p[0], p[128]),
                        fmaxf(p[(size_t)Win * 128], p[(size_t)(Win + 1) * 128]));
        __half h = __float2half_rn(v);
        hi[i] = h;
        lo[i] = __float2half_rn(v - __half2float(h));
    }
}

// ---------------- NHWC maxpool 2x2: fp32 -> fp32 -----------------------------
__global__ void mp_nhwc(const float* __restrict__ in, float* __restrict__ out,
                        int Hin, int Win)
{
    const int Ho = Hin >> 1, Wo = Win >> 1;
    const size_t total = (size_t)BB * Ho * Wo * 128;
    for (size_t i = (size_t)blockIdx.x * blockDim.x + threadIdx.x; i < total;
         i += (size_t)gridDim.x * blockDim.x) {
        int c = (int)(i & 127);
        size_t r = i >> 7;
        int wo = (int)(r % Wo); r /= Wo;
        int ho = (int)(r % Ho); int b = (int)(r / Ho);
        const float* p = in + (((size_t)b * Hin + 2 * ho) * Win + 2 * wo) * 128 + c;
        out[i] = fmaxf(fmaxf(p[0], p[128]),
                       fmaxf(p[(size_t)Win * 128], p[(size_t)(Win + 1) * 128]));
    }
}

// ---------------- VQ: argmax(d2), gather val (NHWC bf16), dict MSE ------------
__global__ void __launch_bounds__(256)
vq_kernel(const float* __restrict__ z, const float* __restrict__ dict,
          __nv_bfloat16* __restrict__ valh, float* __restrict__ idx_out)
{
    extern __shared__ float dsmf[];
    __shared__ float zt[36 * 128];
    __shared__ float wn[128];
    __shared__ int   sidx[36];

    const int b = blockIdx.x, tid = threadIdx.x;

    for (int i = tid; i < 128 * 128; i += NT) {
        int k = i >> 7; int c = i & 127;
        dsmf[k * 129 + c] = dict[i];
    }
    for (int i = tid; i < 36 * 128; i += NT)
        zt[i] = z[(size_t)b * 4608 + i];
    __syncthreads();
    if (tid < 128) {
        float s = 0.f;
        const float* dp = dsmf + tid * 129;
        for (int c = 0; c < 128; c++) s += dp[c] * dp[c];
        wn[tid] = s;
    }
    __syncthreads();

    const int lane = tid & 31, wid = tid >> 5;
    for (int pos = wid; pos < 36; pos += 8) {
        float d0 = 0.f, d1 = 0.f, d2s = 0.f, d3 = 0.f, zn = 0.f;
        const float* zp = zt + pos * 128;
        const float* p0 = dsmf + (lane      ) * 129;
        const float* p1 = dsmf + (lane + 32 ) * 129;
        const float* p2 = dsmf + (lane + 64 ) * 129;
        const float* p3 = dsmf + (lane + 96 ) * 129;
        for (int c = 0; c < 128; c++) {
            float zv = zp[c];
            zn += zv * zv;
            d0 += p0[c] * zv; d1 += p1[c] * zv;
            d2s += p2[c] * zv; d3 += p3[c] * zv;
        }
        float bv = zn + wn[lane] - 2.f * d0; int bk = lane;
        float v1 = zn + wn[lane + 32] - 2.f * d1; if (v1 > bv) { bv = v1; bk = lane + 32; }
        float v2 = zn + wn[lane + 64] - 2.f * d2s; if (v2 > bv) { bv = v2; bk = lane + 64; }
        float v3 = zn + wn[lane + 96] - 2.f * d3; if (v3 > bv) { bv = v3; bk = lane + 96; }
        #pragma unroll
        for (int o = 16; o; o >>= 1) {
            float ov = __shfl_xor_sync(0xffffffffu, bv, o);
            int   ok = __shfl_xor_sync(0xffffffffu, bk, o);
            if (ov > bv || (ov == bv && ok < bk)) { bv = ov; bk = ok; }
        }
        if (lane == 0) {
            sidx[pos] = bk;
            if (idx_out) idx_out[b * 36 + pos] = (float)bk;
        }
    }
    __syncthreads();

    float lsum = 0.f;
    for (int i = tid; i < 4608; i += NT) {
        int pos = i >> 7; int c = i & 127;
        float v  = dsmf[sidx[pos] * 129 + c];
        float zv = zt[i];
        valh[(size_t)b * 4608 + i] = __float2bfloat16(v);
        float d = v - zv;
        lsum += d * d;
    }
    lsum = warp_sum(lsum);
    if ((tid & 31) == 0) atomicAdd(&g_dict_sum, (double)lsum);
}

// ---------------- mu (1x1 conv) fused with reconstruction loss (NHWC bf16) ---
__global__ void __launch_bounds__(256)
mu_loss(const __nv_bfloat16* __restrict__ f4, const float* __restrict__ x,
        const float* __restrict__ mw, const float* __restrict__ mb)
{
    __shared__ float mws[128];
    const int b = blockIdx.x, tid = threadIdx.x;
    if (tid < 128) mws[tid] = mw[tid];
    __syncthreads();
    float lsum = 0.f;
    for (int px = tid; px < 784; px += NT) {
        const uint4* fp = (const uint4*)(f4 + ((size_t)b * 784 + px) * 128);
        float s = mb[0];
        #pragma unroll
        for (int j = 0; j < 16; j++) {
            uint4 v = fp[j];
            const __nv_bfloat16* h = (const __nv_bfloat16*)&v;
            #pragma unroll
            for (int t = 0; t < 8; t++)
                s += __bfloat162float(h[t]) * mws[j * 8 + t];
        }
        float d = s - x[(size_t)b * 784 + px];
        lsum += d * d;
    }
    lsum = warp_sum(lsum);
    if ((tid & 31) == 0) atomicAdd(&g_rec_sum, (double)lsum);
}

__global__ void finalize_kernel(float* loss_out)
{
    if (loss_out) {
        double dict_mse = g_dict_sum / 1179648.0;
        loss_out[0] = (float)(g_rec_sum / 200704.0);
        loss_out[1] = (float)(dict_mse * 5.0);
        loss_out[2] = (float)(dict_mse * 1.25);
        loss_out[3] = 0.f;
    }
}

// ---------------- host side ----------------------------------------------------
extern "C" void kernel_launch(void* const* d_in, const int* in_sizes, int n_in,
                              void* d_out, int out_size)
{
    const float* x    = (const float*)d_in[0];
    const float* w1   = (const float*)d_in[1];
    const float* b1   = (const float*)d_in[2];
    const float* w2   = (const float*)d_in[3];
    const float* b2   = (const float*)d_in[4];
    const float* w3   = (const float*)d_in[5];
    const float* b3   = (const float*)d_in[6];
    const float* t1w  = (const float*)d_in[7];
    const float* t1b  = (const float*)d_in[8];
    const float* t2w  = (const float*)d_in[9];
    const float* t2b  = (const float*)d_in[10];
    const float* t3w  = (const float*)d_in[11];
    const float* t3b  = (const float*)d_in[12];
    const float* t4w  = (const float*)d_in[13];
    const float* t4b  = (const float*)d_in[14];
    const float* mw   = (const float*)d_in[15];
    const float* mb   = (const float*)d_in[16];
    const float* dictw= (const float*)d_in[17];

    float* outp = (float*)d_out;
    float* loss_ptr = outp;
    float* idx_ptr  = outp + 4;
    if (out_size < 9220) { loss_ptr = nullptr; idx_ptr = outp; }

    __half *c1hi, *c1lo, *p1hi, *p1lo, *w2hi, *w2lo, *w3hi, *w3lo;
    float *c2f, *c3f, *zn;
    __nv_bfloat16 *valh, *f1h, *f2h, *f3h, *f4h, *wp1, *wpt2, *wp3, *wp4;
    cudaGetSymbolAddress((void**)&c1hi, g_c1hi);
    cudaGetSymbolAddress((void**)&c1lo, g_c1lo);
    cudaGetSymbolAddress((void**)&c2f,  g_c2f);
    cudaGetSymbolAddress((void**)&p1hi, g_p1hi);
    cudaGetSymbolAddress((void**)&p1lo, g_p1lo);
    cudaGetSymbolAddress((void**)&c3f,  g_c3f);
    cudaGetSymbolAddress((void**)&zn,   g_zn);
    cudaGetSymbolAddress((void**)&valh, g_valh);
    cudaGetSymbolAddress((void**)&f1h,  g_f1h);
    cudaGetSymbolAddress((void**)&f2h,  g_f2h);
    cudaGetSymbolAddress((void**)&f3h,  g_f3h);
    cudaGetSymbolAddress((void**)&f4h,  g_f4h);
    cudaGetSymbolAddress((void**)&wp1,  g_wp1);
    cudaGetSymbolAddress((void**)&wpt2, g_wpt2);
    cudaGetSymbolAddress((void**)&wp3,  g_wp3);
    cudaGetSymbolAddress((void**)&wp4,  g_wp4);
    cudaGetSymbolAddress((void**)&w2hi, g_w2hi);
    cudaGetSymbolAddress((void**)&w2lo, g_w2lo);
    cudaGetSymbolAddress((void**)&w3hi, g_w3hi);
    cudaGetSymbolAddress((void**)&w3lo, g_w3lo);

    static bool attr_set = false;
    if (!attr_set) {
        cudaFuncSetAttribute(vq_kernel, cudaFuncAttributeMaxDynamicSharedMemorySize,
                             128 * 129 * (int)sizeof(float));
        cudaFuncSetAttribute(tc_eng1, cudaFuncAttributeMaxDynamicSharedMemorySize,
                             2 * TILEA + 2 * TILE);
        cudaFuncSetAttribute(tc_t2, cudaFuncAttributeMaxDynamicSharedMemorySize,
                             2 * TILEA + 2 * TILE);
        cudaFuncSetAttribute(tc_enc3, cudaFuncAttributeMaxDynamicSharedMemorySize,
                             2 * TILEA + 2 * TILE);
        attr_set = true;
    }

    // launch order: tc_enc3(conv2) at our index 3 (harness prepends ~2 launches,
    // so ncu -s 5 -c 1 should land on it)
    init_kernel<<<1, 1>>>();                                    // 0
    prepack_fwd_split<<<25, 256>>>(w2, w2hi, w2lo);             // 1
    conv1_split<<<dim3(BB, 576), 128>>>(x, w1, b1, c1hi, c1lo); // 2
    tc_enc3<<<576, 256, 2 * TILEA + 2 * TILE>>>(                // 3 <- profile
        (const uint16_t*)c1hi, (const uint16_t*)c1lo,
        (const uint16_t*)w2hi, (const uint16_t*)w2lo,
        b2, c2f, 24, 24, 24, 24, 2, 1);
    prepack_fwd_split<<<25, 256>>>(w3, w3hi, w3lo);
    mp_split_nhwc<<<4096, 256>>>(c2f, p1hi, p1lo, 24, 24);
    tc_enc3<<<144, 256, 2 * TILEA + 2 * TILE>>>(
        (const uint16_t*)p1hi, (const uint16_t*)p1lo,
        (const uint16_t*)w3hi, (const uint16_t*)w3lo,
        b3, c3f, 12, 12, 12, 12, 2, 0);
    mp_nhwc<<<2048, 256>>>(c3f, zn, 12, 12);
    prepack_w<<<16, 256>>>(t1w, wp1, 4);
    prepack_t2<<<16, 256>>>(t2w, wpt2);
    prepack_w<<<25, 256>>>(t3w, wp3, 5);
    prepack_w<<<25, 256>>>(t4w, wp4, 5);

    vq_kernel<<<BB, NT, 128 * 129 * sizeof(float)>>>(zn, dictw, valh, idx_ptr);

    tc_eng1<<<81, 256, 2 * TILEA + 2 * TILE>>>(
        (const uint16_t*)valh, (const uint16_t*)wp1, t1b, f1h, 6, 6, 9, 9, 3, 4);
    tc_t2<<<dim3(100, 1, 4), 256, 2 * TILEA + 2 * TILE>>>(
        (const uint16_t*)f1h, (const uint16_t*)wpt2, t2b, f2h);
    tc_eng1<<<576, 256, 2 * TILEA + 2 * TILE>>>(
        (const uint16_t*)f2h, (const uint16_t*)wp3, t3b, f3h, 20, 20, 24, 24, 4, 5);
    tc_eng1<<<784, 256, 2 * TILEA + 2 * TILE>>>(
        (const uint16_t*)f3h, (const uint16_t*)wp4, t4b, f4h, 24, 24, 28, 28, 4, 5);

    mu_loss<<<BB, NT>>>(f4h, x, mw, mb);
    finalize_kernel<<<1, 1>>>(loss_ptr);
}

// round 10
// speedup vs baseline: 6.7471x; 1.1198x over previous
#include <cuda_runtime.h>
#include <cuda_bf16.h>
#include <cuda_fp16.h>
#include <cstdint>

#define BB 256
#define NT 256
#define TILE 34816          // 128 rows x 272B
#define TILEA 69632         // 256 rows x 272B

// ---------------- scratch (device globals; no allocation APIs) ---------------
__device__ __half g_c1hi[(size_t)BB*576*128];
__device__ __half g_c1lo[(size_t)BB*576*128];
__device__ float  g_c2f [(size_t)BB*576*128];
__device__ __half g_p1hi[(size_t)BB*144*128];
__device__ __half g_p1lo[(size_t)BB*144*128];
__device__ float  g_c3f [(size_t)BB*144*128];
__device__ float  g_zn  [(size_t)BB*36*128];
__device__ __nv_bfloat16 g_valh[(size_t)BB*36*128];
__device__ __nv_bfloat16 g_f1h[(size_t)BB*81*128];
__device__ __nv_bfloat16 g_f2h[(size_t)BB*400*128];
__device__ __nv_bfloat16 g_f3h[(size_t)BB*576*128];
__device__ __nv_bfloat16 g_f4h[(size_t)BB*784*128];
__device__ __nv_bfloat16 g_wp1[16*128*136];
__device__ __nv_bfloat16 g_wpt2[16*128*136];
__device__ __nv_bfloat16 g_wp3[25*128*136];
__device__ __nv_bfloat16 g_wp4[25*128*136];
__device__ __half g_w2hi[25*128*136];
__device__ __half g_w2lo[25*128*136];
__device__ __half g_w3hi[25*128*136];
__device__ __half g_w3lo[25*128*136];
__device__ double g_rec_sum;
__device__ double g_dict_sum;

__global__ void init_kernel() { g_rec_sum = 0.0; g_dict_sum = 0.0; }

__inline__ __device__ float warp_sum(float v) {
    #pragma unroll
    for (int o = 16; o; o >>= 1) v += __shfl_xor_sync(0xffffffffu, v, o);
    return v;
}

// ---------------- mma / cp.async helpers --------------------------------------
__device__ __forceinline__ uint32_t smem_u32(const void* p) {
    uint32_t a;
    asm("{ .reg .u64 t; cvta.to.shared.u64 t, %1; cvt.u32.u64 %0, t; }"
        : "=r"(a) : "l"(p));
    return a;
}

#define LDSM_X4(r0, r1, r2, r3, addr)                                          \
    asm volatile("ldmatrix.sync.aligned.m8n8.x4.shared.b16 {%0,%1,%2,%3}, [%4];" \
                 : "=r"(r0), "=r"(r1), "=r"(r2), "=r"(r3) : "r"(addr))

#define MMA_BF16(c, a0, a1, a2, a3, b0, b1)                                    \
    asm volatile("mma.sync.aligned.m16n8k16.row.col.f32.bf16.bf16.f32 "        \
                 "{%0,%1,%2,%3}, {%4,%5,%6,%7}, {%8,%9}, {%0,%1,%2,%3};"       \
                 : "+f"((c)[0]), "+f"((c)[1]), "+f"((c)[2]), "+f"((c)[3])      \
                 : "r"(a0), "r"(a1), "r"(a2), "r"(a3), "r"(b0), "r"(b1))

#define MMA_F16(c, a0, a1, a2, a3, b0, b1)                                     \
    asm volatile("mma.sync.aligned.m16n8k16.row.col.f32.f16.f16.f32 "          \
                 "{%0,%1,%2,%3}, {%4,%5,%6,%7}, {%8,%9}, {%0,%1,%2,%3};"       \
                 : "+f"((c)[0]), "+f"((c)[1]), "+f"((c)[2]), "+f"((c)[3])      \
                 : "r"(a0), "r"(a1), "r"(a2), "r"(a3), "r"(b0), "r"(b1))

#define CP16(d, s, n)                                                          \
    asm volatile("cp.async.cg.shared.global [%0], [%1], 16, %2;"               \
                 :: "r"(d), "l"(s), "r"(n))
#define CP_COMMIT() asm volatile("cp.async.commit_group;" ::: "memory")
#define CP_WAIT0()  asm volatile("cp.async.wait_group 0;" ::: "memory")
#define CP_WAIT1()  asm volatile("cp.async.wait_group 1;" ::: "memory")

// ---------------- fused weight prepack (all layers, one launch) ---------------
__device__ __forceinline__ void pp_fwd_split(const float* W, __half* dh, __half* dl,
                                             int tap)
{
    int ky = tap / 5, kx = tap - ky * 5;
    size_t tb = (size_t)tap * 128 * 136;
    for (int i = threadIdx.x; i < 16384; i += blockDim.x) {
        int co = i >> 7, ci = i & 127;
        float v = W[(((size_t)co * 128 + ci) * 5 + ky) * 5 + kx];
        __half h = __float2half_rn(v);
        dh[tb + co * 136 + ci] = h;
        dl[tb + co * 136 + ci] = __float2half_rn(v - __half2float(h));
    }
}

__device__ __forceinline__ void pp_deconv(const float* W, __nv_bfloat16* dst,
                                          int tap, int K)
{
    int ky = tap / K, kx = tap - ky * K;
    __nv_bfloat16* base = dst + (size_t)tap * 128 * 136;
    for (int i = threadIdx.x; i < 16384; i += blockDim.x) {
        int co = i >> 7, ci = i & 127;
        float v = W[(((size_t)ci * 128 + co) * K + (K - 1 - ky)) * K + (K - 1 - kx)];
        base[co * 136 + ci] = __float2bfloat16(v);
    }
}

__device__ __forceinline__ void pp_t2(const float* W, __nv_bfloat16* dst, int idx)
{
    int par = idx >> 2, tap = idx & 3;
    int py = par >> 1, px = par & 1;
    int ti = tap >> 1, tj = tap & 1;
    int ky = py + 2 * ti, kx = px + 2 * tj;
    __nv_bfloat16* base = dst + (size_t)idx * 128 * 136;
    for (int i = threadIdx.x; i < 16384; i += blockDim.x) {
        int co = i >> 7, ci = i & 127;
        float v = W[(((size_t)ci * 128 + co) * 4 + ky) * 4 + kx];
        base[co * 136 + ci] = __float2bfloat16(v);
    }
}

__global__ void prepack_all(const float* w2, const float* w3,
                            const float* t1w, const float* t2w,
                            const float* t3w, const float* t4w,
                            __half* w2hi, __half* w2lo,
                            __half* w3hi, __half* w3lo,
                            __nv_bfloat16* wp1, __nv_bfloat16* wpt2,
                            __nv_bfloat16* wp3, __nv_bfloat16* wp4)
{
    int bid = blockIdx.x;
    if      (bid < 25)  pp_fwd_split(w2, w2hi, w2lo, bid);
    else if (bid < 50)  pp_fwd_split(w3, w3hi, w3lo, bid - 25);
    else if (bid < 66)  pp_deconv(t1w, wp1, bid - 50, 4);
    else if (bid < 82)  pp_t2(t2w, wpt2, bid - 66);
    else if (bid < 107) pp_deconv(t3w, wp3, bid - 82, 5);
    else                pp_deconv(t4w, wp4, bid - 107, 5);
}

// ====== fused 3-pass fp16-split encoder conv, M=256, pass-reordered ===========
__global__ void __launch_bounds__(256, 1)
tc_enc3(const uint16_t* __restrict__ inHi, const uint16_t* __restrict__ inLo,
        const uint16_t* __restrict__ wHi,  const uint16_t* __restrict__ wLo,
        const float* __restrict__ bias, float* __restrict__ outp,
        int Hin, int Win, int Hout, int Wout, int pad, int relu)
{
    extern __shared__ char dsm[];
    __shared__ float sbias[128];
    const int tid  = threadIdx.x;
    const int wid  = tid >> 5;
    const int lane = tid & 31;
    const int Npix = Hout * Wout;
    const int totalPx = BB * Npix;
    const int pbase = blockIdx.x * 256;

    const uint32_t smA   = smem_u32(dsm);
    const uint32_t smBhi = smA + 2 * TILEA;
    const uint32_t smBlo = smBhi + TILE;
    if (tid < 128) sbias[tid] = bias[tid];

    const int ap = pbase + tid;
    const bool apv = (ap < totalPx);
    const int bA  = apv ? ap / Npix : 0;
    const int apn = apv ? ap - bA * Npix : 0;
    const int apy = apn / Wout;
    const int apx = apn - apy * Wout;
    const uint32_t adst0 = smA + tid * 272;

    const int pxg = wid >> 1, cog = wid & 1;
    float acc[4][8][4];
    #pragma unroll
    for (int m = 0; m < 4; m++)
        #pragma unroll
        for (int n = 0; n < 8; n++)
            #pragma unroll
            for (int j = 0; j < 4; j++) acc[m][n][j] = 0.f;

    const uint32_t a_rd0 = smA + (pxg * 64 + (lane & 15)) * 272 + ((lane >> 4) << 4);
    const uint32_t b_rdb = (cog * 64 + ((lane >> 4) << 3) + (lane & 7)) * 272
                         + (((lane >> 3) & 1) << 4);

    auto stage_A = [&](int it) {
        const int tap = (it < 25) ? it : it - 25;
        const uint16_t* abuf = (it < 25) ? inHi : inLo;
        const int ky = tap / 5, kx = tap - ky * 5;
        const int iy = apy + ky - pad, ix = apx + kx - pad;
        const bool inb = apv && (unsigned)iy < (unsigned)Hin && (unsigned)ix < (unsigned)Win;
        const char* as = inb ? (const char*)(abuf + ((size_t)(bA * Hin + iy) * Win + ix) * 128)
                             : (const char*)abuf;
        const uint32_t ad = adst0 + (it & 1) * TILEA;
        const int sz = inb ? 16 : 0;
        #pragma unroll
        for (int j = 0; j < 16; ++j)
            CP16(ad + j * 16, as + (size_t)j * 16, sz);
    };

    auto stage_Btile = [&](const uint16_t* wbuf, int tap, uint32_t bd) {
        const char* wb = (const char*)(wbuf + (size_t)tap * 128 * 136);
        #pragma unroll
        for (int j = 0; j < 8; ++j)
            CP16(bd + (j * 256 + tid) * 16, wb + (size_t)(j * 256 + tid) * 16, 16);
        if (tid < 128)
            CP16(bd + (2048 + tid) * 16, wb + (size_t)(2048 + tid) * 16, 16);
    };

    auto mma_pass = [&](uint32_t abase, uint32_t bbase) {
        #pragma unroll
        for (int ks = 0; ks < 8; ++ks) {
            uint32_t a[4][4], bq[4][4];
            #pragma unroll
            for (int i = 0; i < 4; ++i)
                LDSM_X4(a[i][0], a[i][1], a[i][2], a[i][3],
                        a_rd0 + abase + i * 16 * 272 + ks * 32);
            #pragma unroll
            for (int nb = 0; nb < 4; ++nb)
                LDSM_X4(bq[nb][0], bq[nb][1], bq[nb][2], bq[nb][3],
                        bbase + b_rdb + nb * 16 * 272 + ks * 32);
            #pragma unroll
            for (int nb = 0; nb < 4; ++nb)
                #pragma unroll
                for (int i = 0; i < 4; ++i) {
                    MMA_F16(acc[i][2 * nb],     a[i][0], a[i][1], a[i][2], a[i][3],
                            bq[nb][0], bq[nb][1]);
                    MMA_F16(acc[i][2 * nb + 1], a[i][0], a[i][1], a[i][2], a[i][3],
                            bq[nb][2], bq[nb][3]);
                }
        }
    };

    stage_A(0);
    CP_COMMIT();

    for (int it = 0; it < 50; ++it) {
        const int tap = (it < 25) ? it : it - 25;
        const int ph  = (it < 25) ? 0 : 1;
        stage_Btile(wHi, tap, smBhi);
        if (ph == 0) stage_Btile(wLo, tap, smBlo);
        CP_COMMIT();
        if (it < 49) {
            stage_A(it + 1);
            CP_COMMIT();
            CP_WAIT1();
        } else {
            CP_WAIT0();
        }
        __syncthreads();
        const uint32_t abase = (it & 1) * TILEA;
        mma_pass(abase, smBhi);
        if (ph == 0) mma_pass(abase, smBlo);
        __syncthreads();
    }

    #pragma unroll
    for (int mb = 0; mb < 4; ++mb) {
        const int row0 = pbase + pxg * 64 + mb * 16 + (lane >> 2);
        const int row1 = row0 + 8;
        const bool v0 = (row0 < totalPx), v1 = (row1 < totalPx);
        #pragma unroll
        for (int nt = 0; nt < 8; ++nt) {
            const int co = cog * 64 + nt * 8 + 2 * (lane & 3);
            const float bz0 = sbias[co], bz1 = sbias[co + 1];
            float p00 = acc[mb][nt][0] + bz0, p01 = acc[mb][nt][1] + bz1;
            float p10 = acc[mb][nt][2] + bz0, p11 = acc[mb][nt][3] + bz1;
            if (relu) {
                p00 = fmaxf(p00, 0.f); p01 = fmaxf(p01, 0.f);
                p10 = fmaxf(p10, 0.f); p11 = fmaxf(p11, 0.f);
            }
            if (v0) *(float2*)(outp + (size_t)row0 * 128 + co) = make_float2(p00, p01);
            if (v1) *(float2*)(outp + (size_t)row1 * 128 + co) = make_float2(p10, p11);
        }
    }
}

// ================= 1-pass bf16 engine, M=256, flattened tiling ================
__global__ void __launch_bounds__(256, 1)
tc_eng1(const uint16_t* __restrict__ in, const uint16_t* __restrict__ wpack,
        const float* __restrict__ bias, __nv_bfloat16* __restrict__ outp,
        int Hin, int Win, int Hout, int Wout, int pad, int K)
{
    extern __shared__ char dsm[];
    __shared__ float sbias[128];
    const int tid  = threadIdx.x;
    const int wid  = tid >> 5;
    const int lane = tid & 31;
    const int Npix = Hout * Wout;
    const int totalPx = BB * Npix;
    const int pbase = blockIdx.x * 256;

    const uint32_t smA = smem_u32(dsm);
    const uint32_t smB = smA + 2 * TILEA;
    if (tid < 128) sbias[tid] = bias[tid];

    const int ap = pbase + tid;
    const bool apv = (ap < totalPx);
    const int bA  = apv ? ap / Npix : 0;
    const int apn = apv ? ap - bA * Npix : 0;
    const int apy = apn / Wout;
    const int apx = apn - apy * Wout;
    const uint32_t adst0 = smA + tid * 272;

    const int pxg = wid >> 1, cog = wid & 1;
    float acc[4][8][4];
    #pragma unroll
    for (int m = 0; m < 4; m++)
        #pragma unroll
        for (int n = 0; n < 8; n++)
            #pragma unroll
            for (int j = 0; j < 4; j++) acc[m][n][j] = 0.f;

    const uint32_t a_rd0 = smA + (pxg * 64 + (lane & 15)) * 272 + ((lane >> 4) << 4);
    const uint32_t b_rdb = (cog * 64 + ((lane >> 4) << 3) + (lane & 7)) * 272
                         + (((lane >> 3) & 1) << 4);
    const int NIT = K * K;

    auto stage = [&](int tap) {
        const int buf = tap & 1;
        const int ky = tap / K, kx = tap - ky * K;
        const char* wb = (const char*)(wpack + (size_t)tap * 128 * 136);
        const uint32_t bd = smB + buf * TILE;
        #pragma unroll
        for (int j = 0; j < 8; ++j)
            CP16(bd + (j * 256 + tid) * 16, wb + (size_t)(j * 256 + tid) * 16, 16);
        if (tid < 128)
            CP16(bd + (2048 + tid) * 16, wb + (size_t)(2048 + tid) * 16, 16);
        const int iy = apy + ky - pad, ix = apx + kx - pad;
        const bool inb = apv && (unsigned)iy < (unsigned)Hin && (unsigned)ix < (unsigned)Win;
        const char* as = inb ? (const char*)(in + ((size_t)(bA * Hin + iy) * Win + ix) * 128)
                             : (const char*)in;
        const uint32_t ad = adst0 + buf * TILEA;
        const int sz = inb ? 16 : 0;
        #pragma unroll
        for (int j = 0; j < 16; ++j)
            CP16(ad + j * 16, as + (size_t)j * 16, sz);
        CP_COMMIT();
    };

    stage(0);
    for (int it = 0; it < NIT; ++it) {
        CP_WAIT0();
        __syncthreads();
        if (it + 1 < NIT) stage(it + 1);
        const uint32_t abase = (it & 1) * TILEA;
        const uint32_t bbase = smB + (it & 1) * TILE;
        #pragma unroll
        for (int ks = 0; ks < 8; ++ks) {
            uint32_t a[4][4], bq[4][4];
            #pragma unroll
            for (int i = 0; i < 4; ++i)
                LDSM_X4(a[i][0], a[i][1], a[i][2], a[i][3],
                        a_rd0 + abase + i * 16 * 272 + ks * 32);
            #pragma unroll
            for (int nb = 0; nb < 4; ++nb)
                LDSM_X4(bq[nb][0], bq[nb][1], bq[nb][2], bq[nb][3],
                        bbase + b_rdb + nb * 16 * 272 + ks * 32);
            #pragma unroll
            for (int nb = 0; nb < 4; ++nb)
                #pragma unroll
                for (int i = 0; i < 4; ++i) {
                    MMA_BF16(acc[i][2 * nb],     a[i][0], a[i][1], a[i][2], a[i][3],
                             bq[nb][0], bq[nb][1]);
                    MMA_BF16(acc[i][2 * nb + 1], a[i][0], a[i][1], a[i][2], a[i][3],
                             bq[nb][2], bq[nb][3]);
                }
        }
        __syncthreads();
    }

    #pragma unroll
    for (int mb = 0; mb < 4; ++mb) {
        const int row0 = pbase + pxg * 64 + mb * 16 + (lane >> 2);
        const int row1 = row0 + 8;
        const bool v0 = (row0 < totalPx), v1 = (row1 < totalPx);
        #pragma unroll
        for (int nt = 0; nt < 8; ++nt) {
            const int co = cog * 64 + nt * 8 + 2 * (lane & 3);
            const float bz0 = sbias[co], bz1 = sbias[co + 1];
            float p00 = fmaxf(acc[mb][nt][0] + bz0, 0.f);
            float p01 = fmaxf(acc[mb][nt][1] + bz1, 0.f);
            float p10 = fmaxf(acc[mb][nt][2] + bz0, 0.f);
            float p11 = fmaxf(acc[mb][nt][3] + bz1, 0.f);
            if (v0) {
                __nv_bfloat162 h = __floats2bfloat162_rn(p00, p01);
                *(uint32_t*)(outp + (size_t)row0 * 128 + co) = *reinterpret_cast<uint32_t*>(&h);
            }
            if (v1) {
                __nv_bfloat162 h = __floats2bfloat162_rn(p10, p11);
                *(uint32_t*)(outp + (size_t)row1 * 128 + co) = *reinterpret_cast<uint32_t*>(&h);
            }
        }
    }
}

// ================= t2 stride-2 deconv, parity decomposition, M=256 ============
__global__ void __launch_bounds__(256, 1)
tc_t2(const uint16_t* __restrict__ in, const uint16_t* __restrict__ wpack,
      const float* __restrict__ bias, __nv_bfloat16* __restrict__ outp)
{
    extern __shared__ char dsm[];
    __shared__ float sbias[128];
    const int tid  = threadIdx.x;
    const int wid  = tid >> 5;
    const int lane = tid & 31;
    const int par  = blockIdx.z;
    const int py   = par >> 1, px = par & 1;
    const int totalPx = BB * 100;
    const int pbase = blockIdx.x * 256;

    const uint32_t smA = smem_u32(dsm);
    const uint32_t smB = smA + 2 * TILEA;
    if (tid < 128) sbias[tid] = bias[tid];

    const int ap = pbase + tid;
    const bool apv = (ap < totalPx);
    const int bA  = apv ? ap / 100 : 0;
    const int apn = apv ? ap - bA * 100 : 0;
    const int apy = apn / 10;
    const int apx = apn - apy * 10;
    const uint32_t adst0 = smA + tid * 272;

    const int pxg = wid >> 1, cog = wid & 1;
    float acc[4][8][4];
    #pragma unroll
    for (int m = 0; m < 4; m++)
        #pragma unroll
        for (int n = 0; n < 8; n++)
            #pragma unroll
            for (int j = 0; j < 4; j++) acc[m][n][j] = 0.f;

    const uint32_t a_rd0 = smA + (pxg * 64 + (lane & 15)) * 272 + ((lane >> 4) << 4);
    const uint32_t b_rdb = (cog * 64 + ((lane >> 4) << 3) + (lane & 7)) * 272
                         + (((lane >> 3) & 1) << 4);

    auto stage = [&](int tap) {
        const int buf = tap & 1;
        const int ti = tap >> 1, tj = tap & 1;
        const char* wb = (const char*)(wpack + (size_t)(par * 4 + tap) * 128 * 136);
        const uint32_t bd = smB + buf * TILE;
        #pragma unroll
        for (int j = 0; j < 8; ++j)
            CP16(bd + (j * 256 + tid) * 16, wb + (size_t)(j * 256 + tid) * 16, 16);
        if (tid < 128)
            CP16(bd + (2048 + tid) * 16, wb + (size_t)(2048 + tid) * 16, 16);
        const int iy = apy - ti, ix = apx - tj;
        const bool inb = apv && (unsigned)iy < 9u && (unsigned)ix < 9u;
        const char* as = inb ? (const char*)(in + ((size_t)(bA * 9 + iy) * 9 + ix) * 128)
                             : (const char*)in;
        const uint32_t ad = adst0 + buf * TILEA;
        const int sz = inb ? 16 : 0;
        #pragma unroll
        for (int j = 0; j < 16; ++j)
            CP16(ad + j * 16, as + (size_t)j * 16, sz);
        CP_COMMIT();
    };

    stage(0);
    for (int it = 0; it < 4; ++it) {
        CP_WAIT0();
        __syncthreads();
        if (it + 1 < 4) stage(it + 1);
        const uint32_t abase = (it & 1) * TILEA;
        const uint32_t bbase = smB + (it & 1) * TILE;
        #pragma unroll
        for (int ks = 0; ks < 8; ++ks) {
            uint32_t a[4][4], bq[4][4];
            #pragma unroll
            for (int i = 0; i < 4; ++i)
                LDSM_X4(a[i][0], a[i][1], a[i][2], a[i][3],
                        a_rd0 + abase + i * 16 * 272 + ks * 32);
            #pragma unroll
            for (int nb = 0; nb < 4; ++nb)
                LDSM_X4(bq[nb][0], bq[nb][1], bq[nb][2], bq[nb][3],
                        bbase + b_rdb + nb * 16 * 272 + ks * 32);
            #pragma unroll
            for (int nb = 0; nb < 4; ++nb)
                #pragma unroll
                for (int i = 0; i < 4; ++i) {
                    MMA_BF16(acc[i][2 * nb],     a[i][0], a[i][1], a[i][2], a[i][3],
                             bq[nb][0], bq[nb][1]);
                    MMA_BF16(acc[i][2 * nb + 1], a[i][0], a[i][1], a[i][2], a[i][3],
                             bq[nb][2], bq[nb][3]);
                }
        }
        __syncthreads();
    }

    #pragma unroll
    for (int mb = 0; mb < 4; ++mb) {
        const int r0g = pbase + pxg * 64 + mb * 16 + (lane >> 2);
        const int r1g = r0g + 8;
        int b0 = r0g / 100, q0 = r0g - b0 * 100, y0 = q0 / 10, x0 = q0 - y0 * 10;
        int b1 = r1g / 100, q1 = r1g - b1 * 100, y1 = q1 / 10, x1 = q1 - y1 * 10;
        size_t o0 = ((size_t)b0 * 400 + (2 * y0 + py) * 20 + 2 * x0 + px) * 128;
        size_t o1 = ((size_t)b1 * 400 + (2 * y1 + py) * 20 + 2 * x1 + px) * 128;
        #pragma unroll
        for (int nt = 0; nt < 8; ++nt) {
            const int co = cog * 64 + nt * 8 + 2 * (lane & 3);
            const float bz0 = sbias[co], bz1 = sbias[co + 1];
            float p00 = fmaxf(acc[mb][nt][0] + bz0, 0.f);
            float p01 = fmaxf(acc[mb][nt][1] + bz1, 0.f);
            float p10 = fmaxf(acc[mb][nt][2] + bz0, 0.f);
            float p11 = fmaxf(acc[mb][nt][3] + bz1, 0.f);
            if (r0g < totalPx) {
                __nv_bfloat162 h = __floats2bfloat162_rn(p00, p01);
                *(uint32_t*)(outp + o0 + co) = *reinterpret_cast<uint32_t*>(&h);
            }
            if (r1g < totalPx) {
                __nv_bfloat162 h = __floats2bfloat162_rn(p10, p11);
                *(uint32_t*)(outp + o1 + co) = *reinterpret_cast<uint32_t*>(&h);
            }
        }
    }
}

// ---------------- conv1: 8 px/block, weights in registers ---------------------
__global__ void __launch_bounds__(128)
conv1_split(const float* __restrict__ x, const float* __restrict__ w1,
            const float* __restrict__ b1, __half* __restrict__ hi,
            __half* __restrict__ lo)
{
    const int b = blockIdx.x, g = blockIdx.y;     // g = 0..71 (8-px groups)
    const int p0 = g * 8;
    const int oy = p0 / 24, ox0 = p0 - oy * 24;   // group lies within one row
    const int co = threadIdx.x;
    __shared__ float xs[5][12];
    for (int i = co; i < 60; i += 128) {
        int r = i / 12, c = i - r * 12;
        xs[r][c] = x[(size_t)b * 784 + (oy + r) * 28 + ox0 + c];
    }
    __syncthreads();
    float w[25];
    #pragma unroll
    for (int t = 0; t < 25; ++t) w[t] = w1[co * 25 + t];
    const float bz = b1[co];
    #pragma unroll
    for (int px = 0; px < 8; ++px) {
        float v = bz;
        #pragma unroll
        for (int t = 0; t < 25; ++t)
            v += w[t] * xs[t / 5][t % 5 + px];
        v = fmaxf(v, 0.f);
        __half h = __float2half_rn(v);
        size_t o = ((size_t)b * 576 + p0 + px) * 128 + co;
        hi[o] = h;
        lo[o] = __float2half_rn(v - __half2float(h));
    }
}

// ---------------- NHWC maxpool 2x2: fp32 -> fp16 hi/lo -----------------------
__global__ void mp_split_nhwc(const float* __restrict__ in, __half* __restrict__ hi,
                              __half* __restrict__ lo, int Hin, int Win)
{
    const int Ho = Hin >> 1, Wo = Win >> 1;
    const size_t total = (size_t)BB * Ho * Wo * 128;
    for (size_t i = (size_t)blockIdx.x * blockDim.x + threadIdx.x; i < total;
         i += (size_t)gridDim.x * blockDim.x) {
        int c = (int)(i & 127);
        size_t r = i >> 7;
        int wo = (int)(r % Wo); r /= Wo;
        int ho = (int)(r % Ho); int b = (int)(r / Ho);
        const float* p = in + (((size_t)b * Hin + 2 * ho) * Win + 2 * wo) * 128 + c;
        float v = fmaxf(fmaxf(p[0], p[128]),
                        fmaxf(p[(size_t)Win * 128], p[(size_t)(Win + 1) * 128]));
        __half h = __float2half_rn(v);
        hi[i] = h;
        lo[i] = __float2half_rn(v - __half2float(h));
    }
}

// ---------------- NHWC maxpool 2x2: fp32 -> fp32 -----------------------------
__global__ void mp_nhwc(const float* __restrict__ in, float* __restrict__ out,
                        int Hin, int Win)
{
    const int Ho = Hin >> 1, Wo = Win >> 1;
    const size_t total = (size_t)BB * Ho * Wo * 128;
    for (size_t i = (size_t)blockIdx.x * blockDim.x + threadIdx.x; i < total;
         i += (size_t)gridDim.x * blockDim.x) {
        int c = (int)(i & 127);
        size_t r = i >> 7;
        int wo = (int)(r % Wo); r /= Wo;
        int ho = (int)(r % Ho); int b = (int)(r / Ho);
        const float* p = in + (((size_t)b * Hin + 2 * ho) * Win + 2 * wo) * 128 + c;
        out[i] = fmaxf(fmaxf(p[0], p[128]),
                       fmaxf(p[(size_t)Win * 128], p[(size_t)(Win + 1) * 128]));
    }
}

// ---------------- VQ: argmax(d2), gather val (NHWC bf16), dict MSE ------------
__global__ void __launch_bounds__(256)
vq_kernel(const float* __restrict__ z, const float* __restrict__ dict,
          __nv_bfloat16* __restrict__ valh, float* __restrict__ idx_out)
{
    extern __shared__ float dsmf[];
    __shared__ float zt[36 * 128];
    __shared__ float wn[128];
    __shared__ int   sidx[36];

    const int b = blockIdx.x, tid = threadIdx.x;

    for (int i = tid; i < 128 * 128; i += NT) {
        int k = i >> 7; int c = i & 127;
        dsmf[k * 129 + c] = dict[i];
    }
    for (int i = tid; i < 36 * 128; i += NT)
        zt[i] = z[(size_t)b * 4608 + i];
    __syncthreads();
    if (tid < 128) {
        float s = 0.f;
        const float* dp = dsmf + tid * 129;
        for (int c = 0; c < 128; c++) s += dp[c] * dp[c];
        wn[tid] = s;
    }
    __syncthreads();

    const int lane = tid & 31, wid = tid >> 5;
    for (int pos = wid; pos < 36; pos += 8) {
        float d0 = 0.f, d1 = 0.f, d2s = 0.f, d3 = 0.f, zn = 0.f;
        const float* zp = zt + pos * 128;
        const float* p0 = dsmf + (lane      ) * 129;
        const float* p1 = dsmf + (lane + 32 ) * 129;
        const float* p2 = dsmf + (lane + 64 ) * 129;
        const float* p3 = dsmf + (lane + 96 ) * 129;
        for (int c = 0; c < 128; c++) {
            float zv = zp[c];
            zn += zv * zv;
            d0 += p0[c] * zv; d1 += p1[c] * zv;
            d2s += p2[c] * zv; d3 += p3[c] * zv;
        }
        float bv = zn + wn[lane] - 2.f * d0; int bk = lane;
        float v1 = zn + wn[lane + 32] - 2.f * d1; if (v1 > bv) { bv = v1; bk = lane + 32; }
        float v2 = zn + wn[lane + 64] - 2.f * d2s; if (v2 > bv) { bv = v2; bk = lane + 64; }
        float v3 = zn + wn[lane + 96] - 2.f * d3; if (v3 > bv) { bv = v3; bk = lane + 96; }
        #pragma unroll
        for (int o = 16; o; o >>= 1) {
            float ov = __shfl_xor_sync(0xffffffffu, bv, o);
            int   ok = __shfl_xor_sync(0xffffffffu, bk, o);
            if (ov > bv || (ov == bv && ok < bk)) { bv = ov; bk = ok; }
        }
        if (lane == 0) {
            sidx[pos] = bk;
            if (idx_out) idx_out[b * 36 + pos] = (float)bk;
        }
    }
    __syncthreads();

    float lsum = 0.f;
    for (int i = tid; i < 4608; i += NT) {
        int pos = i >> 7; int c = i & 127;
        float v  = dsmf[sidx[pos] * 129 + c];
        float zv = zt[i];
        valh[(size_t)b * 4608 + i] = __float2bfloat16(v);
        float d = v - zv;
        lsum += d * d;
    }
    lsum = warp_sum(lsum);
    if ((tid & 31) == 0) atomicAdd(&g_dict_sum, (double)lsum);
}

// ---------------- mu (1x1 conv) fused with reconstruction loss (NHWC bf16) ---
__global__ void __launch_bounds__(256)
mu_loss(const __nv_bfloat16* __restrict__ f4, const float* __restrict__ x,
        const float* __restrict__ mw, const float* __restrict__ mb)
{
    __shared__ float mws[128];
    const int b = blockIdx.x, tid = threadIdx.x;
    if (tid < 128) mws[tid] = mw[tid];
    __syncthreads();
    float lsum = 0.f;
    for (int px = tid; px < 784; px += NT) {
        const uint4* fp = (const uint4*)(f4 + ((size_t)b * 784 + px) * 128);
        float s = mb[0];
        #pragma unroll
        for (int j = 0; j < 16; j++) {
            uint4 v = fp[j];
            const __nv_bfloat16* h = (const __nv_bfloat16*)&v;
            #pragma unroll
            for (int t = 0; t < 8; t++)
                s += __bfloat162float(h[t]) * mws[j * 8 + t];
        }
        float d = s - x[(size_t)b * 784 + px];
        lsum += d * d;
    }
    lsum = warp_sum(lsum);
    if ((tid & 31) == 0) atomicAdd(&g_rec_sum, (double)lsum);
}

__global__ void finalize_kernel(float* loss_out)
{
    if (loss_out) {
        double dict_mse = g_dict_sum / 1179648.0;
        loss_out[0] = (float)(g_rec_sum / 200704.0);
        loss_out[1] = (float)(dict_mse * 5.0);
        loss_out[2] = (float)(dict_mse * 1.25);
        loss_out[3] = 0.f;
    }
}

// ---------------- host side ----------------------------------------------------
extern "C" void kernel_launch(void* const* d_in, const int* in_sizes, int n_in,
                              void* d_out, int out_size)
{
    const float* x    = (const float*)d_in[0];
    const float* w1   = (const float*)d_in[1];
    const float* b1   = (const float*)d_in[2];
    const float* w2   = (const float*)d_in[3];
    const float* b2   = (const float*)d_in[4];
    const float* w3   = (const float*)d_in[5];
    const float* b3   = (const float*)d_in[6];
    const float* t1w  = (const float*)d_in[7];
    const float* t1b  = (const float*)d_in[8];
    const float* t2w  = (const float*)d_in[9];
    const float* t2b  = (const float*)d_in[10];
    const float* t3w  = (const float*)d_in[11];
    const float* t3b  = (const float*)d_in[12];
    const float* t4w  = (const float*)d_in[13];
    const float* t4b  = (const float*)d_in[14];
    const float* mw   = (const float*)d_in[15];
    const float* mb   = (const float*)d_in[16];
    const float* dictw= (const float*)d_in[17];

    float* outp = (float*)d_out;
    float* loss_ptr = outp;
    float* idx_ptr  = outp + 4;
    if (out_size < 9220) { loss_ptr = nullptr; idx_ptr = outp; }

    __half *c1hi, *c1lo, *p1hi, *p1lo, *w2hi, *w2lo, *w3hi, *w3lo;
    float *c2f, *c3f, *zn;
    __nv_bfloat16 *valh, *f1h, *f2h, *f3h, *f4h, *wp1, *wpt2, *wp3, *wp4;
    cudaGetSymbolAddress((void**)&c1hi, g_c1hi);
    cudaGetSymbolAddress((void**)&c1lo, g_c1lo);
    cudaGetSymbolAddress((void**)&c2f,  g_c2f);
    cudaGetSymbolAddress((void**)&p1hi, g_p1hi);
    cudaGetSymbolAddress((void**)&p1lo, g_p1lo);
    cudaGetSymbolAddress((void**)&c3f,  g_c3f);
    cudaGetSymbolAddress((void**)&zn,   g_zn);
    cudaGetSymbolAddress((void**)&valh, g_valh);
    cudaGetSymbolAddress((void**)&f1h,  g_f1h);
    cudaGetSymbolAddress((void**)&f2h,  g_f2h);
    cudaGetSymbolAddress((void**)&f3h,  g_f3h);
    cudaGetSymbolAddress((void**)&f4h,  g_f4h);
    cudaGetSymbolAddress((void**)&wp1,  g_wp1);
    cudaGetSymbolAddress((void**)&wpt2, g_wpt2);
    cudaGetSymbolAddress((void**)&wp3,  g_wp3);
    cudaGetSymbolAddress((void**)&wp4,  g_wp4);
    cudaGetSymbolAddress((void**)&w2hi, g_w2hi);
    cudaGetSymbolAddress((void**)&w2lo, g_w2lo);
    cudaGetSymbolAddress((void**)&w3hi, g_w3hi);
    cudaGetSymbolAddress((void**)&w3lo, g_w3lo);

    static bool attr_set = false;
    if (!attr_set) {
        cudaFuncSetAttribute(vq_kernel, cudaFuncAttributeMaxDynamicSharedMemorySize,
                             128 * 129 * (int)sizeof(float));
        cudaFuncSetAttribute(tc_eng1, cudaFuncAttributeMaxDynamicSharedMemorySize,
                             2 * TILEA + 2 * TILE);
        cudaFuncSetAttribute(tc_t2, cudaFuncAttributeMaxDynamicSharedMemorySize,
                             2 * TILEA + 2 * TILE);
        cudaFuncSetAttribute(tc_enc3, cudaFuncAttributeMaxDynamicSharedMemorySize,
                             2 * TILEA + 2 * TILE);
        attr_set = true;
    }

    init_kernel<<<1, 1>>>();                                    // 0
    prepack_all<<<132, 256>>>(w2, w3, t1w, t2w, t3w, t4w,       // 1
                              w2hi, w2lo, w3hi, w3lo, wp1, wpt2, wp3, wp4);
    conv1_split<<<dim3(BB, 72), 128>>>(x, w1, b1, c1hi, c1lo);  // 2
    tc_enc3<<<576, 256, 2 * TILEA + 2 * TILE>>>(                // 3 <- profiled
        (const uint16_t*)c1hi, (const uint16_t*)c1lo,
        (const uint16_t*)w2hi, (const uint16_t*)w2lo,
        b2, c2f, 24, 24, 24, 24, 2, 1);
    mp_split_nhwc<<<4096, 256>>>(c2f, p1hi, p1lo, 24, 24);
    tc_enc3<<<144, 256, 2 * TILEA + 2 * TILE>>>(
        (const uint16_t*)p1hi, (const uint16_t*)p1lo,
        (const uint16_t*)w3hi, (const uint16_t*)w3lo,
        b3, c3f, 12, 12, 12, 12, 2, 0);
    mp_nhwc<<<2048, 256>>>(c3f, zn, 12, 12);

    vq_kernel<<<BB, NT, 128 * 129 * sizeof(float)>>>(zn, dictw, valh, idx_ptr);

    tc_eng1<<<81, 256, 2 * TILEA + 2 * TILE>>>(
        (const uint16_t*)valh, (const uint16_t*)wp1, t1b, f1h, 6, 6, 9, 9, 3, 4);
    tc_t2<<<dim3(100, 1, 4), 256, 2 * TILEA + 2 * TILE>>>(
        (const uint16_t*)f1h, (const uint16_t*)wpt2, t2b, f2h);
    tc_eng1<<<576, 256, 2 * TILEA + 2 * TILE>>>(
        (const uint16_t*)f2h, (const uint16_t*)wp3, t3b, f3h, 20, 20, 24, 24, 4, 5);
    tc_eng1<<<784, 256, 2 * TILEA + 2 * TILE>>>(
        (const uint16_t*)f3h, (const uint16_t*)wp4, t4b, f4h, 24, 24, 28, 28, 4, 5);

    mu_loss<<<BB, NT>>>(f4h, x, mw, mb);
    finalize_kernel<<<1, 1>>>(loss_ptr);
}

// round 11
// speedup vs baseline: 6.7759x; 1.0043x over previous
#include <cuda_runtime.h>
#include <cuda_bf16.h>
#include <cuda_fp16.h>
#include <cstdint>

#define BB 256
#define NT 256
#define TILE 34816          // 128 rows x 272B
#define TILEA 69632         // 256 rows x 272B

// ---------------- scratch (device globals; no allocation APIs) ---------------
__device__ __half g_c1hi[(size_t)BB*576*128];
__device__ __half g_c1lo[(size_t)BB*576*128];
__device__ float  g_c2f [(size_t)BB*576*128];
__device__ __half g_p1hi[(size_t)BB*144*128];
__device__ __half g_p1lo[(size_t)BB*144*128];
__device__ float  g_c3f [(size_t)BB*144*128];
__device__ float  g_zn  [(size_t)BB*36*128];
__device__ __nv_bfloat16 g_valh[(size_t)BB*36*128];
__device__ __nv_bfloat16 g_f1h[(size_t)BB*81*128];
__device__ __nv_bfloat16 g_f2h[(size_t)BB*400*128];
__device__ __nv_bfloat16 g_f3h[(size_t)BB*576*128];
__device__ __nv_bfloat16 g_f4h[(size_t)BB*784*128];
__device__ __nv_bfloat16 g_wp1[16*128*136];
__device__ __nv_bfloat16 g_wpt2[16*128*136];
__device__ __nv_bfloat16 g_wp3[25*128*136];
__device__ __nv_bfloat16 g_wp4[25*128*136];
__device__ __half g_w2hi[25*128*136];
__device__ __half g_w2lo[25*128*136];
__device__ __half g_w3hi[25*128*136];
__device__ __half g_w3lo[25*128*136];
__device__ double g_rec_sum;
__device__ double g_dict_sum;

__global__ void init_kernel() { g_rec_sum = 0.0; g_dict_sum = 0.0; }

__inline__ __device__ float warp_sum(float v) {
    #pragma unroll
    for (int o = 16; o; o >>= 1) v += __shfl_xor_sync(0xffffffffu, v, o);
    return v;
}

// ---------------- mma / cp.async helpers --------------------------------------
__device__ __forceinline__ uint32_t smem_u32(const void* p) {
    uint32_t a;
    asm("{ .reg .u64 t; cvta.to.shared.u64 t, %1; cvt.u32.u64 %0, t; }"
        : "=r"(a) : "l"(p));
    return a;
}

#define LDSM_X4(r0, r1, r2, r3, addr)                                          \
    asm volatile("ldmatrix.sync.aligned.m8n8.x4.shared.b16 {%0,%1,%2,%3}, [%4];" \
                 : "=r"(r0), "=r"(r1), "=r"(r2), "=r"(r3) : "r"(addr))

#define MMA_BF16(c, a0, a1, a2, a3, b0, b1)                                    \
    asm volatile("mma.sync.aligned.m16n8k16.row.col.f32.bf16.bf16.f32 "        \
                 "{%0,%1,%2,%3}, {%4,%5,%6,%7}, {%8,%9}, {%0,%1,%2,%3};"       \
                 : "+f"((c)[0]), "+f"((c)[1]), "+f"((c)[2]), "+f"((c)[3])      \
                 : "r"(a0), "r"(a1), "r"(a2), "r"(a3), "r"(b0), "r"(b1))

#define MMA_F16(c, a0, a1, a2, a3, b0, b1)                                     \
    asm volatile("mma.sync.aligned.m16n8k16.row.col.f32.f16.f16.f32 "          \
                 "{%0,%1,%2,%3}, {%4,%5,%6,%7}, {%8,%9}, {%0,%1,%2,%3};"       \
                 : "+f"((c)[0]), "+f"((c)[1]), "+f"((c)[2]), "+f"((c)[3])      \
                 : "r"(a0), "r"(a1), "r"(a2), "r"(a3), "r"(b0), "r"(b1))

#define CP16(d, s, n)                                                          \
    asm volatile("cp.async.cg.shared.global [%0], [%1], 16, %2;"               \
                 :: "r"(d), "l"(s), "r"(n))
#define CP_COMMIT() asm volatile("cp.async.commit_group;" ::: "memory")
#define CP_WAIT0()  asm volatile("cp.async.wait_group 0;" ::: "memory")
#define CP_WAIT1()  asm volatile("cp.async.wait_group 1;" ::: "memory")

// ---------------- fused weight prepack (all layers, one launch) ---------------
__device__ __forceinline__ void pp_fwd_split(const float* W, __half* dh, __half* dl,
                                             int tap)
{
    int ky = tap / 5, kx = tap - ky * 5;
    size_t tb = (size_t)tap * 128 * 136;
    for (int i = threadIdx.x; i < 16384; i += blockDim.x) {
        int co = i >> 7, ci = i & 127;
        float v = W[(((size_t)co * 128 + ci) * 5 + ky) * 5 + kx];
        __half h = __float2half_rn(v);
        dh[tb + co * 136 + ci] = h;
        dl[tb + co * 136 + ci] = __float2half_rn(v - __half2float(h));
    }
}

__device__ __forceinline__ void pp_deconv(const float* W, __nv_bfloat16* dst,
                                          int tap, int K)
{
    int ky = tap / K, kx = tap - ky * K;
    __nv_bfloat16* base = dst + (size_t)tap * 128 * 136;
    for (int i = threadIdx.x; i < 16384; i += blockDim.x) {
        int co = i >> 7, ci = i & 127;
        float v = W[(((size_t)ci * 128 + co) * K + (K - 1 - ky)) * K + (K - 1 - kx)];
        base[co * 136 + ci] = __float2bfloat16(v);
    }
}

__device__ __forceinline__ void pp_t2(const float* W, __nv_bfloat16* dst, int idx)
{
    int par = idx >> 2, tap = idx & 3;
    int py = par >> 1, px = par & 1;
    int ti = tap >> 1, tj = tap & 1;
    int ky = py + 2 * ti, kx = px + 2 * tj;
    __nv_bfloat16* base = dst + (size_t)idx * 128 * 136;
    for (int i = threadIdx.x; i < 16384; i += blockDim.x) {
        int co = i >> 7, ci = i & 127;
        float v = W[(((size_t)ci * 128 + co) * 4 + ky) * 4 + kx];
        base[co * 136 + ci] = __float2bfloat16(v);
    }
}

__global__ void prepack_all(const float* w2, const float* w3,
                            const float* t1w, const float* t2w,
                            const float* t3w, const float* t4w,
                            __half* w2hi, __half* w2lo,
                            __half* w3hi, __half* w3lo,
                            __nv_bfloat16* wp1, __nv_bfloat16* wpt2,
                            __nv_bfloat16* wp3, __nv_bfloat16* wp4)
{
    int bid = blockIdx.x;
    if      (bid < 25)  pp_fwd_split(w2, w2hi, w2lo, bid);
    else if (bid < 50)  pp_fwd_split(w3, w3hi, w3lo, bid - 25);
    else if (bid < 66)  pp_deconv(t1w, wp1, bid - 50, 4);
    else if (bid < 82)  pp_t2(t2w, wpt2, bid - 66);
    else if (bid < 107) pp_deconv(t3w, wp3, bid - 82, 5);
    else                pp_deconv(t4w, wp4, bid - 107, 5);
}

// ====== fused 3-pass fp16-split encoder conv, M=256, A-reuse fused passes =====
__global__ void __launch_bounds__(256, 1)
tc_enc3(const uint16_t* __restrict__ inHi, const uint16_t* __restrict__ inLo,
        const uint16_t* __restrict__ wHi,  const uint16_t* __restrict__ wLo,
        const float* __restrict__ bias, float* __restrict__ outp,
        int Hin, int Win, int Hout, int Wout, int pad, int relu)
{
    extern __shared__ char dsm[];
    __shared__ float sbias[128];
    const int tid  = threadIdx.x;
    const int wid  = tid >> 5;
    const int lane = tid & 31;
    const int Npix = Hout * Wout;
    const int totalPx = BB * Npix;
    const int pbase = blockIdx.x * 256;

    const uint32_t smA   = smem_u32(dsm);
    const uint32_t smBhi = smA + 2 * TILEA;
    const uint32_t smBlo = smBhi + TILE;
    if (tid < 128) sbias[tid] = bias[tid];

    const int ap = pbase + tid;
    const bool apv = (ap < totalPx);
    const int bA  = apv ? ap / Npix : 0;
    const int apn = apv ? ap - bA * Npix : 0;
    const int apy = apn / Wout;
    const int apx = apn - apy * Wout;
    const uint32_t adst0 = smA + tid * 272;

    const int pxg = wid >> 1, cog = wid & 1;
    float acc[4][8][4];
    #pragma unroll
    for (int m = 0; m < 4; m++)
        #pragma unroll
        for (int n = 0; n < 8; n++)
            #pragma unroll
            for (int j = 0; j < 4; j++) acc[m][n][j] = 0.f;

    const uint32_t a_rd0 = smA + (pxg * 64 + (lane & 15)) * 272 + ((lane >> 4) << 4);
    const uint32_t b_rdb = (cog * 64 + ((lane >> 4) << 3) + (lane & 7)) * 272
                         + (((lane >> 3) & 1) << 4);

    auto stage_A = [&](int it) {
        const int tap = (it < 25) ? it : it - 25;
        const uint16_t* abuf = (it < 25) ? inHi : inLo;
        const int ky = tap / 5, kx = tap - ky * 5;
        const int iy = apy + ky - pad, ix = apx + kx - pad;
        const bool inb = apv && (unsigned)iy < (unsigned)Hin && (unsigned)ix < (unsigned)Win;
        const char* as = inb ? (const char*)(abuf + ((size_t)(bA * Hin + iy) * Win + ix) * 128)
                             : (const char*)abuf;
        const uint32_t ad = adst0 + (it & 1) * TILEA;
        const int sz = inb ? 16 : 0;
        #pragma unroll
        for (int j = 0; j < 16; ++j)
            CP16(ad + j * 16, as + (size_t)j * 16, sz);
    };

    auto stage_Btile = [&](const uint16_t* wbuf, int tap, uint32_t bd) {
        const char* wb = (const char*)(wbuf + (size_t)tap * 128 * 136);
        #pragma unroll
        for (int j = 0; j < 8; ++j)
            CP16(bd + (j * 256 + tid) * 16, wb + (size_t)(j * 256 + tid) * 16, 16);
        if (tid < 128)
            CP16(bd + (2048 + tid) * 16, wb + (size_t)(2048 + tid) * 16, 16);
    };

    stage_A(0);
    CP_COMMIT();

    for (int it = 0; it < 50; ++it) {
        const int tap = (it < 25) ? it : it - 25;
        const int ph  = (it < 25) ? 0 : 1;
        stage_Btile(wHi, tap, smBhi);
        if (ph == 0) stage_Btile(wLo, tap, smBlo);
        CP_COMMIT();
        if (it < 49) {
            stage_A(it + 1);
            CP_COMMIT();
            CP_WAIT1();
        } else {
            CP_WAIT0();
        }
        __syncthreads();
        const uint32_t abase = (it & 1) * TILEA;

        // fused pass: load A once per ks, run Bhi MMAs then (phase 0) Blo MMAs
        #pragma unroll
        for (int ks = 0; ks < 8; ++ks) {
            uint32_t a[4][4], bq[4][4];
            #pragma unroll
            for (int i = 0; i < 4; ++i)
                LDSM_X4(a[i][0], a[i][1], a[i][2], a[i][3],
                        a_rd0 + abase + i * 16 * 272 + ks * 32);
            #pragma unroll
            for (int nb = 0; nb < 4; ++nb)
                LDSM_X4(bq[nb][0], bq[nb][1], bq[nb][2], bq[nb][3],
                        smBhi + b_rdb + nb * 16 * 272 + ks * 32);
            #pragma unroll
            for (int nb = 0; nb < 4; ++nb)
                #pragma unroll
                for (int i = 0; i < 4; ++i) {
                    MMA_F16(acc[i][2 * nb],     a[i][0], a[i][1], a[i][2], a[i][3],
                            bq[nb][0], bq[nb][1]);
                    MMA_F16(acc[i][2 * nb + 1], a[i][0], a[i][1], a[i][2], a[i][3],
                            bq[nb][2], bq[nb][3]);
                }
            if (ph == 0) {
                #pragma unroll
                for (int nb = 0; nb < 4; ++nb)
                    LDSM_X4(bq[nb][0], bq[nb][1], bq[nb][2], bq[nb][3],
                            smBlo + b_rdb + nb * 16 * 272 + ks * 32);
                #pragma unroll
                for (int nb = 0; nb < 4; ++nb)
                    #pragma unroll
                    for (int i = 0; i < 4; ++i) {
                        MMA_F16(acc[i][2 * nb],     a[i][0], a[i][1], a[i][2], a[i][3],
                                bq[nb][0], bq[nb][1]);
                        MMA_F16(acc[i][2 * nb + 1], a[i][0], a[i][1], a[i][2], a[i][3],
                                bq[nb][2], bq[nb][3]);
                    }
            }
        }
        __syncthreads();
    }

    #pragma unroll
    for (int mb = 0; mb < 4; ++mb) {
        const int row0 = pbase + pxg * 64 + mb * 16 + (lane >> 2);
        const int row1 = row0 + 8;
        const bool v0 = (row0 < totalPx), v1 = (row1 < totalPx);
        #pragma unroll
        for (int nt = 0; nt < 8; ++nt) {
            const int co = cog * 64 + nt * 8 + 2 * (lane & 3);
            const float bz0 = sbias[co], bz1 = sbias[co + 1];
            float p00 = acc[mb][nt][0] + bz0, p01 = acc[mb][nt][1] + bz1;
            float p10 = acc[mb][nt][2] + bz0, p11 = acc[mb][nt][3] + bz1;
            if (relu) {
                p00 = fmaxf(p00, 0.f); p01 = fmaxf(p01, 0.f);
                p10 = fmaxf(p10, 0.f); p11 = fmaxf(p11, 0.f);
            }
            if (v0) *(float2*)(outp + (size_t)row0 * 128 + co) = make_float2(p00, p01);
            if (v1) *(float2*)(outp + (size_t)row1 * 128 + co) = make_float2(p10, p11);
        }
    }
}

// ================= 1-pass bf16 engine, M=256, flattened tiling ================
__global__ void __launch_bounds__(256, 1)
tc_eng1(const uint16_t* __restrict__ in, const uint16_t* __restrict__ wpack,
        const float* __restrict__ bias, __nv_bfloat16* __restrict__ outp,
        int Hin, int Win, int Hout, int Wout, int pad, int K)
{
    extern __shared__ char dsm[];
    __shared__ float sbias[128];
    const int tid  = threadIdx.x;
    const int wid  = tid >> 5;
    const int lane = tid & 31;
    const int Npix = Hout * Wout;
    const int totalPx = BB * Npix;
    const int pbase = blockIdx.x * 256;

    const uint32_t smA = smem_u32(dsm);
    const uint32_t smB = smA + 2 * TILEA;
    if (tid < 128) sbias[tid] = bias[tid];

    const int ap = pbase + tid;
    const bool apv = (ap < totalPx);
    const int bA  = apv ? ap / Npix : 0;
    const int apn = apv ? ap - bA * Npix : 0;
    const int apy = apn / Wout;
    const int apx = apn - apy * Wout;
    const uint32_t adst0 = smA + tid * 272;

    const int pxg = wid >> 1, cog = wid & 1;
    float acc[4][8][4];
    #pragma unroll
    for (int m = 0; m < 4; m++)
        #pragma unroll
        for (int n = 0; n < 8; n++)
            #pragma unroll
            for (int j = 0; j < 4; j++) acc[m][n][j] = 0.f;

    const uint32_t a_rd0 = smA + (pxg * 64 + (lane & 15)) * 272 + ((lane >> 4) << 4);
    const uint32_t b_rdb = (cog * 64 + ((lane >> 4) << 3) + (lane & 7)) * 272
                         + (((lane >> 3) & 1) << 4);
    const int NIT = K * K;

    auto stage = [&](int tap) {
        const int buf = tap & 1;
        const int ky = tap / K, kx = tap - ky * K;
        const char* wb = (const char*)(wpack + (size_t)tap * 128 * 136);
        const uint32_t bd = smB + buf * TILE;
        #pragma unroll
        for (int j = 0; j < 8; ++j)
            CP16(bd + (j * 256 + tid) * 16, wb + (size_t)(j * 256 + tid) * 16, 16);
        if (tid < 128)
            CP16(bd + (2048 + tid) * 16, wb + (size_t)(2048 + tid) * 16, 16);
        const int iy = apy + ky - pad, ix = apx + kx - pad;
        const bool inb = apv && (unsigned)iy < (unsigned)Hin && (unsigned)ix < (unsigned)Win;
        const char* as = inb ? (const char*)(in + ((size_t)(bA * Hin + iy) * Win + ix) * 128)
                             : (const char*)in;
        const uint32_t ad = adst0 + buf * TILEA;
        const int sz = inb ? 16 : 0;
        #pragma unroll
        for (int j = 0; j < 16; ++j)
            CP16(ad + j * 16, as + (size_t)j * 16, sz);
        CP_COMMIT();
    };

    stage(0);
    for (int it = 0; it < NIT; ++it) {
        CP_WAIT0();
        __syncthreads();
        if (it + 1 < NIT) stage(it + 1);
        const uint32_t abase = (it & 1) * TILEA;
        const uint32_t bbase = smB + (it & 1) * TILE;
        #pragma unroll
        for (int ks = 0; ks < 8; ++ks) {
            uint32_t a[4][4], bq[4][4];
            #pragma unroll
            for (int i = 0; i < 4; ++i)
                LDSM_X4(a[i][0], a[i][1], a[i][2], a[i][3],
                        a_rd0 + abase + i * 16 * 272 + ks * 32);
            #pragma unroll
            for (int nb = 0; nb < 4; ++nb)
                LDSM_X4(bq[nb][0], bq[nb][1], bq[nb][2], bq[nb][3],
                        bbase + b_rdb + nb * 16 * 272 + ks * 32);
            #pragma unroll
            for (int nb = 0; nb < 4; ++nb)
                #pragma unroll
                for (int i = 0; i < 4; ++i) {
                    MMA_BF16(acc[i][2 * nb],     a[i][0], a[i][1], a[i][2], a[i][3],
                             bq[nb][0], bq[nb][1]);
                    MMA_BF16(acc[i][2 * nb + 1], a[i][0], a[i][1], a[i][2], a[i][3],
                             bq[nb][2], bq[nb][3]);
                }
        }
        __syncthreads();
    }

    #pragma unroll
    for (int mb = 0; mb < 4; ++mb) {
        const int row0 = pbase + pxg * 64 + mb * 16 + (lane >> 2);
        const int row1 = row0 + 8;
        const bool v0 = (row0 < totalPx), v1 = (row1 < totalPx);
        #pragma unroll
        for (int nt = 0; nt < 8; ++nt) {
            const int co = cog * 64 + nt * 8 + 2 * (lane & 3);
            const float bz0 = sbias[co], bz1 = sbias[co + 1];
            float p00 = fmaxf(acc[mb][nt][0] + bz0, 0.f);
            float p01 = fmaxf(acc[mb][nt][1] + bz1, 0.f);
            float p10 = fmaxf(acc[mb][nt][2] + bz0, 0.f);
            float p11 = fmaxf(acc[mb][nt][3] + bz1, 0.f);
            if (v0) {
                __nv_bfloat162 h = __floats2bfloat162_rn(p00, p01);
                *(uint32_t*)(outp + (size_t)row0 * 128 + co) = *reinterpret_cast<uint32_t*>(&h);
            }
            if (v1) {
                __nv_bfloat162 h = __floats2bfloat162_rn(p10, p11);
                *(uint32_t*)(outp + (size_t)row1 * 128 + co) = *reinterpret_cast<uint32_t*>(&h);
            }
        }
    }
}

// ================= t2 stride-2 deconv, parity decomposition, M=256 ============
__global__ void __launch_bounds__(256, 1)
tc_t2(const uint16_t* __restrict__ in, const uint16_t* __restrict__ wpack,
      const float* __restrict__ bias, __nv_bfloat16* __restrict__ outp)
{
    extern __shared__ char dsm[];
    __shared__ float sbias[128];
    const int tid  = threadIdx.x;
    const int wid  = tid >> 5;
    const int lane = tid & 31;
    const int par  = blockIdx.z;
    const int py   = par >> 1, px = par & 1;
    const int totalPx = BB * 100;
    const int pbase = blockIdx.x * 256;

    const uint32_t smA = smem_u32(dsm);
    const uint32_t smB = smA + 2 * TILEA;
    if (tid < 128) sbias[tid] = bias[tid];

    const int ap = pbase + tid;
    const bool apv = (ap < totalPx);
    const int bA  = apv ? ap / 100 : 0;
    const int apn = apv ? ap - bA * 100 : 0;
    const int apy = apn / 10;
    const int apx = apn - apy * 10;
    const uint32_t adst0 = smA + tid * 272;

    const int pxg = wid >> 1, cog = wid & 1;
    float acc[4][8][4];
    #pragma unroll
    for (int m = 0; m < 4; m++)
        #pragma unroll
        for (int n = 0; n < 8; n++)
            #pragma unroll
            for (int j = 0; j < 4; j++) acc[m][n][j] = 0.f;

    const uint32_t a_rd0 = smA + (pxg * 64 + (lane & 15)) * 272 + ((lane >> 4) << 4);
    const uint32_t b_rdb = (cog * 64 + ((lane >> 4) << 3) + (lane & 7)) * 272
                         + (((lane >> 3) & 1) << 4);

    auto stage = [&](int tap) {
        const int buf = tap & 1;
        const int ti = tap >> 1, tj = tap & 1;
        const char* wb = (const char*)(wpack + (size_t)(par * 4 + tap) * 128 * 136);
        const uint32_t bd = smB + buf * TILE;
        #pragma unroll
        for (int j = 0; j < 8; ++j)
            CP16(bd + (j * 256 + tid) * 16, wb + (size_t)(j * 256 + tid) * 16, 16);
        if (tid < 128)
            CP16(bd + (2048 + tid) * 16, wb + (size_t)(2048 + tid) * 16, 16);
        const int iy = apy - ti, ix = apx - tj;
        const bool inb = apv && (unsigned)iy < 9u && (unsigned)ix < 9u;
        const char* as = inb ? (const char*)(in + ((size_t)(bA * 9 + iy) * 9 + ix) * 128)
                             : (const char*)in;
        const uint32_t ad = adst0 + buf * TILEA;
        const int sz = inb ? 16 : 0;
        #pragma unroll
        for (int j = 0; j < 16; ++j)
            CP16(ad + j * 16, as + (size_t)j * 16, sz);
        CP_COMMIT();
    };

    stage(0);
    for (int it = 0; it < 4; ++it) {
        CP_WAIT0();
        __syncthreads();
        if (it + 1 < 4) stage(it + 1);
        const uint32_t abase = (it & 1) * TILEA;
        const uint32_t bbase = smB + (it & 1) * TILE;
        #pragma unroll
        for (int ks = 0; ks < 8; ++ks) {
            uint32_t a[4][4], bq[4][4];
            #pragma unroll
            for (int i = 0; i < 4; ++i)
                LDSM_X4(a[i][0], a[i][1], a[i][2], a[i][3],
                        a_rd0 + abase + i * 16 * 272 + ks * 32);
            #pragma unroll
            for (int nb = 0; nb < 4; ++nb)
                LDSM_X4(bq[nb][0], bq[nb][1], bq[nb][2], bq[nb][3],
                        bbase + b_rdb + nb * 16 * 272 + ks * 32);
            #pragma unroll
            for (int nb = 0; nb < 4; ++nb)
                #pragma unroll
                for (int i = 0; i < 4; ++i) {
                    MMA_BF16(acc[i][2 * nb],     a[i][0], a[i][1], a[i][2], a[i][3],
                             bq[nb][0], bq[nb][1]);
                    MMA_BF16(acc[i][2 * nb + 1], a[i][0], a[i][1], a[i][2], a[i][3],
                             bq[nb][2], bq[nb][3]);
                }
        }
        __syncthreads();
    }

    #pragma unroll
    for (int mb = 0; mb < 4; ++mb) {
        const int r0g = pbase + pxg * 64 + mb * 16 + (lane >> 2);
        const int r1g = r0g + 8;
        int b0 = r0g / 100, q0 = r0g - b0 * 100, y0 = q0 / 10, x0 = q0 - y0 * 10;
        int b1 = r1g / 100, q1 = r1g - b1 * 100, y1 = q1 / 10, x1 = q1 - y1 * 10;
        size_t o0 = ((size_t)b0 * 400 + (2 * y0 + py) * 20 + 2 * x0 + px) * 128;
        size_t o1 = ((size_t)b1 * 400 + (2 * y1 + py) * 20 + 2 * x1 + px) * 128;
        #pragma unroll
        for (int nt = 0; nt < 8; ++nt) {
            const int co = cog * 64 + nt * 8 + 2 * (lane & 3);
            const float bz0 = sbias[co], bz1 = sbias[co + 1];
            float p00 = fmaxf(acc[mb][nt][0] + bz0, 0.f);
            float p01 = fmaxf(acc[mb][nt][1] + bz1, 0.f);
            float p10 = fmaxf(acc[mb][nt][2] + bz0, 0.f);
            float p11 = fmaxf(acc[mb][nt][3] + bz1, 0.f);
            if (r0g < totalPx) {
                __nv_bfloat162 h = __floats2bfloat162_rn(p00, p01);
                *(uint32_t*)(outp + o0 + co) = *reinterpret_cast<uint32_t*>(&h);
            }
            if (r1g < totalPx) {
                __nv_bfloat162 h = __floats2bfloat162_rn(p10, p11);
                *(uint32_t*)(outp + o1 + co) = *reinterpret_cast<uint32_t*>(&h);
            }
        }
    }
}

// ---------------- conv1: 8 px/block, weights in registers ---------------------
__global__ void __launch_bounds__(128)
conv1_split(const float* __restrict__ x, const float* __restrict__ w1,
            const float* __restrict__ b1, __half* __restrict__ hi,
            __half* __restrict__ lo)
{
    const int b = blockIdx.x, g = blockIdx.y;
    const int p0 = g * 8;
    const int oy = p0 / 24, ox0 = p0 - oy * 24;
    const int co = threadIdx.x;
    __shared__ float xs[5][12];
    for (int i = co; i < 60; i += 128) {
        int r = i / 12, c = i - r * 12;
        xs[r][c] = x[(size_t)b * 784 + (oy + r) * 28 + ox0 + c];
    }
    __syncthreads();
    float w[25];
    #pragma unroll
    for (int t = 0; t < 25; ++t) w[t] = w1[co * 25 + t];
    const float bz = b1[co];
    #pragma unroll
    for (int px = 0; px < 8; ++px) {
        float v = bz;
        #pragma unroll
        for (int t = 0; t < 25; ++t)
            v += w[t] * xs[t / 5][t % 5 + px];
        v = fmaxf(v, 0.f);
        __half h = __float2half_rn(v);
        size_t o = ((size_t)b * 576 + p0 + px) * 128 + co;
        hi[o] = h;
        lo[o] = __float2half_rn(v - __half2float(h));
    }
}

// ---------------- NHWC maxpool 2x2: fp32 -> fp16 hi/lo -----------------------
__global__ void mp_split_nhwc(const float* __restrict__ in, __half* __restrict__ hi,
                              __half* __restrict__ lo, int Hin, int Win)
{
    const int Ho = Hin >> 1, Wo = Win >> 1;
    const size_t total = (size_t)BB * Ho * Wo * 128;
    for (size_t i = (size_t)blockIdx.x * blockDim.x + threadIdx.x; i < total;
         i += (size_t)gridDim.x * blockDim.x) {
        int c = (int)(i & 127);
        size_t r = i >> 7;
        int wo = (int)(r % Wo); r /= Wo;
        int ho = (int)(r % Ho); int b = (int)(r / Ho);
        const float* p = in + (((size_t)b * Hin + 2 * ho) * Win + 2 * wo) * 128 + c;
        float v = fmaxf(fmaxf(p[0], p[128]),
                        fmaxf(p[(size_t)Win * 128], p[(size_t)(Win + 1) * 128]));
        __half h = __float2half_rn(v);
        hi[i] = h;
        lo[i] = __float2half_rn(v - __half2float(h));
    }
}

// ---------------- NHWC maxpool 2x2: fp32 -> fp32 -----------------------------
__global__ void mp_nhwc(const float* __restrict__ in, float* __restrict__ out,
                        int Hin, int Win)
{
    const int Ho = Hin >> 1, Wo = Win >> 1;
    const size_t total = (size_t)BB * Ho * Wo * 128;
    for (size_t i = (size_t)blockIdx.x * blockDim.x + threadIdx.x; i < total;
         i += (size_t)gridDim.x * blockDim.x) {
        int c = (int)(i & 127);
        size_t r = i >> 7;
        int wo = (int)(r % Wo); r /= Wo;
        int ho = (int)(r % Ho); int b = (int)(r / Ho);
        const float* p = in + (((size_t)b * Hin + 2 * ho) * Win + 2 * wo) * 128 + c;
        out[i] = fmaxf(fmaxf(p[0], p[128]),
                       fmaxf(p[(size_t)Win * 128], p[(size_t)(Win + 1) * 128]));
    }
}

// ---------------- VQ: argmax(d2), gather val (NHWC bf16), dict MSE ------------
__global__ void __launch_bounds__(256)
vq_kernel(const float* __restrict__ z, const float* __restrict__ dict,
          __nv_bfloat16* __restrict__ valh, float* __restrict__ idx_out)
{
    extern __shared__ float dsmf[];
    __shared__ float zt[36 * 128];
    __shared__ float wn[128];
    __shared__ int   sidx[36];

    const int b = blockIdx.x, tid = threadIdx.x;

    for (int i = tid; i < 128 * 128; i += NT) {
        int k = i >> 7; int c = i & 127;
        dsmf[k * 129 + c] = dict[i];
    }
    for (int i = tid; i < 36 * 128; i += NT)
        zt[i] = z[(size_t)b * 4608 + i];
    __syncthreads();
    if (tid < 128) {
        float s = 0.f;
        const float* dp = dsmf + tid * 129;
        for (int c = 0; c < 128; c++) s += dp[c] * dp[c];
        wn[tid] = s;
    }
    __syncthreads();

    const int lane = tid & 31, wid = tid >> 5;
    for (int pos = wid; pos < 36; pos += 8) {
        float d0 = 0.f, d1 = 0.f, d2s = 0.f, d3 = 0.f, zn = 0.f;
        const float* zp = zt + pos * 128;
        const float* p0 = dsmf + (lane      ) * 129;
        const float* p1 = dsmf + (lane + 32 ) * 129;
        const float* p2 = dsmf + (lane + 64 ) * 129;
        const float* p3 = dsmf + (lane + 96 ) * 129;
        for (int c = 0; c < 128; c++) {
            float zv = zp[c];
            zn += zv * zv;
            d0 += p0[c] * zv; d1 += p1[c] * zv;
            d2s += p2[c] * zv; d3 += p3[c] * zv;
        }
        float bv = zn + wn[lane] - 2.f * d0; int bk = lane;
        float v1 = zn + wn[lane + 32] - 2.f * d1; if (v1 > bv) { bv = v1; bk = lane + 32; }
        float v2 = zn + wn[lane + 64] - 2.f * d2s; if (v2 > bv) { bv = v2; bk = lane + 64; }
        float v3 = zn + wn[lane + 96] - 2.f * d3; if (v3 > bv) { bv = v3; bk = lane + 96; }
        #pragma unroll
        for (int o = 16; o; o >>= 1) {
            float ov = __shfl_xor_sync(0xffffffffu, bv, o);
            int   ok = __shfl_xor_sync(0xffffffffu, bk, o);
            if (ov > bv || (ov == bv && ok < bk)) { bv = ov; bk = ok; }
        }
        if (lane == 0) {
            sidx[pos] = bk;
            if (idx_out) idx_out[b * 36 + pos] = (float)bk;
        }
    }
    __syncthreads();

    float lsum = 0.f;
    for (int i = tid; i < 4608; i += NT) {
        int pos = i >> 7; int c = i & 127;
        float v  = dsmf[sidx[pos] * 129 + c];
        float zv = zt[i];
        valh[(size_t)b * 4608 + i] = __float2bfloat16(v);
        float d = v - zv;
        lsum += d * d;
    }
    lsum = warp_sum(lsum);
    if ((tid & 31) == 0) atomicAdd(&g_dict_sum, (double)lsum);
}

// ---------------- mu (1x1 conv) fused with reconstruction loss (NHWC bf16) ---
__global__ void __launch_bounds__(256)
mu_loss(const __nv_bfloat16* __restrict__ f4, const float* __restrict__ x,
        const float* __restrict__ mw, const float* __restrict__ mb)
{
    __shared__ float mws[128];
    const int b = blockIdx.x, tid = threadIdx.x;
    if (tid < 128) mws[tid] = mw[tid];
    __syncthreads();
    float lsum = 0.f;
    for (int px = tid; px < 784; px += NT) {
        const uint4* fp = (const uint4*)(f4 + ((size_t)b * 784 + px) * 128);
        float s = mb[0];
        #pragma unroll
        for (int j = 0; j < 16; j++) {
            uint4 v = fp[j];
            const __nv_bfloat16* h = (const __nv_bfloat16*)&v;
            #pragma unroll
            for (int t = 0; t < 8; t++)
                s += __bfloat162float(h[t]) * mws[j * 8 + t];
        }
        float d = s - x[(size_t)b * 784 + px];
        lsum += d * d;
    }
    lsum = warp_sum(lsum);
    if ((tid & 31) == 0) atomicAdd(&g_rec_sum, (double)lsum);
}

__global__ void finalize_kernel(float* loss_out)
{
    if (loss_out) {
        double dict_mse = g_dict_sum / 1179648.0;
        loss_out[0] = (float)(g_rec_sum / 200704.0);
        loss_out[1] = (float)(dict_mse * 5.0);
        loss_out[2] = (float)(dict_mse * 1.25);
        loss_out[3] = 0.f;
    }
}

// ---------------- host side ----------------------------------------------------
extern "C" void kernel_launch(void* const* d_in, const int* in_sizes, int n_in,
                              void* d_out, int out_size)
{
    const float* x    = (const float*)d_in[0];
    const float* w1   = (const float*)d_in[1];
    const float* b1   = (const float*)d_in[2];
    const float* w2   = (const float*)d_in[3];
    const float* b2   = (const float*)d_in[4];
    const float* w3   = (const float*)d_in[5];
    const float* b3   = (const float*)d_in[6];
    const float* t1w  = (const float*)d_in[7];
    const float* t1b  = (const float*)d_in[8];
    const float* t2w  = (const float*)d_in[9];
    const float* t2b  = (const float*)d_in[10];
    const float* t3w  = (const float*)d_in[11];
    const float* t3b  = (const float*)d_in[12];
    const float* t4w  = (const float*)d_in[13];
    const float* t4b  = (const float*)d_in[14];
    const float* mw   = (const float*)d_in[15];
    const float* mb   = (const float*)d_in[16];
    const float* dictw= (const float*)d_in[17];

    float* outp = (float*)d_out;
    float* loss_ptr = outp;
    float* idx_ptr  = outp + 4;
    if (out_size < 9220) { loss_ptr = nullptr; idx_ptr = outp; }

    __half *c1hi, *c1lo, *p1hi, *p1lo, *w2hi, *w2lo, *w3hi, *w3lo;
    float *c2f, *c3f, *zn;
    __nv_bfloat16 *valh, *f1h, *f2h, *f3h, *f4h, *wp1, *wpt2, *wp3, *wp4;
    cudaGetSymbolAddress((void**)&c1hi, g_c1hi);
    cudaGetSymbolAddress((void**)&c1lo, g_c1lo);
    cudaGetSymbolAddress((void**)&c2f,  g_c2f);
    cudaGetSymbolAddress((void**)&p1hi, g_p1hi);
    cudaGetSymbolAddress((void**)&p1lo, g_p1lo);
    cudaGetSymbolAddress((void**)&c3f,  g_c3f);
    cudaGetSymbolAddress((void**)&zn,   g_zn);
    cudaGetSymbolAddress((void**)&valh, g_valh);
    cudaGetSymbolAddress((void**)&f1h,  g_f1h);
    cudaGetSymbolAddress((void**)&f2h,  g_f2h);
    cudaGetSymbolAddress((void**)&f3h,  g_f3h);
    cudaGetSymbolAddress((void**)&f4h,  g_f4h);
    cudaGetSymbolAddress((void**)&wp1,  g_wp1);
    cudaGetSymbolAddress((void**)&wpt2, g_wpt2);
    cudaGetSymbolAddress((void**)&wp3,  g_wp3);
    cudaGetSymbolAddress((void**)&wp4,  g_wp4);
    cudaGetSymbolAddress((void**)&w2hi, g_w2hi);
    cudaGetSymbolAddress((void**)&w2lo, g_w2lo);
    cudaGetSymbolAddress((void**)&w3hi, g_w3hi);
    cudaGetSymbolAddress((void**)&w3lo, g_w3lo);

    static bool attr_set = false;
    if (!attr_set) {
        cudaFuncSetAttribute(vq_kernel, cudaFuncAttributeMaxDynamicSharedMemorySize,
                             128 * 129 * (int)sizeof(float));
        cudaFuncSetAttribute(tc_eng1, cudaFuncAttributeMaxDynamicSharedMemorySize,
                             2 * TILEA + 2 * TILE);
        cudaFuncSetAttribute(tc_t2, cudaFuncAttributeMaxDynamicSharedMemorySize,
                             2 * TILEA + 2 * TILE);
        cudaFuncSetAttribute(tc_enc3, cudaFuncAttributeMaxDynamicSharedMemorySize,
                             2 * TILEA + 2 * TILE);
        attr_set = true;
    }

    init_kernel<<<1, 1>>>();                                    // 0
    prepack_all<<<132, 256>>>(w2, w3, t1w, t2w, t3w, t4w,       // 1
                              w2hi, w2lo, w3hi, w3lo, wp1, wpt2, wp3, wp4);
    conv1_split<<<dim3(BB, 72), 128>>>(x, w1, b1, c1hi, c1lo);  // 2
    tc_enc3<<<576, 256, 2 * TILEA + 2 * TILE>>>(                // 3 <- profiled
        (const uint16_t*)c1hi, (const uint16_t*)c1lo,
        (const uint16_t*)w2hi, (const uint16_t*)w2lo,
        b2, c2f, 24, 24, 24, 24, 2, 1);
    mp_split_nhwc<<<4096, 256>>>(c2f, p1hi, p1lo, 24, 24);
    tc_enc3<<<144, 256, 2 * TILEA + 2 * TILE>>>(
        (const uint16_t*)p1hi, (const uint16_t*)p1lo,
        (const uint16_t*)w3hi, (const uint16_t*)w3lo,
        b3, c3f, 12, 12, 12, 12, 2, 0);
    mp_nhwc<<<2048, 256>>>(c3f, zn, 12, 12);

    vq_kernel<<<BB, NT, 128 * 129 * sizeof(float)>>>(zn, dictw, valh, idx_ptr);

    tc_eng1<<<81, 256, 2 * TILEA + 2 * TILE>>>(
        (const uint16_t*)valh, (const uint16_t*)wp1, t1b, f1h, 6, 6, 9, 9, 3, 4);
    tc_t2<<<dim3(100, 1, 4), 256, 2 * TILEA + 2 * TILE>>>(
        (const uint16_t*)f1h, (const uint16_t*)wpt2, t2b, f2h);
    tc_eng1<<<576, 256, 2 * TILEA + 2 * TILE>>>(
        (const uint16_t*)f2h, (const uint16_t*)wp3, t3b, f3h, 20, 20, 24, 24, 4, 5);
    tc_eng1<<<784, 256, 2 * TILEA + 2 * TILE>>>(
        (const uint16_t*)f3h, (const uint16_t*)wp4, t4b, f4h, 24, 24, 28, 28, 4, 5);

    mu_loss<<<BB, NT>>>(f4h, x, mw, mb);
    finalize_kernel<<<1, 1>>>(loss_ptr);
}

// round 12
// speedup vs baseline: 6.7917x; 1.0023x over previous
#include <cuda_runtime.h>
#include <cuda_bf16.h>
#include <cuda_fp16.h>
#include <cstdint>

#define BB 256
#define NT 256
#define TILE 34816          // 128 rows x 272B
#define TILEA 69632         // 256 rows x 272B

// ---------------- scratch (device globals; no allocation APIs) ---------------
__device__ __half g_c1hi[(size_t)BB*576*128];
__device__ __half g_c1lo[(size_t)BB*576*128];
__device__ float  g_c2f [(size_t)BB*576*128];
__device__ __half g_p1hi[(size_t)BB*144*128];
__device__ __half g_p1lo[(size_t)BB*144*128];
__device__ float  g_c3f [(size_t)BB*144*128];
__device__ float  g_zn  [(size_t)BB*36*128];
__device__ __nv_bfloat16 g_valh[(size_t)BB*36*128];
__device__ __nv_bfloat16 g_f1h[(size_t)BB*81*128];
__device__ __nv_bfloat16 g_f2h[(size_t)BB*400*128];
__device__ __nv_bfloat16 g_f3h[(size_t)BB*576*128];
__device__ __nv_bfloat16 g_f4h[(size_t)BB*784*128];
__device__ __nv_bfloat16 g_wp1[16*128*136];
__device__ __nv_bfloat16 g_wpt2[16*128*136];
__device__ __nv_bfloat16 g_wp3[25*128*136];
__device__ __nv_bfloat16 g_wp4[25*128*136];
__device__ __half g_w2hi[25*128*136];
__device__ __half g_w2lo[25*128*136];
__device__ __half g_w3hi[25*128*136];
__device__ __half g_w3lo[25*128*136];
__device__ double g_rec_sum;
__device__ double g_dict_sum;

__global__ void init_kernel() { g_rec_sum = 0.0; g_dict_sum = 0.0; }

__inline__ __device__ float warp_sum(float v) {
    #pragma unroll
    for (int o = 16; o; o >>= 1) v += __shfl_xor_sync(0xffffffffu, v, o);
    return v;
}

// ---------------- mma / cp.async helpers --------------------------------------
__device__ __forceinline__ uint32_t smem_u32(const void* p) {
    uint32_t a;
    asm("{ .reg .u64 t; cvta.to.shared.u64 t, %1; cvt.u32.u64 %0, t; }"
        : "=r"(a) : "l"(p));
    return a;
}

#define LDSM_X4(r0, r1, r2, r3, addr)                                          \
    asm volatile("ldmatrix.sync.aligned.m8n8.x4.shared.b16 {%0,%1,%2,%3}, [%4];" \
                 : "=r"(r0), "=r"(r1), "=r"(r2), "=r"(r3) : "r"(addr))

#define MMA_BF16(c, a0, a1, a2, a3, b0, b1)                                    \
    asm volatile("mma.sync.aligned.m16n8k16.row.col.f32.bf16.bf16.f32 "        \
                 "{%0,%1,%2,%3}, {%4,%5,%6,%7}, {%8,%9}, {%0,%1,%2,%3};"       \
                 : "+f"((c)[0]), "+f"((c)[1]), "+f"((c)[2]), "+f"((c)[3])      \
                 : "r"(a0), "r"(a1), "r"(a2), "r"(a3), "r"(b0), "r"(b1))

#define MMA_F16(c, a0, a1, a2, a3, b0, b1)                                     \
    asm volatile("mma.sync.aligned.m16n8k16.row.col.f32.f16.f16.f32 "          \
                 "{%0,%1,%2,%3}, {%4,%5,%6,%7}, {%8,%9}, {%0,%1,%2,%3};"       \
                 : "+f"((c)[0]), "+f"((c)[1]), "+f"((c)[2]), "+f"((c)[3])      \
                 : "r"(a0), "r"(a1), "r"(a2), "r"(a3), "r"(b0), "r"(b1))

#define CP16(d, s, n)                                                          \
    asm volatile("cp.async.cg.shared.global [%0], [%1], 16, %2;"               \
                 :: "r"(d), "l"(s), "r"(n))
#define CP_COMMIT() asm volatile("cp.async.commit_group;" ::: "memory")
#define CP_WAIT0()  asm volatile("cp.async.wait_group 0;" ::: "memory")
#define CP_WAIT1()  asm volatile("cp.async.wait_group 1;" ::: "memory")

// ---------------- fused weight prepack (all layers, one launch) ---------------
__device__ __forceinline__ void pp_fwd_split(const float* W, __half* dh, __half* dl,
                                             int tap)
{
    int ky = tap / 5, kx = tap - ky * 5;
    size_t tb = (size_t)tap * 128 * 136;
    for (int i = threadIdx.x; i < 16384; i += blockDim.x) {
        int co = i >> 7, ci = i & 127;
        float v = W[(((size_t)co * 128 + ci) * 5 + ky) * 5 + kx];
        __half h = __float2half_rn(v);
        dh[tb + co * 136 + ci] = h;
        dl[tb + co * 136 + ci] = __float2half_rn(v - __half2float(h));
    }
}

__device__ __forceinline__ void pp_deconv(const float* W, __nv_bfloat16* dst,
                                          int tap, int K)
{
    int ky = tap / K, kx = tap - ky * K;
    __nv_bfloat16* base = dst + (size_t)tap * 128 * 136;
    for (int i = threadIdx.x; i < 16384; i += blockDim.x) {
        int co = i >> 7, ci = i & 127;
        float v = W[(((size_t)ci * 128 + co) * K + (K - 1 - ky)) * K + (K - 1 - kx)];
        base[co * 136 + ci] = __float2bfloat16(v);
    }
}

__device__ __forceinline__ void pp_t2(const float* W, __nv_bfloat16* dst, int idx)
{
    int par = idx >> 2, tap = idx & 3;
    int py = par >> 1, px = par & 1;
    int ti = tap >> 1, tj = tap & 1;
    int ky = py + 2 * ti, kx = px + 2 * tj;
    __nv_bfloat16* base = dst + (size_t)idx * 128 * 136;
    for (int i = threadIdx.x; i < 16384; i += blockDim.x) {
        int co = i >> 7, ci = i & 127;
        float v = W[(((size_t)ci * 128 + co) * 4 + ky) * 4 + kx];
        base[co * 136 + ci] = __float2bfloat16(v);
    }
}

__global__ void prepack_all(const float* w2, const float* w3,
                            const float* t1w, const float* t2w,
                            const float* t3w, const float* t4w,
                            __half* w2hi, __half* w2lo,
                            __half* w3hi, __half* w3lo,
                            __nv_bfloat16* wp1, __nv_bfloat16* wpt2,
                            __nv_bfloat16* wp3, __nv_bfloat16* wp4)
{
    int bid = blockIdx.x;
    if      (bid < 25)  pp_fwd_split(w2, w2hi, w2lo, bid);
    else if (bid < 50)  pp_fwd_split(w3, w3hi, w3lo, bid - 25);
    else if (bid < 66)  pp_deconv(t1w, wp1, bid - 50, 4);
    else if (bid < 82)  pp_t2(t2w, wpt2, bid - 66);
    else if (bid < 107) pp_deconv(t3w, wp3, bid - 82, 5);
    else                pp_deconv(t4w, wp4, bid - 107, 5);
}

// ====== fused 3-pass fp16-split encoder conv, M=256, 512 threads ==============
__global__ void __launch_bounds__(512, 1)
tc_enc3(const uint16_t* __restrict__ inHi, const uint16_t* __restrict__ inLo,
        const uint16_t* __restrict__ wHi,  const uint16_t* __restrict__ wLo,
        const float* __restrict__ bias, float* __restrict__ outp,
        int Hin, int Win, int Hout, int Wout, int pad, int relu)
{
    extern __shared__ char dsm[];
    __shared__ float sbias[128];
    const int tid  = threadIdx.x;
    const int wid  = tid >> 5;
    const int lane = tid & 31;
    const int Npix = Hout * Wout;
    const int totalPx = BB * Npix;
    const int pbase = blockIdx.x * 256;

    const uint32_t smA   = smem_u32(dsm);
    const uint32_t smBhi = smA + 2 * TILEA;
    const uint32_t smBlo = smBhi + TILE;
    if (tid < 128) sbias[tid] = bias[tid];

    const int arow = tid >> 1, ahalf = tid & 1;
    const int ap = pbase + arow;
    const bool apv = (ap < totalPx);
    const int bA  = apv ? ap / Npix : 0;
    const int apn = apv ? ap - bA * Npix : 0;
    const int apy = apn / Wout;
    const int apx = apn - apy * Wout;
    const uint32_t adst0 = smA + arow * 272 + ahalf * 128;

    const int pxg = wid >> 1, cog = wid & 1;   // 8 px-groups x 2 co-groups
    float acc[2][8][4];
    #pragma unroll
    for (int m = 0; m < 2; m++)
        #pragma unroll
        for (int n = 0; n < 8; n++)
            #pragma unroll
            for (int j = 0; j < 4; j++) acc[m][n][j] = 0.f;

    const uint32_t a_rd0 = smA + (pxg * 32 + (lane & 15)) * 272 + ((lane >> 4) << 4);
    const uint32_t b_rdb = (cog * 64 + ((lane >> 4) << 3) + (lane & 7)) * 272
                         + (((lane >> 3) & 1) << 4);

    auto stage_A = [&](int it) {
        const int tap = (it < 25) ? it : it - 25;
        const uint16_t* abuf = (it < 25) ? inHi : inLo;
        const int ky = tap / 5, kx = tap - ky * 5;
        const int iy = apy + ky - pad, ix = apx + kx - pad;
        const bool inb = apv && (unsigned)iy < (unsigned)Hin && (unsigned)ix < (unsigned)Win;
        const char* as = inb ? (const char*)(abuf + ((size_t)(bA * Hin + iy) * Win + ix) * 128
                                             + ahalf * 64)
                             : (const char*)abuf;
        const uint32_t ad = adst0 + (it & 1) * TILEA;
        const int sz = inb ? 16 : 0;
        #pragma unroll
        for (int j = 0; j < 8; ++j)
            CP16(ad + j * 16, as + (size_t)j * 16, sz);
    };

    auto stage_Btile = [&](const uint16_t* wbuf, int tap, uint32_t bd) {
        const char* wb = (const char*)(wbuf + (size_t)tap * 128 * 136);
        #pragma unroll
        for (int j = 0; j < 4; ++j)
            CP16(bd + (j * 512 + tid) * 16, wb + (size_t)(j * 512 + tid) * 16, 16);
        if (tid < 128)
            CP16(bd + (2048 + tid) * 16, wb + (size_t)(2048 + tid) * 16, 16);
    };

    stage_A(0);
    CP_COMMIT();

    for (int it = 0; it < 50; ++it) {
        const int tap = (it < 25) ? it : it - 25;
        const int ph  = (it < 25) ? 0 : 1;
        stage_Btile(wHi, tap, smBhi);
        if (ph == 0) stage_Btile(wLo, tap, smBlo);
        CP_COMMIT();
        if (it < 49) {
            stage_A(it + 1);
            CP_COMMIT();
            CP_WAIT1();
        } else {
            CP_WAIT0();
        }
        __syncthreads();
        const uint32_t abase = (it & 1) * TILEA;

        #pragma unroll
        for (int ks = 0; ks < 8; ++ks) {
            uint32_t a[2][4], bq[4][4];
            #pragma unroll
            for (int i = 0; i < 2; ++i)
                LDSM_X4(a[i][0], a[i][1], a[i][2], a[i][3],
                        a_rd0 + abase + i * 16 * 272 + ks * 32);
            #pragma unroll
            for (int nb = 0; nb < 4; ++nb)
                LDSM_X4(bq[nb][0], bq[nb][1], bq[nb][2], bq[nb][3],
                        smBhi + b_rdb + nb * 16 * 272 + ks * 32);
            #pragma unroll
            for (int nb = 0; nb < 4; ++nb)
                #pragma unroll
                for (int i = 0; i < 2; ++i) {
                    MMA_F16(acc[i][2 * nb],     a[i][0], a[i][1], a[i][2], a[i][3],
                            bq[nb][0], bq[nb][1]);
                    MMA_F16(acc[i][2 * nb + 1], a[i][0], a[i][1], a[i][2], a[i][3],
                            bq[nb][2], bq[nb][3]);
                }
            if (ph == 0) {
                #pragma unroll
                for (int nb = 0; nb < 4; ++nb)
                    LDSM_X4(bq[nb][0], bq[nb][1], bq[nb][2], bq[nb][3],
                            smBlo + b_rdb + nb * 16 * 272 + ks * 32);
                #pragma unroll
                for (int nb = 0; nb < 4; ++nb)
                    #pragma unroll
                    for (int i = 0; i < 2; ++i) {
                        MMA_F16(acc[i][2 * nb],     a[i][0], a[i][1], a[i][2], a[i][3],
                                bq[nb][0], bq[nb][1]);
                        MMA_F16(acc[i][2 * nb + 1], a[i][0], a[i][1], a[i][2], a[i][3],
                                bq[nb][2], bq[nb][3]);
                    }
            }
        }
        __syncthreads();
    }

    #pragma unroll
    for (int mb = 0; mb < 2; ++mb) {
        const int row0 = pbase + pxg * 32 + mb * 16 + (lane >> 2);
        const int row1 = row0 + 8;
        const bool v0 = (row0 < totalPx), v1 = (row1 < totalPx);
        #pragma unroll
        for (int nt = 0; nt < 8; ++nt) {
            const int co = cog * 64 + nt * 8 + 2 * (lane & 3);
            const float bz0 = sbias[co], bz1 = sbias[co + 1];
            float p00 = acc[mb][nt][0] + bz0, p01 = acc[mb][nt][1] + bz1;
            float p10 = acc[mb][nt][2] + bz0, p11 = acc[mb][nt][3] + bz1;
            if (relu) {
                p00 = fmaxf(p00, 0.f); p01 = fmaxf(p01, 0.f);
                p10 = fmaxf(p10, 0.f); p11 = fmaxf(p11, 0.f);
            }
            if (v0) *(float2*)(outp + (size_t)row0 * 128 + co) = make_float2(p00, p01);
            if (v1) *(float2*)(outp + (size_t)row1 * 128 + co) = make_float2(p10, p11);
        }
    }
}

// ================= 1-pass bf16 engine, M=256, 512 threads =====================
__global__ void __launch_bounds__(512, 1)
tc_eng1(const uint16_t* __restrict__ in, const uint16_t* __restrict__ wpack,
        const float* __restrict__ bias, __nv_bfloat16* __restrict__ outp,
        int Hin, int Win, int Hout, int Wout, int pad, int K)
{
    extern __shared__ char dsm[];
    __shared__ float sbias[128];
    const int tid  = threadIdx.x;
    const int wid  = tid >> 5;
    const int lane = tid & 31;
    const int Npix = Hout * Wout;
    const int totalPx = BB * Npix;
    const int pbase = blockIdx.x * 256;

    const uint32_t smA = smem_u32(dsm);
    const uint32_t smB = smA + 2 * TILEA;
    if (tid < 128) sbias[tid] = bias[tid];

    const int arow = tid >> 1, ahalf = tid & 1;
    const int ap = pbase + arow;
    const bool apv = (ap < totalPx);
    const int bA  = apv ? ap / Npix : 0;
    const int apn = apv ? ap - bA * Npix : 0;
    const int apy = apn / Wout;
    const int apx = apn - apy * Wout;
    const uint32_t adst0 = smA + arow * 272 + ahalf * 128;

    const int pxg = wid >> 1, cog = wid & 1;
    float acc[2][8][4];
    #pragma unroll
    for (int m = 0; m < 2; m++)
        #pragma unroll
        for (int n = 0; n < 8; n++)
            #pragma unroll
            for (int j = 0; j < 4; j++) acc[m][n][j] = 0.f;

    const uint32_t a_rd0 = smA + (pxg * 32 + (lane & 15)) * 272 + ((lane >> 4) << 4);
    const uint32_t b_rdb = (cog * 64 + ((lane >> 4) << 3) + (lane & 7)) * 272
                         + (((lane >> 3) & 1) << 4);
    const int NIT = K * K;

    auto stage = [&](int tap) {
        const int buf = tap & 1;
        const int ky = tap / K, kx = tap - ky * K;
        const char* wb = (const char*)(wpack + (size_t)tap * 128 * 136);
        const uint32_t bd = smB + buf * TILE;
        #pragma unroll
        for (int j = 0; j < 4; ++j)
            CP16(bd + (j * 512 + tid) * 16, wb + (size_t)(j * 512 + tid) * 16, 16);
        if (tid < 128)
            CP16(bd + (2048 + tid) * 16, wb + (size_t)(2048 + tid) * 16, 16);
        const int iy = apy + ky - pad, ix = apx + kx - pad;
        const bool inb = apv && (unsigned)iy < (unsigned)Hin && (unsigned)ix < (unsigned)Win;
        const char* as = inb ? (const char*)(in + ((size_t)(bA * Hin + iy) * Win + ix) * 128
                                             + ahalf * 64)
                             : (const char*)in;
        const uint32_t ad = adst0 + buf * TILEA;
        const int sz = inb ? 16 : 0;
        #pragma unroll
        for (int j = 0; j < 8; ++j)
            CP16(ad + j * 16, as + (size_t)j * 16, sz);
        CP_COMMIT();
    };

    stage(0);
    for (int it = 0; it < NIT; ++it) {
        CP_WAIT0();
        __syncthreads();
        if (it + 1 < NIT) stage(it + 1);
        const uint32_t abase = (it & 1) * TILEA;
        const uint32_t bbase = smB + (it & 1) * TILE;
        #pragma unroll
        for (int ks = 0; ks < 8; ++ks) {
            uint32_t a[2][4], bq[4][4];
            #pragma unroll
            for (int i = 0; i < 2; ++i)
                LDSM_X4(a[i][0], a[i][1], a[i][2], a[i][3],
                        a_rd0 + abase + i * 16 * 272 + ks * 32);
            #pragma unroll
            for (int nb = 0; nb < 4; ++nb)
                LDSM_X4(bq[nb][0], bq[nb][1], bq[nb][2], bq[nb][3],
                        bbase + b_rdb + nb * 16 * 272 + ks * 32);
            #pragma unroll
            for (int nb = 0; nb < 4; ++nb)
                #pragma unroll
                for (int i = 0; i < 2; ++i) {
                    MMA_BF16(acc[i][2 * nb],     a[i][0], a[i][1], a[i][2], a[i][3],
                             bq[nb][0], bq[nb][1]);
                    MMA_BF16(acc[i][2 * nb + 1], a[i][0], a[i][1], a[i][2], a[i][3],
                             bq[nb][2], bq[nb][3]);
                }
        }
        // no trailing sync: A/B double-buffered; next leading sync orders reuse
    }

    #pragma unroll
    for (int mb = 0; mb < 2; ++mb) {
        const int row0 = pbase + pxg * 32 + mb * 16 + (lane >> 2);
        const int row1 = row0 + 8;
        const bool v0 = (row0 < totalPx), v1 = (row1 < totalPx);
        #pragma unroll
        for (int nt = 0; nt < 8; ++nt) {
            const int co = cog * 64 + nt * 8 + 2 * (lane & 3);
            const float bz0 = sbias[co], bz1 = sbias[co + 1];
            float p00 = fmaxf(acc[mb][nt][0] + bz0, 0.f);
            float p01 = fmaxf(acc[mb][nt][1] + bz1, 0.f);
            float p10 = fmaxf(acc[mb][nt][2] + bz0, 0.f);
            float p11 = fmaxf(acc[mb][nt][3] + bz1, 0.f);
            if (v0) {
                __nv_bfloat162 h = __floats2bfloat162_rn(p00, p01);
                *(uint32_t*)(outp + (size_t)row0 * 128 + co) = *reinterpret_cast<uint32_t*>(&h);
            }
            if (v1) {
                __nv_bfloat162 h = __floats2bfloat162_rn(p10, p11);
                *(uint32_t*)(outp + (size_t)row1 * 128 + co) = *reinterpret_cast<uint32_t*>(&h);
            }
        }
    }
}

// ================= t2 stride-2 deconv, parity decomposition, 512 thr ==========
__global__ void __launch_bounds__(512, 1)
tc_t2(const uint16_t* __restrict__ in, const uint16_t* __restrict__ wpack,
      const float* __restrict__ bias, __nv_bfloat16* __restrict__ outp)
{
    extern __shared__ char dsm[];
    __shared__ float sbias[128];
    const int tid  = threadIdx.x;
    const int wid  = tid >> 5;
    const int lane = tid & 31;
    const int par  = blockIdx.z;
    const int py   = par >> 1, px = par & 1;
    const int totalPx = BB * 100;
    const int pbase = blockIdx.x * 256;

    const uint32_t smA = smem_u32(dsm);
    const uint32_t smB = smA + 2 * TILEA;
    if (tid < 128) sbias[tid] = bias[tid];

    const int arow = tid >> 1, ahalf = tid & 1;
    const int ap = pbase + arow;
    const bool apv = (ap < totalPx);
    const int bA  = apv ? ap / 100 : 0;
    const int apn = apv ? ap - bA * 100 : 0;
    const int apy = apn / 10;
    const int apx = apn - apy * 10;
    const uint32_t adst0 = smA + arow * 272 + ahalf * 128;

    const int pxg = wid >> 1, cog = wid & 1;
    float acc[2][8][4];
    #pragma unroll
    for (int m = 0; m < 2; m++)
        #pragma unroll
        for (int n = 0; n < 8; n++)
            #pragma unroll
            for (int j = 0; j < 4; j++) acc[m][n][j] = 0.f;

    const uint32_t a_rd0 = smA + (pxg * 32 + (lane & 15)) * 272 + ((lane >> 4) << 4);
    const uint32_t b_rdb = (cog * 64 + ((lane >> 4) << 3) + (lane & 7)) * 272
                         + (((lane >> 3) & 1) << 4);

    auto stage = [&](int tap) {
        const int buf = tap & 1;
        const int ti = tap >> 1, tj = tap & 1;
        const char* wb = (const char*)(wpack + (size_t)(par * 4 + tap) * 128 * 136);
        const uint32_t bd = smB + buf * TILE;
        #pragma unroll
        for (int j = 0; j < 4; ++j)
            CP16(bd + (j * 512 + tid) * 16, wb + (size_t)(j * 512 + tid) * 16, 16);
        if (tid < 128)
            CP16(bd + (2048 + tid) * 16, wb + (size_t)(2048 + tid) * 16, 16);
        const int iy = apy - ti, ix = apx - tj;
        const bool inb = apv && (unsigned)iy < 9u && (unsigned)ix < 9u;
        const char* as = inb ? (const char*)(in + ((size_t)(bA * 9 + iy) * 9 + ix) * 128
                                             + ahalf * 64)
                             : (const char*)in;
        const uint32_t ad = adst0 + buf * TILEA;
        const int sz = inb ? 16 : 0;
        #pragma unroll
        for (int j = 0; j < 8; ++j)
            CP16(ad + j * 16, as + (size_t)j * 16, sz);
        CP_COMMIT();
    };

    stage(0);
    for (int it = 0; it < 4; ++it) {
        CP_WAIT0();
        __syncthreads();
        if (it + 1 < 4) stage(it + 1);
        const uint32_t abase = (it & 1) * TILEA;
        const uint32_t bbase = smB + (it & 1) * TILE;
        #pragma unroll
        for (int ks = 0; ks < 8; ++ks) {
            uint32_t a[2][4], bq[4][4];
            #pragma unroll
            for (int i = 0; i < 2; ++i)
                LDSM_X4(a[i][0], a[i][1], a[i][2], a[i][3],
                        a_rd0 + abase + i * 16 * 272 + ks * 32);
            #pragma unroll
            for (int nb = 0; nb < 4; ++nb)
                LDSM_X4(bq[nb][0], bq[nb][1], bq[nb][2], bq[nb][3],
                        bbase + b_rdb + nb * 16 * 272 + ks * 32);
            #pragma unroll
            for (int nb = 0; nb < 4; ++nb)
                #pragma unroll
                for (int i = 0; i < 2; ++i) {
                    MMA_BF16(acc[i][2 * nb],     a[i][0], a[i][1], a[i][2], a[i][3],
                             bq[nb][0], bq[nb][1]);
                    MMA_BF16(acc[i][2 * nb + 1], a[i][0], a[i][1], a[i][2], a[i][3],
                             bq[nb][2], bq[nb][3]);
                }
        }
    }

    #pragma unroll
    for (int mb = 0; mb < 2; ++mb) {
        const int r0g = pbase + pxg * 32 + mb * 16 + (lane >> 2);
        const int r1g = r0g + 8;
        int b0 = r0g / 100, q0 = r0g - b0 * 100, y0 = q0 / 10, x0 = q0 - y0 * 10;
        int b1 = r1g / 100, q1 = r1g - b1 * 100, y1 = q1 / 10, x1 = q1 - y1 * 10;
        size_t o0 = ((size_t)b0 * 400 + (2 * y0 + py) * 20 + 2 * x0 + px) * 128;
        size_t o1 = ((size_t)b1 * 400 + (2 * y1 + py) * 20 + 2 * x1 + px) * 128;
        #pragma unroll
        for (int nt = 0; nt < 8; ++nt) {
            const int co = cog * 64 + nt * 8 + 2 * (lane & 3);
            const float bz0 = sbias[co], bz1 = sbias[co + 1];
            float p00 = fmaxf(acc[mb][nt][0] + bz0, 0.f);
            float p01 = fmaxf(acc[mb][nt][1] + bz1, 0.f);
            float p10 = fmaxf(acc[mb][nt][2] + bz0, 0.f);
            float p11 = fmaxf(acc[mb][nt][3] + bz1, 0.f);
            if (r0g < totalPx) {
                __nv_bfloat162 h = __floats2bfloat162_rn(p00, p01);
                *(uint32_t*)(outp + o0 + co) = *reinterpret_cast<uint32_t*>(&h);
            }
            if (r1g < totalPx) {
                __nv_bfloat162 h = __floats2bfloat162_rn(p10, p11);
                *(uint32_t*)(outp + o1 + co) = *reinterpret_cast<uint32_t*>(&h);
            }
        }
    }
}

// ---------------- conv1: 8 px/block, weights in registers ---------------------
__global__ void __launch_bounds__(128)
conv1_split(const float* __restrict__ x, const float* __restrict__ w1,
            const float* __restrict__ b1, __half* __restrict__ hi,
            __half* __restrict__ lo)
{
    const int b = blockIdx.x, g = blockIdx.y;
    const int p0 = g * 8;
    const int oy = p0 / 24, ox0 = p0 - oy * 24;
    const int co = threadIdx.x;
    __shared__ float xs[5][12];
    for (int i = co; i < 60; i += 128) {
        int r = i / 12, c = i - r * 12;
        xs[r][c] = x[(size_t)b * 784 + (oy + r) * 28 + ox0 + c];
    }
    __syncthreads();
    float w[25];
    #pragma unroll
    for (int t = 0; t < 25; ++t) w[t] = w1[co * 25 + t];
    const float bz = b1[co];
    #pragma unroll
    for (int px = 0; px < 8; ++px) {
        float v = bz;
        #pragma unroll
        for (int t = 0; t < 25; ++t)
            v += w[t] * xs[t / 5][t % 5 + px];
        v = fmaxf(v, 0.f);
        __half h = __float2half_rn(v);
        size_t o = ((size_t)b * 576 + p0 + px) * 128 + co;
        hi[o] = h;
        lo[o] = __float2half_rn(v - __half2float(h));
    }
}

// ---------------- NHWC maxpool 2x2: fp32 -> fp16 hi/lo -----------------------
__global__ void mp_split_nhwc(const float* __restrict__ in, __half* __restrict__ hi,
                              __half* __restrict__ lo, int Hin, int Win)
{
    const int Ho = Hin >> 1, Wo = Win >> 1;
    const size_t total = (size_t)BB * Ho * Wo * 128;
    for (size_t i = (size_t)blockIdx.x * blockDim.x + threadIdx.x; i < total;
         i += (size_t)gridDim.x * blockDim.x) {
        int c = (int)(i & 127);
        size_t r = i >> 7;
        int wo = (int)(r % Wo); r /= Wo;
        int ho = (int)(r % Ho); int b = (int)(r / Ho);
        const float* p = in + (((size_t)b * Hin + 2 * ho) * Win + 2 * wo) * 128 + c;
        float v = fmaxf(fmaxf(p[0], p[128]),
                        fmaxf(p[(size_t)Win * 128], p[(size_t)(Win + 1) * 128]));
        __half h = __float2half_rn(v);
        hi[i] = h;
        lo[i] = __float2half_rn(v - __half2float(h));
    }
}

// ---------------- NHWC maxpool 2x2: fp32 -> fp32 -----------------------------
__global__ void mp_nhwc(const float* __restrict__ in, float* __restrict__ out,
                        int Hin, int Win)
{
    const int Ho = Hin >> 1, Wo = Win >> 1;
    const size_t total = (size_t)BB * Ho * Wo * 128;
    for (size_t i = (size_t)blockIdx.x * blockDim.x + threadIdx.x; i < total;
         i += (size_t)gridDim.x * blockDim.x) {
        int c = (int)(i & 127);
        size_t r = i >> 7;
        int wo = (int)(r % Wo); r /= Wo;
        int ho = (int)(r % Ho); int b = (int)(r / Ho);
        const float* p = in + (((size_t)b * Hin + 2 * ho) * Win + 2 * wo) * 128 + c;
        out[i] = fmaxf(fmaxf(p[0], p[128]),
                       fmaxf(p[(size_t)Win * 128], p[(size_t)(Win + 1) * 128]));
    }
}

// ---------------- VQ: argmax(d2), gather val (NHWC bf16), dict MSE ------------
__global__ void __launch_bounds__(256)
vq_kernel(const float* __restrict__ z, const float* __restrict__ dict,
          __nv_bfloat16* __restrict__ valh, float* __restrict__ idx_out)
{
    extern __shared__ float dsmf[];
    __shared__ float zt[36 * 128];
    __shared__ float wn[128];
    __shared__ int   sidx[36];

    const int b = blockIdx.x, tid = threadIdx.x;

    for (int i = tid; i < 128 * 128; i += NT) {
        int k = i >> 7; int c = i & 127;
        dsmf[k * 129 + c] = dict[i];
    }
    for (int i = tid; i < 36 * 128; i += NT)
        zt[i] = z[(size_t)b * 4608 + i];
    __syncthreads();
    if (tid < 128) {
        float s = 0.f;
        const float* dp = dsmf + tid * 129;
        for (int c = 0; c < 128; c++) s += dp[c] * dp[c];
        wn[tid] = s;
    }
    __syncthreads();

    const int lane = tid & 31, wid = tid >> 5;
    for (int pos = wid; pos < 36; pos += 8) {
        float d0 = 0.f, d1 = 0.f, d2s = 0.f, d3 = 0.f, zn = 0.f;
        const float* zp = zt + pos * 128;
        const float* p0 = dsmf + (lane      ) * 129;
        const float* p1 = dsmf + (lane + 32 ) * 129;
        const float* p2 = dsmf + (lane + 64 ) * 129;
        const float* p3 = dsmf + (lane + 96 ) * 129;
        for (int c = 0; c < 128; c++) {
            float zv = zp[c];
            zn += zv * zv;
            d0 += p0[c] * zv; d1 += p1[c] * zv;
            d2s += p2[c] * zv; d3 += p3[c] * zv;
        }
        float bv = zn + wn[lane] - 2.f * d0; int bk = lane;
        float v1 = zn + wn[lane + 32] - 2.f * d1; if (v1 > bv) { bv = v1; bk = lane + 32; }
        float v2 = zn + wn[lane + 64] - 2.f * d2s; if (v2 > bv) { bv = v2; bk = lane + 64; }
        float v3 = zn + wn[lane + 96] - 2.f * d3; if (v3 > bv) { bv = v3; bk = lane + 96; }
        #pragma unroll
        for (int o = 16; o; o >>= 1) {
            float ov = __shfl_xor_sync(0xffffffffu, bv, o);
            int   ok = __shfl_xor_sync(0xffffffffu, bk, o);
            if (ov > bv || (ov == bv && ok < bk)) { bv = ov; bk = ok; }
        }
        if (lane == 0) {
            sidx[pos] = bk;
            if (idx_out) idx_out[b * 36 + pos] = (float)bk;
        }
    }
    __syncthreads();

    float lsum = 0.f;
    for (int i = tid; i < 4608; i += NT) {
        int pos = i >> 7; int c = i & 127;
        float v  = dsmf[sidx[pos] * 129 + c];
        float zv = zt[i];
        valh[(size_t)b * 4608 + i] = __float2bfloat16(v);
        float d = v - zv;
        lsum += d * d;
    }
    lsum = warp_sum(lsum);
    if ((tid & 31) == 0) atomicAdd(&g_dict_sum, (double)lsum);
}

// ---------------- mu (1x1 conv) fused with reconstruction loss (NHWC bf16) ---
__global__ void __launch_bounds__(256)
mu_loss(const __nv_bfloat16* __restrict__ f4, const float* __restrict__ x,
        const float* __restrict__ mw, const float* __restrict__ mb)
{
    __shared__ float mws[128];
    const int b = blockIdx.x, tid = threadIdx.x;
    if (tid < 128) mws[tid] = mw[tid];
    __syncthreads();
    float lsum = 0.f;
    for (int px = tid; px < 784; px += NT) {
        const uint4* fp = (const uint4*)(f4 + ((size_t)b * 784 + px) * 128);
        float s = mb[0];
        #pragma unroll
        for (int j = 0; j < 16; j++) {
            uint4 v = fp[j];
            const __nv_bfloat16* h = (const __nv_bfloat16*)&v;
            #pragma unroll
            for (int t = 0; t < 8; t++)
                s += __bfloat162float(h[t]) * mws[j * 8 + t];
        }
        float d = s - x[(size_t)b * 784 + px];
        lsum += d * d;
    }
    lsum = warp_sum(lsum);
    if ((tid & 31) == 0) atomicAdd(&g_rec_sum, (double)lsum);
}

__global__ void finalize_kernel(float* loss_out)
{
    if (loss_out) {
        double dict_mse = g_dict_sum / 1179648.0;
        loss_out[0] = (float)(g_rec_sum / 200704.0);
        loss_out[1] = (float)(dict_mse * 5.0);
        loss_out[2] = (float)(dict_mse * 1.25);
        loss_out[3] = 0.f;
    }
}

// ---------------- host side ----------------------------------------------------
extern "C" void kernel_launch(void* const* d_in, const int* in_sizes, int n_in,
                              void* d_out, int out_size)
{
    const float* x    = (const float*)d_in[0];
    const float* w1   = (const float*)d_in[1];
    const float* b1   = (const float*)d_in[2];
    const float* w2   = (const float*)d_in[3];
    const float* b2   = (const float*)d_in[4];
    const float* w3   = (const float*)d_in[5];
    const float* b3   = (const float*)d_in[6];
    const float* t1w  = (const float*)d_in[7];
    const float* t1b  = (const float*)d_in[8];
    const float* t2w  = (const float*)d_in[9];
    const float* t2b  = (const float*)d_in[10];
    const float* t3w  = (const float*)d_in[11];
    const float* t3b  = (const float*)d_in[12];
    const float* t4w  = (const float*)d_in[13];
    const float* t4b  = (const float*)d_in[14];
    const float* mw   = (const float*)d_in[15];
    const float* mb   = (const float*)d_in[16];
    const float* dictw= (const float*)d_in[17];

    float* outp = (float*)d_out;
    float* loss_ptr = outp;
    float* idx_ptr  = outp + 4;
    if (out_size < 9220) { loss_ptr = nullptr; idx_ptr = outp; }

    __half *c1hi, *c1lo, *p1hi, *p1lo, *w2hi, *w2lo, *w3hi, *w3lo;
    float *c2f, *c3f, *zn;
    __nv_bfloat16 *valh, *f1h, *f2h, *f3h, *f4h, *wp1, *wpt2, *wp3, *wp4;
    cudaGetSymbolAddress((void**)&c1hi, g_c1hi);
    cudaGetSymbolAddress((void**)&c1lo, g_c1lo);
    cudaGetSymbolAddress((void**)&c2f,  g_c2f);
    cudaGetSymbolAddress((void**)&p1hi, g_p1hi);
    cudaGetSymbolAddress((void**)&p1lo, g_p1lo);
    cudaGetSymbolAddress((void**)&c3f,  g_c3f);
    cudaGetSymbolAddress((void**)&zn,   g_zn);
    cudaGetSymbolAddress((void**)&valh, g_valh);
    cudaGetSymbolAddress((void**)&f1h,  g_f1h);
    cudaGetSymbolAddress((void**)&f2h,  g_f2h);
    cudaGetSymbolAddress((void**)&f3h,  g_f3h);
    cudaGetSymbolAddress((void**)&f4h,  g_f4h);
    cudaGetSymbolAddress((void**)&wp1,  g_wp1);
    cudaGetSymbolAddress((void**)&wpt2, g_wpt2);
    cudaGetSymbolAddress((void**)&wp3,  g_wp3);
    cudaGetSymbolAddress((void**)&wp4,  g_wp4);
    cudaGetSymbolAddress((void**)&w2hi, g_w2hi);
    cudaGetSymbolAddress((void**)&w2lo, g_w2lo);
    cudaGetSymbolAddress((void**)&w3hi, g_w3hi);
    cudaGetSymbolAddress((void**)&w3lo, g_w3lo);

    static bool attr_set = false;
    if (!attr_set) {
        cudaFuncSetAttribute(vq_kernel, cudaFuncAttributeMaxDynamicSharedMemorySize,
                             128 * 129 * (int)sizeof(float));
        cudaFuncSetAttribute(tc_eng1, cudaFuncAttributeMaxDynamicSharedMemorySize,
                             2 * TILEA + 2 * TILE);
        cudaFuncSetAttribute(tc_t2, cudaFuncAttributeMaxDynamicSharedMemorySize,
                             2 * TILEA + 2 * TILE);
        cudaFuncSetAttribute(tc_enc3, cudaFuncAttributeMaxDynamicSharedMemorySize,
                             2 * TILEA + 2 * TILE);
        attr_set = true;
    }

    init_kernel<<<1, 1>>>();                                    // 0
    prepack_all<<<132, 256>>>(w2, w3, t1w, t2w, t3w, t4w,       // 1
                              w2hi, w2lo, w3hi, w3lo, wp1, wpt2, wp3, wp4);
    conv1_split<<<dim3(BB, 72), 128>>>(x, w1, b1, c1hi, c1lo);  // 2
    tc_enc3<<<576, 512, 2 * TILEA + 2 * TILE>>>(                // 3 <- profiled
        (const uint16_t*)c1hi, (const uint16_t*)c1lo,
        (const uint16_t*)w2hi, (const uint16_t*)w2lo,
        b2, c2f, 24, 24, 24, 24, 2, 1);
    mp_split_nhwc<<<4096, 256>>>(c2f, p1hi, p1lo, 24, 24);
    tc_enc3<<<144, 512, 2 * TILEA + 2 * TILE>>>(
        (const uint16_t*)p1hi, (const uint16_t*)p1lo,
        (const uint16_t*)w3hi, (const uint16_t*)w3lo,
        b3, c3f, 12, 12, 12, 12, 2, 0);
    mp_nhwc<<<2048, 256>>>(c3f, zn, 12, 12);

    vq_kernel<<<BB, NT, 128 * 129 * sizeof(float)>>>(zn, dictw, valh, idx_ptr);

    tc_eng1<<<81, 512, 2 * TILEA + 2 * TILE>>>(
        (const uint16_t*)valh, (const uint16_t*)wp1, t1b, f1h, 6, 6, 9, 9, 3, 4);
    tc_t2<<<dim3(100, 1, 4), 512, 2 * TILEA + 2 * TILE>>>(
        (const uint16_t*)f1h, (const uint16_t*)wpt2, t2b, f2h);
    tc_eng1<<<576, 512, 2 * TILEA + 2 * TILE>>>(
        (const uint16_t*)f2h, (const uint16_t*)wp3, t3b, f3h, 20, 20, 24, 24, 4, 5);
    tc_eng1<<<784, 512, 2 * TILEA + 2 * TILE>>>(
        (const uint16_t*)f3h, (const uint16_t*)wp4, t4b, f4h, 24, 24, 28, 28, 4, 5);

    mu_loss<<<BB, NT>>>(f4h, x, mw, mb);
    finalize_kernel<<<1, 1>>>(loss_ptr);
}